// round 1
// baseline (speedup 1.0000x reference)
#include <cuda_runtime.h>
#include <math_constants.h>

#define BB 4
#define SS 2048
#define EE 1024
#define HH 16
#define DD 64

// Scratch (device globals — allocation-free rule)
__device__ float g_q[BB*HH*SS*DD];
__device__ float g_k[BB*HH*SS*DD];
__device__ float g_v[BB*HH*SS*DD];
__device__ float g_o[BB*HH*SS*DD];

// ---------------------------------------------------------------------------
// Kernel 1: QKV projection.  For each (which in {q,k,v}, head h):
//   out[b,h,s,d] = sum_e x[b,s,e] * W[h,e,d] + bias[h,d]
// GEMM: C[8192 x 64] = X[8192 x 1024] * W[1024 x 64]
// Tile: BM=128, BN=64, BK=16, 256 threads, 8x4 per-thread microtile.
// ---------------------------------------------------------------------------
__global__ __launch_bounds__(256) void qkv_kernel(
    const float* __restrict__ x,
    const float* __restrict__ wq, const float* __restrict__ bq,
    const float* __restrict__ wk, const float* __restrict__ bk,
    const float* __restrict__ wv, const float* __restrict__ bv)
{
    __shared__ float As[16][128];   // A transposed: As[k][m]
    __shared__ float Bs[16][64];    // Bs[k][n]

    const int mt = blockIdx.x;      // 0..63
    const int z  = blockIdx.y;      // 0..47
    const int which = z >> 4;
    const int h = z & 15;

    const float* Wp; const float* bp; float* outp;
    if (which == 0)      { Wp = wq; bp = bq; outp = g_q; }
    else if (which == 1) { Wp = wk; bp = bk; outp = g_k; }
    else                 { Wp = wv; bp = bv; outp = g_v; }
    Wp += (size_t)h * EE * DD;
    bp += h * DD;

    const int tid = threadIdx.x;
    const int ty = tid >> 4, tx = tid & 15;
    const int m0 = mt * 128;

    float acc[8][4];
    #pragma unroll
    for (int i = 0; i < 8; i++)
        #pragma unroll
        for (int j = 0; j < 4; j++) acc[i][j] = 0.f;

    for (int k0 = 0; k0 < EE; k0 += 16) {
        // Load A tile: 128 rows x 16 cols, transposed into As
        #pragma unroll
        for (int q = 0; q < 2; q++) {
            int idx = q * 256 + tid;
            int r = idx >> 2;
            int c = (idx & 3) * 4;
            float4 a = *(const float4*)&x[(size_t)(m0 + r) * EE + k0 + c];
            As[c + 0][r] = a.x; As[c + 1][r] = a.y;
            As[c + 2][r] = a.z; As[c + 3][r] = a.w;
        }
        // Load B tile: 16 rows x 64 cols
        {
            int r = tid >> 4;
            int c = (tid & 15) * 4;
            *(float4*)&Bs[r][c] = *(const float4*)&Wp[(size_t)(k0 + r) * DD + c];
        }
        __syncthreads();

        #pragma unroll
        for (int k = 0; k < 16; k++) {
            float4 a0 = *(const float4*)&As[k][ty * 8];
            float4 a1 = *(const float4*)&As[k][ty * 8 + 4];
            float4 b  = *(const float4*)&Bs[k][tx * 4];
            float ra[8] = {a0.x, a0.y, a0.z, a0.w, a1.x, a1.y, a1.z, a1.w};
            float rb[4] = {b.x, b.y, b.z, b.w};
            #pragma unroll
            for (int i = 0; i < 8; i++)
                #pragma unroll
                for (int j = 0; j < 4; j++)
                    acc[i][j] += ra[i] * rb[j];
        }
        __syncthreads();
    }

    // Epilogue: add bias, write to [B,H,S,D] layout
    #pragma unroll
    for (int i = 0; i < 8; i++) {
        int m = m0 + ty * 8 + i;
        int b = m >> 11;       // /2048
        int s = m & 2047;
        float* orow = &outp[(((size_t)b * HH + h) * SS + s) * DD + tx * 4];
        #pragma unroll
        for (int j = 0; j < 4; j++)
            orow[j] = acc[i][j] + bp[tx * 4 + j];
    }
}

// ---------------------------------------------------------------------------
// Kernel 2: causal flash attention, fp32.
// One block per (bh, 64-row tile). Br = Bc = 64, D = 64, 256 threads.
// K is stored TRANSPOSED in smem (Kts[d][j]) for conflict-free QK^T reads.
// Online softmax in log2 domain (scores pre-scaled by 1/sqrt(D)*log2(e)).
// ---------------------------------------------------------------------------
__global__ __launch_bounds__(256) void attn_kernel()
{
    extern __shared__ float sm[];
    float* Qs   = sm;                 // [64][64]  row-major [i][d]
    float* Kts  = Qs  + 64 * 64;      // [64][64]  transposed [d][j]
    float* Vs   = Kts + 64 * 64;      // [64][64]  row-major [j][d]
    float* Ps   = Vs  + 64 * 64;      // [64][65]  scores / probs (padded)
    float* mrow = Ps  + 64 * 65;      // [64]
    float* lrow = mrow + 64;          // [64]
    float* arow = lrow + 64;          // [64]

    const int rt  = blockIdx.x;       // row tile 0..31
    const int bh  = blockIdx.y;       // 0..63
    const int tid = threadIdx.x;
    const int ty = tid >> 4, tx = tid & 15;

    const float* qp = g_q + (size_t)bh * SS * DD;
    const float* kp = g_k + (size_t)bh * SS * DD;
    const float* vp = g_v + (size_t)bh * SS * DD;

    const int row0 = rt * 64;

    // Load Q tile (coalesced float4)
    #pragma unroll
    for (int q = 0; q < 4; q++) {
        int idx = q * 256 + tid;
        int r = idx >> 4;
        int c = (idx & 15) * 4;
        *(float4*)&Qs[r * 64 + c] = *(const float4*)&qp[(size_t)(row0 + r) * DD + c];
    }
    if (tid < 64) { mrow[tid] = -CUDART_INF_F; lrow[tid] = 0.f; }

    float o[4][4];
    #pragma unroll
    for (int i = 0; i < 4; i++)
        #pragma unroll
        for (int j = 0; j < 4; j++) o[i][j] = 0.f;

    const float sscale = 0.125f * 1.4426950408889634f; // 1/sqrt(64) * log2(e)

    __syncthreads();

    for (int ct = 0; ct <= rt; ct++) {
        const int col0 = ct * 64;

        // Load K (transposed) and V tiles
        #pragma unroll
        for (int q = 0; q < 4; q++) {
            int idx = q * 256 + tid;
            int r = idx >> 4;
            int c = (idx & 15) * 4;
            float4 kv = *(const float4*)&kp[(size_t)(col0 + r) * DD + c];
            Kts[(c + 0) * 64 + r] = kv.x;
            Kts[(c + 1) * 64 + r] = kv.y;
            Kts[(c + 2) * 64 + r] = kv.z;
            Kts[(c + 3) * 64 + r] = kv.w;
            *(float4*)&Vs[r * 64 + c] = *(const float4*)&vp[(size_t)(col0 + r) * DD + c];
        }
        __syncthreads();

        // S = Q K^T  (4x4 microtile per thread)
        float sacc[4][4];
        #pragma unroll
        for (int i = 0; i < 4; i++)
            #pragma unroll
            for (int j = 0; j < 4; j++) sacc[i][j] = 0.f;

        #pragma unroll 8
        for (int d = 0; d < 64; d++) {
            float qa[4];
            #pragma unroll
            for (int i = 0; i < 4; i++) qa[i] = Qs[(ty * 4 + i) * 64 + d];
            float4 kb = *(const float4*)&Kts[d * 64 + tx * 4];
            float rb[4] = {kb.x, kb.y, kb.z, kb.w};
            #pragma unroll
            for (int i = 0; i < 4; i++)
                #pragma unroll
                for (int j = 0; j < 4; j++)
                    sacc[i][j] += qa[i] * rb[j];
        }

        // Mask (causal) + scale, write scores to smem
        #pragma unroll
        for (int i = 0; i < 4; i++) {
            int rg = row0 + ty * 4 + i;
            #pragma unroll
            for (int j = 0; j < 4; j++) {
                int cg = col0 + tx * 4 + j;
                float val = (cg <= rg) ? sacc[i][j] * sscale : -CUDART_INF_F;
                Ps[(ty * 4 + i) * 65 + tx * 4 + j] = val;
            }
        }
        __syncthreads();

        // Online softmax (one thread per row)
        if (tid < 64) {
            const int i = tid;
            float mold = mrow[i];
            float mnew = mold;
            #pragma unroll 8
            for (int j = 0; j < 64; j++) mnew = fmaxf(mnew, Ps[i * 65 + j]);
            float alpha = exp2f(mold - mnew);
            float l = lrow[i] * alpha;
            #pragma unroll 8
            for (int j = 0; j < 64; j++) {
                float p = exp2f(Ps[i * 65 + j] - mnew);
                Ps[i * 65 + j] = p;
                l += p;
            }
            mrow[i] = mnew; lrow[i] = l; arow[i] = alpha;
        }
        __syncthreads();

        // Rescale O accumulators, then O += P * V
        float al[4];
        #pragma unroll
        for (int i = 0; i < 4; i++) al[i] = arow[ty * 4 + i];
        #pragma unroll
        for (int i = 0; i < 4; i++)
            #pragma unroll
            for (int j = 0; j < 4; j++) o[i][j] *= al[i];

        #pragma unroll 8
        for (int j = 0; j < 64; j++) {
            float pa[4];
            #pragma unroll
            for (int i = 0; i < 4; i++) pa[i] = Ps[(ty * 4 + i) * 65 + j];
            float4 vb = *(const float4*)&Vs[j * 64 + tx * 4];
            float rv[4] = {vb.x, vb.y, vb.z, vb.w};
            #pragma unroll
            for (int i = 0; i < 4; i++)
                #pragma unroll
                for (int jj = 0; jj < 4; jj++)
                    o[i][jj] += pa[i] * rv[jj];
        }
        __syncthreads();
    }

    // Final normalize + write to g_o [B,H,S,D]
    #pragma unroll
    for (int i = 0; i < 4; i++) {
        float inv = 1.f / lrow[ty * 4 + i];
        float4 out;
        out.x = o[i][0] * inv;
        out.y = o[i][1] * inv;
        out.z = o[i][2] * inv;
        out.w = o[i][3] * inv;
        *(float4*)&g_o[((size_t)bh * SS + row0 + ty * 4 + i) * DD + tx * 4] = out;
    }
}

// ---------------------------------------------------------------------------
// Kernel 3: output projection.
//   y[m, n] = sum_k o_cat[m, k] * wo[k, n] + bo[n]
// where o_cat[b*S+s, h*D+d] = g_o[b,h,s,d].
// GEMM: [8192 x 1024] = [8192 x 1024] * [1024 x 1024]
// ---------------------------------------------------------------------------
__global__ __launch_bounds__(256) void oproj_kernel(
    const float* __restrict__ wo, const float* __restrict__ bo,
    float* __restrict__ y)
{
    __shared__ float As[16][128];
    __shared__ float Bs[16][64];

    const int mt = blockIdx.x;   // 0..63
    const int nt = blockIdx.y;   // 0..15
    const int tid = threadIdx.x;
    const int ty = tid >> 4, tx = tid & 15;
    const int m0 = mt * 128;
    const int n0 = nt * 64;

    float acc[8][4];
    #pragma unroll
    for (int i = 0; i < 8; i++)
        #pragma unroll
        for (int j = 0; j < 4; j++) acc[i][j] = 0.f;

    for (int k0 = 0; k0 < HH * DD; k0 += 16) {
        // A tile: gather from g_o (head-concat layout on the fly)
        #pragma unroll
        for (int q = 0; q < 2; q++) {
            int idx = q * 256 + tid;
            int r = idx >> 2;
            int c = (idx & 3) * 4;
            int m = m0 + r;
            int b = m >> 11;
            int s = m & 2047;
            int k = k0 + c;
            int h = k >> 6;
            int d = k & 63;
            float4 a = *(const float4*)&g_o[(((size_t)b * HH + h) * SS + s) * DD + d];
            As[c + 0][r] = a.x; As[c + 1][r] = a.y;
            As[c + 2][r] = a.z; As[c + 3][r] = a.w;
        }
        {
            int r = tid >> 4;
            int c = (tid & 15) * 4;
            *(float4*)&Bs[r][c] = *(const float4*)&wo[(size_t)(k0 + r) * EE + n0 + c];
        }
        __syncthreads();

        #pragma unroll
        for (int k = 0; k < 16; k++) {
            float4 a0 = *(const float4*)&As[k][ty * 8];
            float4 a1 = *(const float4*)&As[k][ty * 8 + 4];
            float4 b  = *(const float4*)&Bs[k][tx * 4];
            float ra[8] = {a0.x, a0.y, a0.z, a0.w, a1.x, a1.y, a1.z, a1.w};
            float rb[4] = {b.x, b.y, b.z, b.w};
            #pragma unroll
            for (int i = 0; i < 8; i++)
                #pragma unroll
                for (int j = 0; j < 4; j++)
                    acc[i][j] += ra[i] * rb[j];
        }
        __syncthreads();
    }

    #pragma unroll
    for (int i = 0; i < 8; i++) {
        int m = m0 + ty * 8 + i;
        #pragma unroll
        for (int j = 0; j < 4; j++) {
            int n = n0 + tx * 4 + j;
            y[(size_t)m * EE + n] = acc[i][j] + bo[n];
        }
    }
}

// ---------------------------------------------------------------------------
extern "C" void kernel_launch(void* const* d_in, const int* in_sizes, int n_in,
                              void* d_out, int out_size)
{
    const float* x  = (const float*)d_in[0];
    const float* wq = (const float*)d_in[1];
    const float* bq = (const float*)d_in[2];
    const float* wk = (const float*)d_in[3];
    const float* bk = (const float*)d_in[4];
    const float* wv = (const float*)d_in[5];
    const float* bv = (const float*)d_in[6];
    const float* wo = (const float*)d_in[7];
    const float* bo = (const float*)d_in[8];
    float* y = (float*)d_out;

    (void)in_sizes; (void)n_in; (void)out_size;

    // 1) QKV projections: 48 head-GEMMs
    qkv_kernel<<<dim3(64, 48), 256>>>(x, wq, bq, wk, bk, wv, bv);

    // 2) Flash attention (causal)
    const int smem_bytes = (3 * 64 * 64 + 64 * 65 + 3 * 64) * (int)sizeof(float);
    cudaFuncSetAttribute(attn_kernel, cudaFuncAttributeMaxDynamicSharedMemorySize,
                         smem_bytes);
    attn_kernel<<<dim3(32, 64), 256, smem_bytes>>>();

    // 3) Output projection
    oproj_kernel<<<dim3(64, 16), 256>>>(wo, bo, y);
}

// round 3
// speedup vs baseline: 1.5538x; 1.5538x over previous
#include <cuda_runtime.h>
#include <cuda_bf16.h>
#include <math_constants.h>
#include <cstdint>

#define BB 4
#define SS 2048
#define EE 1024
#define HH 16
#define DD 64
#define MM (BB*SS)   // 8192

// ---------------------------------------------------------------------------
// Device-global scratch (allocation-free rule)
// ---------------------------------------------------------------------------
__device__ __align__(16) float g_q[BB*HH*SS*DD];
__device__ __align__(16) float g_k[BB*HH*SS*DD];
__device__ __align__(16) float g_v[BB*HH*SS*DD];
__device__ __align__(16) float g_o[BB*HH*SS*DD];

__device__ __align__(16) __nv_bfloat16 g_xhi[MM*EE];
__device__ __align__(16) __nv_bfloat16 g_xlo[MM*EE];
__device__ __align__(16) __nv_bfloat16 g_whi[48*DD*EE];   // [z][d][e], z=which*16+h
__device__ __align__(16) __nv_bfloat16 g_wlo[48*DD*EE];
__device__ __align__(16) __nv_bfloat16 g_wohi[EE*EE];     // [n][k] (wo transposed)
__device__ __align__(16) __nv_bfloat16 g_wolo[EE*EE];
__device__ __align__(16) __nv_bfloat16 g_ohi[MM*EE];      // [m][h*64+d]
__device__ __align__(16) __nv_bfloat16 g_olo[MM*EE];

// ---------------------------------------------------------------------------
// mma.sync / ldmatrix / cp.async helpers (base-arch features; no tcgen05)
// ---------------------------------------------------------------------------
__device__ __forceinline__ uint32_t smem_to_u32(const void* p) {
    uint32_t a;
    asm("{ .reg .u64 t; cvta.to.shared.u64 t, %1; cvt.u32.u64 %0, t; }"
        : "=r"(a) : "l"(p));
    return a;
}
__device__ __forceinline__ void cp16(uint32_t saddr, const void* gaddr) {
    asm volatile("cp.async.cg.shared.global [%0], [%1], 16;"
                 :: "r"(saddr), "l"(gaddr));
}
#define CP_COMMIT() asm volatile("cp.async.commit_group;" ::: "memory")
#define CP_WAIT1()  asm volatile("cp.async.wait_group 1;" ::: "memory")

__device__ __forceinline__ void ldmx4(uint32_t* r, uint32_t addr) {
    asm volatile("ldmatrix.sync.aligned.m8n8.x4.shared.b16 {%0,%1,%2,%3}, [%4];"
        : "=r"(r[0]), "=r"(r[1]), "=r"(r[2]), "=r"(r[3]) : "r"(addr));
}
__device__ __forceinline__ void mma16816(float* c, const uint32_t* a,
                                         uint32_t b0, uint32_t b1) {
    asm volatile("mma.sync.aligned.m16n8k16.row.col.f32.bf16.bf16.f32 "
        "{%0,%1,%2,%3}, {%4,%5,%6,%7}, {%8,%9}, {%0,%1,%2,%3};"
        : "+f"(c[0]), "+f"(c[1]), "+f"(c[2]), "+f"(c[3])
        : "r"(a[0]), "r"(a[1]), "r"(a[2]), "r"(a[3]), "r"(b0), "r"(b1));
}

// SW64 swizzle for 64-byte rows: conflict-free for ldmatrix + cp.async 16B
#define SWZ64(off) ((off) ^ (((off) >> 3) & 0x30))

// ---------------------------------------------------------------------------
// Split helpers
// ---------------------------------------------------------------------------
__device__ __forceinline__ void split1(float v, __nv_bfloat16& h, __nv_bfloat16& l) {
    h = __float2bfloat16_rn(v);
    l = __float2bfloat16_rn(v - __bfloat162float(h));
}
__device__ __forceinline__ uint32_t pck(__nv_bfloat16 a, __nv_bfloat16 b) {
    return ((uint32_t)__bfloat16_as_ushort(b) << 16) | (uint32_t)__bfloat16_as_ushort(a);
}

// x [8192x1024] fp32 -> hi/lo bf16
__global__ __launch_bounds__(256) void split_x_kernel(const float* __restrict__ x) {
    size_t i = ((size_t)blockIdx.x * 256 + threadIdx.x) * 8;
    float4 v0 = *(const float4*)(x + i);
    float4 v1 = *(const float4*)(x + i + 4);
    float vv[8] = {v0.x, v0.y, v0.z, v0.w, v1.x, v1.y, v1.z, v1.w};
    __nv_bfloat16 h[8], l[8];
    #pragma unroll
    for (int j = 0; j < 8; j++) split1(vv[j], h[j], l[j]);
    uint4 uh = {pck(h[0],h[1]), pck(h[2],h[3]), pck(h[4],h[5]), pck(h[6],h[7])};
    uint4 ul = {pck(l[0],l[1]), pck(l[2],l[3]), pck(l[4],l[5]), pck(l[6],l[7])};
    *(uint4*)(g_xhi + i) = uh;
    *(uint4*)(g_xlo + i) = ul;
}

// g_o [bh][s][d] -> head-concat [m][h*64+d], split hi/lo
__global__ __launch_bounds__(256) void split_o_kernel() {
    size_t i = ((size_t)blockIdx.x * 256 + threadIdx.x) * 8;
    int m = (int)(i >> 10);
    int kk = (int)(i & 1023);
    int h = kk >> 6, d = kk & 63;
    int b = m >> 11, s = m & 2047;
    const float* src = g_o + (((size_t)(b*HH + h) * SS + s) * DD + d);
    float4 v0 = *(const float4*)(src);
    float4 v1 = *(const float4*)(src + 4);
    float vv[8] = {v0.x, v0.y, v0.z, v0.w, v1.x, v1.y, v1.z, v1.w};
    __nv_bfloat16 hh[8], ll[8];
    #pragma unroll
    for (int j = 0; j < 8; j++) split1(vv[j], hh[j], ll[j]);
    uint4 uh = {pck(hh[0],hh[1]), pck(hh[2],hh[3]), pck(hh[4],hh[5]), pck(hh[6],hh[7])};
    uint4 ul = {pck(ll[0],ll[1]), pck(ll[2],ll[3]), pck(ll[4],ll[5]), pck(ll[6],ll[7])};
    *(uint4*)(g_ohi + i) = uh;
    *(uint4*)(g_olo + i) = ul;
}

// wq/wk/wv [16][1024][64] -> g_w{hi,lo} [z][d][e] (transposed, split)
__global__ __launch_bounds__(256) void split_w_kernel(
    const float* __restrict__ wq, const float* __restrict__ wk, const float* __restrict__ wv) {
    __shared__ float t[64][65];
    const int z = blockIdx.y;
    const int which = z >> 4, h = z & 15;
    const float* W = (which == 0 ? wq : which == 1 ? wk : wv) + (size_t)h * EE * DD;
    const int e0 = blockIdx.x * 64;
    const int tid = threadIdx.x;
    #pragma unroll
    for (int q = 0; q < 4; q++) {
        int idx = q * 256 + tid;
        int r = idx >> 4, c = (idx & 15) * 4;
        float4 v = *(const float4*)(W + (size_t)(e0 + r) * DD + c);
        t[r][c] = v.x; t[r][c+1] = v.y; t[r][c+2] = v.z; t[r][c+3] = v.w;
    }
    __syncthreads();
    #pragma unroll
    for (int q = 0; q < 4; q++) {
        int idx = q * 256 + tid;
        int d = idx >> 4, e = (idx & 15) * 4;
        __nv_bfloat16 h4[4], l4[4];
        #pragma unroll
        for (int j = 0; j < 4; j++) split1(t[e + j][d], h4[j], l4[j]);
        size_t o = ((size_t)z * DD + d) * EE + e0 + e;
        *(uint32_t*)(g_whi + o)     = pck(h4[0], h4[1]);
        *(uint32_t*)(g_whi + o + 2) = pck(h4[2], h4[3]);
        *(uint32_t*)(g_wlo + o)     = pck(l4[0], l4[1]);
        *(uint32_t*)(g_wlo + o + 2) = pck(l4[2], l4[3]);
    }
}

// wo [1024 k][1024 n] -> g_wo{hi,lo} [n][k] (transposed, split)
__global__ __launch_bounds__(256) void split_wo_kernel(const float* __restrict__ wo) {
    __shared__ float t[64][65];
    const int k0 = blockIdx.x * 64;
    const int n0 = blockIdx.y * 64;
    const int tid = threadIdx.x;
    #pragma unroll
    for (int q = 0; q < 4; q++) {
        int idx = q * 256 + tid;
        int r = idx >> 4, c = (idx & 15) * 4;
        float4 v = *(const float4*)(wo + (size_t)(k0 + r) * EE + n0 + c);
        t[r][c] = v.x; t[r][c+1] = v.y; t[r][c+2] = v.z; t[r][c+3] = v.w;
    }
    __syncthreads();
    #pragma unroll
    for (int q = 0; q < 4; q++) {
        int idx = q * 256 + tid;
        int d = idx >> 4, e = (idx & 15) * 4;   // d: n index, e: k index
        __nv_bfloat16 h4[4], l4[4];
        #pragma unroll
        for (int j = 0; j < 4; j++) split1(t[e + j][d], h4[j], l4[j]);
        size_t o = (size_t)(n0 + d) * EE + k0 + e;
        *(uint32_t*)(g_wohi + o)     = pck(h4[0], h4[1]);
        *(uint32_t*)(g_wohi + o + 2) = pck(h4[2], h4[3]);
        *(uint32_t*)(g_wolo + o)     = pck(l4[0], l4[1]);
        *(uint32_t*)(g_wolo + o + 2) = pck(l4[2], l4[3]);
    }
}

// ---------------------------------------------------------------------------
// Shared GEMM core: C[128x64] += A[128x1024] * B[64x1024]^T, split-bf16 3-pass.
// 256 threads (8 warps, 4m x 2n), warp tile 32x32, BK=32, 3-stage cp.async.
// A,B are K-major bf16 (row stride 2048 bytes). Stage layout:
//   [0,8K) Ahi  [8K,16K) Alo  [16K,20K) Bhi  [20K,24K) Blo
// ---------------------------------------------------------------------------
#define STAGE_BYTES 24576
#define GEMM_SMEM   (3 * STAGE_BYTES)

__device__ __forceinline__ void load_stage(
    uint32_t sb, int s, int kt, int tid,
    const char* agh, const char* agl, const char* bgh, const char* bgl)
{
    const uint32_t sA = sb + (uint32_t)s * STAGE_BYTES;
    const size_t gk = (size_t)kt * 64 + (size_t)((tid & 3) * 16);
    const int c16 = (tid & 3) * 16;
    #pragma unroll
    for (int i = 0; i < 2; ++i) {
        int row = i * 64 + (tid >> 2);
        uint32_t so = SWZ64((uint32_t)(row * 64 + c16));
        cp16(sA + so,        agh + (size_t)row * 2048 + gk);
        cp16(sA + 8192 + so, agl + (size_t)row * 2048 + gk);
    }
    {
        int row = tid >> 2;
        uint32_t so = SWZ64((uint32_t)(row * 64 + c16));
        cp16(sA + 16384 + so, bgh + (size_t)row * 2048 + gk);
        cp16(sA + 20480 + so, bgl + (size_t)row * 2048 + gk);
    }
}

__device__ __forceinline__ void gemm_core_128x64(
    uint32_t sb,
    const char* agh, const char* agl, const char* bgh, const char* bgl,
    float acc[2][4][4])
{
    const int tid = threadIdx.x;
    const int warp = tid >> 5, lane = tid & 31;
    const int wm = (warp & 3) * 32;
    const int wn = (warp >> 2) * 32;

    // ldmatrix per-lane byte offsets (logical -> swizzled), per frag & k16-half
    uint32_t offA[2][2], offB[2][2];
    {
        const int rbA = (lane & 7) + ((lane >> 3) & 1) * 8;
        const int cA  = (lane >> 4) & 1;
        const int rbB = (lane & 7) + ((lane >> 4) & 1) * 8;
        const int cB  = (lane >> 3) & 1;
        #pragma unroll
        for (int f = 0; f < 2; ++f)
            #pragma unroll
            for (int s = 0; s < 2; ++s) {
                offA[f][s] = SWZ64((uint32_t)((wm + f*16 + rbA) * 64 + (s*2 + cA) * 16));
                offB[f][s] = SWZ64((uint32_t)((wn + f*16 + rbB) * 64 + (s*2 + cB) * 16));
            }
    }
    #pragma unroll
    for (int f = 0; f < 2; f++)
        #pragma unroll
        for (int nf = 0; nf < 4; nf++)
            #pragma unroll
            for (int i = 0; i < 4; i++) acc[f][nf][i] = 0.f;

    // prologue: stages 0,1
    load_stage(sb, 0, 0, tid, agh, agl, bgh, bgl); CP_COMMIT();
    load_stage(sb, 1, 1, tid, agh, agl, bgh, bgl); CP_COMMIT();

    for (int kt = 0; kt < 32; ++kt) {
        CP_WAIT1();
        __syncthreads();
        if (kt + 2 < 32)
            load_stage(sb, (kt + 2) % 3, kt + 2, tid, agh, agl, bgh, bgl);
        CP_COMMIT();

        const uint32_t base = sb + (uint32_t)(kt % 3) * STAGE_BYTES;
        #pragma unroll
        for (int s16 = 0; s16 < 2; ++s16) {
            uint32_t ah0[4], ah1[4], al0[4], al1[4];
            uint32_t bh0[4], bh1[4], bl0[4], bl1[4];
            ldmx4(ah0, base + offA[0][s16]);
            ldmx4(ah1, base + offA[1][s16]);
            ldmx4(al0, base + 8192 + offA[0][s16]);
            ldmx4(al1, base + 8192 + offA[1][s16]);
            ldmx4(bh0, base + 16384 + offB[0][s16]);
            ldmx4(bh1, base + 16384 + offB[1][s16]);
            ldmx4(bl0, base + 20480 + offB[0][s16]);
            ldmx4(bl1, base + 20480 + offB[1][s16]);
            uint32_t* ah[2] = {ah0, ah1};
            uint32_t* al[2] = {al0, al1};
            uint32_t* bh[2] = {bh0, bh1};
            uint32_t* bl[2] = {bl0, bl1};
            #pragma unroll
            for (int f = 0; f < 2; ++f) {
                #pragma unroll
                for (int nf = 0; nf < 4; ++nf) {
                    uint32_t b0h = bh[nf >> 1][(nf & 1) * 2];
                    uint32_t b1h = bh[nf >> 1][(nf & 1) * 2 + 1];
                    uint32_t b0l = bl[nf >> 1][(nf & 1) * 2];
                    uint32_t b1l = bl[nf >> 1][(nf & 1) * 2 + 1];
                    mma16816(acc[f][nf], ah[f], b0h, b1h);
                    mma16816(acc[f][nf], ah[f], b0l, b1l);
                    mma16816(acc[f][nf], al[f], b0h, b1h);
                }
            }
        }
    }
}

// ---------------------------------------------------------------------------
// QKV projection on mma.sync: grid (64 mtiles, 48 z)
// ---------------------------------------------------------------------------
__global__ __launch_bounds__(256) void qkv_mma_kernel(
    const float* __restrict__ bq, const float* __restrict__ bk,
    const float* __restrict__ bv)
{
    extern __shared__ char smem[];
    const uint32_t sb = smem_to_u32(smem);
    const int tid = threadIdx.x;
    const int m0 = blockIdx.x * 128;
    const int z = blockIdx.y;
    const int which = z >> 4, h = z & 15;

    const char* agh = (const char*)(g_xhi + (size_t)m0 * EE);
    const char* agl = (const char*)(g_xlo + (size_t)m0 * EE);
    const char* bgh = (const char*)(g_whi + (size_t)z * DD * EE);
    const char* bgl = (const char*)(g_wlo + (size_t)z * DD * EE);

    float acc[2][4][4];
    gemm_core_128x64(sb, agh, agl, bgh, bgl, acc);

    const float* bp = (which == 0 ? bq : which == 1 ? bk : bv) + h * DD;
    float* outp = (which == 0 ? g_q : which == 1 ? g_k : g_v);

    const int warp = tid >> 5, lane = tid & 31;
    const int wm = (warp & 3) * 32, wn = (warp >> 2) * 32;
    const int r = lane >> 2, cp2 = (lane & 3) * 2;
    #pragma unroll
    for (int f = 0; f < 2; ++f) {
        #pragma unroll
        for (int half = 0; half < 2; ++half) {
            int m = m0 + wm + f * 16 + r + half * 8;
            int b = m >> 11, s = m & 2047;
            float* row = outp + (((size_t)b * HH + h) * SS + s) * DD;
            #pragma unroll
            for (int nf = 0; nf < 4; ++nf) {
                int col = wn + nf * 8 + cp2;
                float2 v;
                v.x = acc[f][nf][half * 2 + 0] + bp[col];
                v.y = acc[f][nf][half * 2 + 1] + bp[col + 1];
                *(float2*)(row + col) = v;
            }
        }
    }
}

// ---------------------------------------------------------------------------
// Output projection on mma.sync: grid (64 mtiles, 16 ntiles)
// ---------------------------------------------------------------------------
__global__ __launch_bounds__(256) void oproj_mma_kernel(
    const float* __restrict__ bo, float* __restrict__ y)
{
    extern __shared__ char smem[];
    const uint32_t sb = smem_to_u32(smem);
    const int tid = threadIdx.x;
    const int m0 = blockIdx.x * 128;
    const int n0 = blockIdx.y * 64;

    const char* agh = (const char*)(g_ohi + (size_t)m0 * EE);
    const char* agl = (const char*)(g_olo + (size_t)m0 * EE);
    const char* bgh = (const char*)(g_wohi + (size_t)n0 * EE);
    const char* bgl = (const char*)(g_wolo + (size_t)n0 * EE);

    float acc[2][4][4];
    gemm_core_128x64(sb, agh, agl, bgh, bgl, acc);

    const int warp = tid >> 5, lane = tid & 31;
    const int wm = (warp & 3) * 32, wn = (warp >> 2) * 32;
    const int r = lane >> 2, cp2 = (lane & 3) * 2;
    #pragma unroll
    for (int f = 0; f < 2; ++f) {
        #pragma unroll
        for (int half = 0; half < 2; ++half) {
            int m = m0 + wm + f * 16 + r + half * 8;
            float* row = y + (size_t)m * EE + n0;
            #pragma unroll
            for (int nf = 0; nf < 4; ++nf) {
                int col = wn + nf * 8 + cp2;
                float2 v;
                v.x = acc[f][nf][half * 2 + 0] + bo[n0 + col];
                v.y = acc[f][nf][half * 2 + 1] + bo[n0 + col + 1];
                *(float2*)(row + col) = v;
            }
        }
    }
}

// ---------------------------------------------------------------------------
// Causal flash attention, fp32 (unchanged from R1 — proven correct)
// ---------------------------------------------------------------------------
__global__ __launch_bounds__(256) void attn_kernel()
{
    extern __shared__ float sm[];
    float* Qs   = sm;
    float* Kts  = Qs  + 64 * 64;
    float* Vs   = Kts + 64 * 64;
    float* Ps   = Vs  + 64 * 64;
    float* mrow = Ps  + 64 * 65;
    float* lrow = mrow + 64;
    float* arow = lrow + 64;

    const int rt  = blockIdx.x;
    const int bh  = blockIdx.y;
    const int tid = threadIdx.x;
    const int ty = tid >> 4, tx = tid & 15;

    const float* qp = g_q + (size_t)bh * SS * DD;
    const float* kp = g_k + (size_t)bh * SS * DD;
    const float* vp = g_v + (size_t)bh * SS * DD;

    const int row0 = rt * 64;

    #pragma unroll
    for (int q = 0; q < 4; q++) {
        int idx = q * 256 + tid;
        int r = idx >> 4;
        int c = (idx & 15) * 4;
        *(float4*)&Qs[r * 64 + c] = *(const float4*)&qp[(size_t)(row0 + r) * DD + c];
    }
    if (tid < 64) { mrow[tid] = -CUDART_INF_F; lrow[tid] = 0.f; }

    float o[4][4];
    #pragma unroll
    for (int i = 0; i < 4; i++)
        #pragma unroll
        for (int j = 0; j < 4; j++) o[i][j] = 0.f;

    const float sscale = 0.125f * 1.4426950408889634f;

    __syncthreads();

    for (int ct = 0; ct <= rt; ct++) {
        const int col0 = ct * 64;

        #pragma unroll
        for (int q = 0; q < 4; q++) {
            int idx = q * 256 + tid;
            int r = idx >> 4;
            int c = (idx & 15) * 4;
            float4 kv = *(const float4*)&kp[(size_t)(col0 + r) * DD + c];
            Kts[(c + 0) * 64 + r] = kv.x;
            Kts[(c + 1) * 64 + r] = kv.y;
            Kts[(c + 2) * 64 + r] = kv.z;
            Kts[(c + 3) * 64 + r] = kv.w;
            *(float4*)&Vs[r * 64 + c] = *(const float4*)&vp[(size_t)(col0 + r) * DD + c];
        }
        __syncthreads();

        float sacc[4][4];
        #pragma unroll
        for (int i = 0; i < 4; i++)
            #pragma unroll
            for (int j = 0; j < 4; j++) sacc[i][j] = 0.f;

        #pragma unroll 8
        for (int d = 0; d < 64; d++) {
            float qa[4];
            #pragma unroll
            for (int i = 0; i < 4; i++) qa[i] = Qs[(ty * 4 + i) * 64 + d];
            float4 kb = *(const float4*)&Kts[d * 64 + tx * 4];
            float rb[4] = {kb.x, kb.y, kb.z, kb.w};
            #pragma unroll
            for (int i = 0; i < 4; i++)
                #pragma unroll
                for (int j = 0; j < 4; j++)
                    sacc[i][j] += qa[i] * rb[j];
        }

        #pragma unroll
        for (int i = 0; i < 4; i++) {
            int rg = row0 + ty * 4 + i;
            #pragma unroll
            for (int j = 0; j < 4; j++) {
                int cg = col0 + tx * 4 + j;
                float val = (cg <= rg) ? sacc[i][j] * sscale : -CUDART_INF_F;
                Ps[(ty * 4 + i) * 65 + tx * 4 + j] = val;
            }
        }
        __syncthreads();

        if (tid < 64) {
            const int i = tid;
            float mold = mrow[i];
            float mnew = mold;
            #pragma unroll 8
            for (int j = 0; j < 64; j++) mnew = fmaxf(mnew, Ps[i * 65 + j]);
            float alpha = exp2f(mold - mnew);
            float l = lrow[i] * alpha;
            #pragma unroll 8
            for (int j = 0; j < 64; j++) {
                float p = exp2f(Ps[i * 65 + j] - mnew);
                Ps[i * 65 + j] = p;
                l += p;
            }
            mrow[i] = mnew; lrow[i] = l; arow[i] = alpha;
        }
        __syncthreads();

        float al[4];
        #pragma unroll
        for (int i = 0; i < 4; i++) al[i] = arow[ty * 4 + i];
        #pragma unroll
        for (int i = 0; i < 4; i++)
            #pragma unroll
            for (int j = 0; j < 4; j++) o[i][j] *= al[i];

        #pragma unroll 8
        for (int j = 0; j < 64; j++) {
            float pa[4];
            #pragma unroll
            for (int i = 0; i < 4; i++) pa[i] = Ps[(ty * 4 + i) * 65 + j];
            float4 vb = *(const float4*)&Vs[j * 64 + tx * 4];
            float rv[4] = {vb.x, vb.y, vb.z, vb.w};
            #pragma unroll
            for (int i = 0; i < 4; i++)
                #pragma unroll
                for (int jj = 0; jj < 4; jj++)
                    o[i][jj] += pa[i] * rv[jj];
        }
        __syncthreads();
    }

    #pragma unroll
    for (int i = 0; i < 4; i++) {
        float inv = 1.f / lrow[ty * 4 + i];
        float4 out;
        out.x = o[i][0] * inv;
        out.y = o[i][1] * inv;
        out.z = o[i][2] * inv;
        out.w = o[i][3] * inv;
        *(float4*)&g_o[((size_t)bh * SS + row0 + ty * 4 + i) * DD + tx * 4] = out;
    }
}

// ---------------------------------------------------------------------------
extern "C" void kernel_launch(void* const* d_in, const int* in_sizes, int n_in,
                              void* d_out, int out_size)
{
    const float* x  = (const float*)d_in[0];
    const float* wq = (const float*)d_in[1];
    const float* bq = (const float*)d_in[2];
    const float* wk = (const float*)d_in[3];
    const float* bk = (const float*)d_in[4];
    const float* wv = (const float*)d_in[5];
    const float* bv = (const float*)d_in[6];
    const float* wo = (const float*)d_in[7];
    const float* bo = (const float*)d_in[8];
    float* y = (float*)d_out;

    (void)in_sizes; (void)n_in; (void)out_size;

    const int attn_smem = (3*64*64 + 64*65 + 3*64) * (int)sizeof(float);
    cudaFuncSetAttribute(qkv_mma_kernel, cudaFuncAttributeMaxDynamicSharedMemorySize,
                         GEMM_SMEM);
    cudaFuncSetAttribute(oproj_mma_kernel, cudaFuncAttributeMaxDynamicSharedMemorySize,
                         GEMM_SMEM);
    cudaFuncSetAttribute(attn_kernel, cudaFuncAttributeMaxDynamicSharedMemorySize,
                         attn_smem);

    // 1) Split/transpose prep (bf16 hi/lo)
    split_x_kernel<<<(MM * EE) / (256 * 8), 256>>>(x);
    split_w_kernel<<<dim3(16, 48), 256>>>(wq, wk, wv);
    split_wo_kernel<<<dim3(16, 16), 256>>>(wo);

    // 2) QKV projection (mma.sync bf16 split-3)
    qkv_mma_kernel<<<dim3(64, 48), 256, GEMM_SMEM>>>(bq, bk, bv);

    // 3) Flash attention (fp32)
    attn_kernel<<<dim3(32, 64), 256, attn_smem>>>();

    // 4) Split attention output, then output projection (mma.sync)
    split_o_kernel<<<(MM * EE) / (256 * 8), 256>>>();
    oproj_mma_kernel<<<dim3(64, 16), 256, GEMM_SMEM>>>(bo, y);
}

// round 4
// speedup vs baseline: 3.3405x; 2.1498x over previous
#include <cuda_runtime.h>
#include <cuda_bf16.h>
#include <math_constants.h>
#include <cstdint>

#define BB 4
#define SS 2048
#define EE 1024
#define HH 16
#define DD 64
#define MM (BB*SS)   // 8192

// ---------------------------------------------------------------------------
// Device-global scratch (allocation-free rule)
// ---------------------------------------------------------------------------
__device__ __align__(16) __nv_bfloat16 g_xhi[MM*EE];
__device__ __align__(16) __nv_bfloat16 g_xlo[MM*EE];
__device__ __align__(16) __nv_bfloat16 g_whi[48*DD*EE];   // [z][d][e], z=which*16+h
__device__ __align__(16) __nv_bfloat16 g_wlo[48*DD*EE];
__device__ __align__(16) __nv_bfloat16 g_wohi[EE*EE];     // [n][k] (wo transposed)
__device__ __align__(16) __nv_bfloat16 g_wolo[EE*EE];

// Q/K/V in split bf16, layout [bh][s][d] (bh = b*16+h), 128B rows
__device__ __align__(16) __nv_bfloat16 g_qhi[BB*HH*SS*DD];
__device__ __align__(16) __nv_bfloat16 g_qlo[BB*HH*SS*DD];
__device__ __align__(16) __nv_bfloat16 g_khi[BB*HH*SS*DD];
__device__ __align__(16) __nv_bfloat16 g_klo[BB*HH*SS*DD];
__device__ __align__(16) __nv_bfloat16 g_vhi[BB*HH*SS*DD];
__device__ __align__(16) __nv_bfloat16 g_vlo[BB*HH*SS*DD];

// Attention output, head-concat layout [m][h*64+d], split bf16
__device__ __align__(16) __nv_bfloat16 g_ohi[MM*EE];
__device__ __align__(16) __nv_bfloat16 g_olo[MM*EE];

// ---------------------------------------------------------------------------
// mma.sync / ldmatrix / cp.async helpers (base-arch; no tcgen05 under sm_103)
// ---------------------------------------------------------------------------
__device__ __forceinline__ uint32_t smem_to_u32(const void* p) {
    uint32_t a;
    asm("{ .reg .u64 t; cvta.to.shared.u64 t, %1; cvt.u32.u64 %0, t; }"
        : "=r"(a) : "l"(p));
    return a;
}
__device__ __forceinline__ void cp16(uint32_t saddr, const void* gaddr) {
    asm volatile("cp.async.cg.shared.global [%0], [%1], 16;"
                 :: "r"(saddr), "l"(gaddr));
}
#define CP_COMMIT() asm volatile("cp.async.commit_group;" ::: "memory")
#define CP_WAIT1()  asm volatile("cp.async.wait_group 1;" ::: "memory")
#define CP_WAIT0()  asm volatile("cp.async.wait_group 0;" ::: "memory")

__device__ __forceinline__ void ldmx4(uint32_t* r, uint32_t addr) {
    asm volatile("ldmatrix.sync.aligned.m8n8.x4.shared.b16 {%0,%1,%2,%3}, [%4];"
        : "=r"(r[0]), "=r"(r[1]), "=r"(r[2]), "=r"(r[3]) : "r"(addr));
}
__device__ __forceinline__ void ldmx4t(uint32_t* r, uint32_t addr) {
    asm volatile("ldmatrix.sync.aligned.m8n8.x4.trans.shared.b16 {%0,%1,%2,%3}, [%4];"
        : "=r"(r[0]), "=r"(r[1]), "=r"(r[2]), "=r"(r[3]) : "r"(addr));
}
__device__ __forceinline__ void mma16816(float* c, const uint32_t* a,
                                         uint32_t b0, uint32_t b1) {
    asm volatile("mma.sync.aligned.m16n8k16.row.col.f32.bf16.bf16.f32 "
        "{%0,%1,%2,%3}, {%4,%5,%6,%7}, {%8,%9}, {%0,%1,%2,%3};"
        : "+f"(c[0]), "+f"(c[1]), "+f"(c[2]), "+f"(c[3])
        : "r"(a[0]), "r"(a[1]), "r"(a[2]), "r"(a[3]), "r"(b0), "r"(b1));
}

#define SWZ64(off)  ((off) ^ (((off) >> 3) & 0x30))   // 64B rows
#define SWZ128(off) ((off) ^ (((off) >> 3) & 0x70))   // 128B rows

// ---------------------------------------------------------------------------
// Split helpers
// ---------------------------------------------------------------------------
__device__ __forceinline__ void split1(float v, __nv_bfloat16& h, __nv_bfloat16& l) {
    h = __float2bfloat16_rn(v);
    l = __float2bfloat16_rn(v - __bfloat162float(h));
}
__device__ __forceinline__ uint32_t pck(__nv_bfloat16 a, __nv_bfloat16 b) {
    return ((uint32_t)__bfloat16_as_ushort(b) << 16) | (uint32_t)__bfloat16_as_ushort(a);
}
__device__ __forceinline__ void split_pair(float v0, float v1,
                                           uint32_t& hi, uint32_t& lo) {
    __nv_bfloat16 h0, l0, h1, l1;
    split1(v0, h0, l0); split1(v1, h1, l1);
    hi = pck(h0, h1); lo = pck(l0, l1);
}

// x [8192x1024] fp32 -> hi/lo bf16
__global__ __launch_bounds__(256) void split_x_kernel(const float* __restrict__ x) {
    size_t i = ((size_t)blockIdx.x * 256 + threadIdx.x) * 8;
    float4 v0 = *(const float4*)(x + i);
    float4 v1 = *(const float4*)(x + i + 4);
    float vv[8] = {v0.x, v0.y, v0.z, v0.w, v1.x, v1.y, v1.z, v1.w};
    __nv_bfloat16 h[8], l[8];
    #pragma unroll
    for (int j = 0; j < 8; j++) split1(vv[j], h[j], l[j]);
    uint4 uh = {pck(h[0],h[1]), pck(h[2],h[3]), pck(h[4],h[5]), pck(h[6],h[7])};
    uint4 ul = {pck(l[0],l[1]), pck(l[2],l[3]), pck(l[4],l[5]), pck(l[6],l[7])};
    *(uint4*)(g_xhi + i) = uh;
    *(uint4*)(g_xlo + i) = ul;
}

// wq/wk/wv [16][1024][64] -> g_w{hi,lo} [z][d][e] (transposed, split)
__global__ __launch_bounds__(256) void split_w_kernel(
    const float* __restrict__ wq, const float* __restrict__ wk, const float* __restrict__ wv) {
    __shared__ float t[64][65];
    const int z = blockIdx.y;
    const int which = z >> 4, h = z & 15;
    const float* W = (which == 0 ? wq : which == 1 ? wk : wv) + (size_t)h * EE * DD;
    const int e0 = blockIdx.x * 64;
    const int tid = threadIdx.x;
    #pragma unroll
    for (int q = 0; q < 4; q++) {
        int idx = q * 256 + tid;
        int r = idx >> 4, c = (idx & 15) * 4;
        float4 v = *(const float4*)(W + (size_t)(e0 + r) * DD + c);
        t[r][c] = v.x; t[r][c+1] = v.y; t[r][c+2] = v.z; t[r][c+3] = v.w;
    }
    __syncthreads();
    #pragma unroll
    for (int q = 0; q < 4; q++) {
        int idx = q * 256 + tid;
        int d = idx >> 4, e = (idx & 15) * 4;
        __nv_bfloat16 h4[4], l4[4];
        #pragma unroll
        for (int j = 0; j < 4; j++) split1(t[e + j][d], h4[j], l4[j]);
        size_t o = ((size_t)z * DD + d) * EE + e0 + e;
        *(uint32_t*)(g_whi + o)     = pck(h4[0], h4[1]);
        *(uint32_t*)(g_whi + o + 2) = pck(h4[2], h4[3]);
        *(uint32_t*)(g_wlo + o)     = pck(l4[0], l4[1]);
        *(uint32_t*)(g_wlo + o + 2) = pck(l4[2], l4[3]);
    }
}

// wo [1024 k][1024 n] -> g_wo{hi,lo} [n][k] (transposed, split)
__global__ __launch_bounds__(256) void split_wo_kernel(const float* __restrict__ wo) {
    __shared__ float t[64][65];
    const int k0 = blockIdx.x * 64;
    const int n0 = blockIdx.y * 64;
    const int tid = threadIdx.x;
    #pragma unroll
    for (int q = 0; q < 4; q++) {
        int idx = q * 256 + tid;
        int r = idx >> 4, c = (idx & 15) * 4;
        float4 v = *(const float4*)(wo + (size_t)(k0 + r) * EE + n0 + c);
        t[r][c] = v.x; t[r][c+1] = v.y; t[r][c+2] = v.z; t[r][c+3] = v.w;
    }
    __syncthreads();
    #pragma unroll
    for (int q = 0; q < 4; q++) {
        int idx = q * 256 + tid;
        int d = idx >> 4, e = (idx & 15) * 4;
        __nv_bfloat16 h4[4], l4[4];
        #pragma unroll
        for (int j = 0; j < 4; j++) split1(t[e + j][d], h4[j], l4[j]);
        size_t o = (size_t)(n0 + d) * EE + k0 + e;
        *(uint32_t*)(g_wohi + o)     = pck(h4[0], h4[1]);
        *(uint32_t*)(g_wohi + o + 2) = pck(h4[2], h4[3]);
        *(uint32_t*)(g_wolo + o)     = pck(l4[0], l4[1]);
        *(uint32_t*)(g_wolo + o + 2) = pck(l4[2], l4[3]);
    }
}

// ---------------------------------------------------------------------------
// Shared GEMM core: C[128x64] += A[128x1024] * B[64x1024]^T, split-bf16 3-pass.
// (unchanged from R3 — proven)
// ---------------------------------------------------------------------------
#define STAGE_BYTES 24576
#define GEMM_SMEM   (3 * STAGE_BYTES)

__device__ __forceinline__ void load_stage(
    uint32_t sb, int s, int kt, int tid,
    const char* agh, const char* agl, const char* bgh, const char* bgl)
{
    const uint32_t sA = sb + (uint32_t)s * STAGE_BYTES;
    const size_t gk = (size_t)kt * 64 + (size_t)((tid & 3) * 16);
    const int c16 = (tid & 3) * 16;
    #pragma unroll
    for (int i = 0; i < 2; ++i) {
        int row = i * 64 + (tid >> 2);
        uint32_t so = SWZ64((uint32_t)(row * 64 + c16));
        cp16(sA + so,        agh + (size_t)row * 2048 + gk);
        cp16(sA + 8192 + so, agl + (size_t)row * 2048 + gk);
    }
    {
        int row = tid >> 2;
        uint32_t so = SWZ64((uint32_t)(row * 64 + c16));
        cp16(sA + 16384 + so, bgh + (size_t)row * 2048 + gk);
        cp16(sA + 20480 + so, bgl + (size_t)row * 2048 + gk);
    }
}

__device__ __forceinline__ void gemm_core_128x64(
    uint32_t sb,
    const char* agh, const char* agl, const char* bgh, const char* bgl,
    float acc[2][4][4])
{
    const int tid = threadIdx.x;
    const int warp = tid >> 5, lane = tid & 31;
    const int wm = (warp & 3) * 32;
    const int wn = (warp >> 2) * 32;

    uint32_t offA[2][2], offB[2][2];
    {
        const int rbA = (lane & 7) + ((lane >> 3) & 1) * 8;
        const int cA  = (lane >> 4) & 1;
        const int rbB = (lane & 7) + ((lane >> 4) & 1) * 8;
        const int cB  = (lane >> 3) & 1;
        #pragma unroll
        for (int f = 0; f < 2; ++f)
            #pragma unroll
            for (int s = 0; s < 2; ++s) {
                offA[f][s] = SWZ64((uint32_t)((wm + f*16 + rbA) * 64 + (s*2 + cA) * 16));
                offB[f][s] = SWZ64((uint32_t)((wn + f*16 + rbB) * 64 + (s*2 + cB) * 16));
            }
    }
    #pragma unroll
    for (int f = 0; f < 2; f++)
        #pragma unroll
        for (int nf = 0; nf < 4; nf++)
            #pragma unroll
            for (int i = 0; i < 4; i++) acc[f][nf][i] = 0.f;

    load_stage(sb, 0, 0, tid, agh, agl, bgh, bgl); CP_COMMIT();
    load_stage(sb, 1, 1, tid, agh, agl, bgh, bgl); CP_COMMIT();

    for (int kt = 0; kt < 32; ++kt) {
        CP_WAIT1();
        __syncthreads();
        if (kt + 2 < 32)
            load_stage(sb, (kt + 2) % 3, kt + 2, tid, agh, agl, bgh, bgl);
        CP_COMMIT();

        const uint32_t base = sb + (uint32_t)(kt % 3) * STAGE_BYTES;
        #pragma unroll
        for (int s16 = 0; s16 < 2; ++s16) {
            uint32_t ah0[4], ah1[4], al0[4], al1[4];
            uint32_t bh0[4], bh1[4], bl0[4], bl1[4];
            ldmx4(ah0, base + offA[0][s16]);
            ldmx4(ah1, base + offA[1][s16]);
            ldmx4(al0, base + 8192 + offA[0][s16]);
            ldmx4(al1, base + 8192 + offA[1][s16]);
            ldmx4(bh0, base + 16384 + offB[0][s16]);
            ldmx4(bh1, base + 16384 + offB[1][s16]);
            ldmx4(bl0, base + 20480 + offB[0][s16]);
            ldmx4(bl1, base + 20480 + offB[1][s16]);
            uint32_t* ah[2] = {ah0, ah1};
            uint32_t* al[2] = {al0, al1};
            uint32_t* bh[2] = {bh0, bh1};
            uint32_t* bl[2] = {bl0, bl1};
            #pragma unroll
            for (int f = 0; f < 2; ++f) {
                #pragma unroll
                for (int nf = 0; nf < 4; ++nf) {
                    uint32_t b0h = bh[nf >> 1][(nf & 1) * 2];
                    uint32_t b1h = bh[nf >> 1][(nf & 1) * 2 + 1];
                    uint32_t b0l = bl[nf >> 1][(nf & 1) * 2];
                    uint32_t b1l = bl[nf >> 1][(nf & 1) * 2 + 1];
                    mma16816(acc[f][nf], ah[f], b0h, b1h);
                    mma16816(acc[f][nf], ah[f], b0l, b1l);
                    mma16816(acc[f][nf], al[f], b0h, b1h);
                }
            }
        }
    }
}

// ---------------------------------------------------------------------------
// QKV projection: epilogue writes split bf16 [bh][s][d] directly.
// ---------------------------------------------------------------------------
__global__ __launch_bounds__(256) void qkv_mma_kernel(
    const float* __restrict__ bq, const float* __restrict__ bk,
    const float* __restrict__ bv)
{
    extern __shared__ char smem[];
    const uint32_t sb = smem_to_u32(smem);
    const int tid = threadIdx.x;
    const int m0 = blockIdx.x * 128;
    const int z = blockIdx.y;
    const int which = z >> 4, h = z & 15;

    const char* agh = (const char*)(g_xhi + (size_t)m0 * EE);
    const char* agl = (const char*)(g_xlo + (size_t)m0 * EE);
    const char* bgh = (const char*)(g_whi + (size_t)z * DD * EE);
    const char* bgl = (const char*)(g_wlo + (size_t)z * DD * EE);

    float acc[2][4][4];
    gemm_core_128x64(sb, agh, agl, bgh, bgl, acc);

    const float* bp = (which == 0 ? bq : which == 1 ? bk : bv) + h * DD;
    __nv_bfloat16* ohp = (which == 0 ? g_qhi : which == 1 ? g_khi : g_vhi);
    __nv_bfloat16* olp = (which == 0 ? g_qlo : which == 1 ? g_klo : g_vlo);

    const int warp = tid >> 5, lane = tid & 31;
    const int wm = (warp & 3) * 32, wn = (warp >> 2) * 32;
    const int r = lane >> 2, cp2 = (lane & 3) * 2;
    #pragma unroll
    for (int f = 0; f < 2; ++f) {
        #pragma unroll
        for (int half = 0; half < 2; ++half) {
            int m = m0 + wm + f * 16 + r + half * 8;
            int b = m >> 11, s = m & 2047;
            size_t rowoff = (((size_t)b * HH + h) * SS + s) * DD;
            #pragma unroll
            for (int nf = 0; nf < 4; ++nf) {
                int col = wn + nf * 8 + cp2;
                float v0 = acc[f][nf][half * 2 + 0] + bp[col];
                float v1 = acc[f][nf][half * 2 + 1] + bp[col + 1];
                uint32_t hi, lo;
                split_pair(v0, v1, hi, lo);
                *(uint32_t*)(ohp + rowoff + col) = hi;
                *(uint32_t*)(olp + rowoff + col) = lo;
            }
        }
    }
}

// ---------------------------------------------------------------------------
// Output projection (unchanged from R3)
// ---------------------------------------------------------------------------
__global__ __launch_bounds__(256) void oproj_mma_kernel(
    const float* __restrict__ bo, float* __restrict__ y)
{
    extern __shared__ char smem[];
    const uint32_t sb = smem_to_u32(smem);
    const int tid = threadIdx.x;
    const int m0 = blockIdx.x * 128;
    const int n0 = blockIdx.y * 64;

    const char* agh = (const char*)(g_ohi + (size_t)m0 * EE);
    const char* agl = (const char*)(g_olo + (size_t)m0 * EE);
    const char* bgh = (const char*)(g_wohi + (size_t)n0 * EE);
    const char* bgl = (const char*)(g_wolo + (size_t)n0 * EE);

    float acc[2][4][4];
    gemm_core_128x64(sb, agh, agl, bgh, bgl, acc);

    const int warp = tid >> 5, lane = tid & 31;
    const int wm = (warp & 3) * 32, wn = (warp >> 2) * 32;
    const int r = lane >> 2, cp2 = (lane & 3) * 2;
    #pragma unroll
    for (int f = 0; f < 2; ++f) {
        #pragma unroll
        for (int half = 0; half < 2; ++half) {
            int m = m0 + wm + f * 16 + r + half * 8;
            float* row = y + (size_t)m * EE + n0;
            #pragma unroll
            for (int nf = 0; nf < 4; ++nf) {
                int col = wn + nf * 8 + cp2;
                float2 v;
                v.x = acc[f][nf][half * 2 + 0] + bo[n0 + col];
                v.y = acc[f][nf][half * 2 + 1] + bo[n0 + col + 1];
                *(float2*)(row + col) = v;
            }
        }
    }
}

// ---------------------------------------------------------------------------
// Flash attention on mma.sync, split-bf16, causal.
// Block: 256 threads (8 warps), Br=128 (16 rows/warp), Bc=64, D=64.
// smem: 2 stages x 32KB (Khi 8K | Klo 8K | Vhi 8K | Vlo 8K), 128B rows, SW128.
// ---------------------------------------------------------------------------
#define AT_STAGE 32768
#define AT_SMEM  (2 * AT_STAGE)

__device__ __forceinline__ void attn_load_kv(
    uint32_t sb, int stage, int ct, int tid,
    const char* khg, const char* klg, const char* vhg, const char* vlg)
{
    const uint32_t st = sb + (uint32_t)stage * AT_STAGE;
    const int col0 = ct * 64;
    #pragma unroll
    for (int p = 0; p < 2; ++p) {
        int idx = p * 256 + tid;
        int r = idx >> 3, c16 = (idx & 7) * 16;
        uint32_t so = SWZ128((uint32_t)(r * 128 + c16));
        size_t g = (size_t)(col0 + r) * 128 + c16;
        cp16(st + so,         khg + g);
        cp16(st +  8192 + so, klg + g);
        cp16(st + 16384 + so, vhg + g);
        cp16(st + 24576 + so, vlg + g);
    }
}

__global__ __launch_bounds__(256, 1) void attn_mma_kernel()
{
    extern __shared__ char smem[];
    const uint32_t sb = smem_to_u32(smem);
    const int tid = threadIdx.x;
    const int warp = tid >> 5, lane = tid & 31;
    const int rt = blockIdx.x;            // 0..15 (128-row tiles)
    const int bh = blockIdx.y;            // 0..63
    const int row0 = rt * 128;
    const int wm = warp * 16;

    const char* qhg = (const char*)(g_qhi + (size_t)bh * SS * DD);
    const char* qlg = (const char*)(g_qlo + (size_t)bh * SS * DD);
    const char* khg = (const char*)(g_khi + (size_t)bh * SS * DD);
    const char* klg = (const char*)(g_klo + (size_t)bh * SS * DD);
    const char* vhg = (const char*)(g_vhi + (size_t)bh * SS * DD);
    const char* vlg = (const char*)(g_vlo + (size_t)bh * SS * DD);

    // ---- load Q tile (hi at sb, lo at sb+16K), extract A-fragments ----
    #pragma unroll
    for (int p = 0; p < 4; ++p) {
        int idx = p * 256 + tid;
        int r = idx >> 3, c16 = (idx & 7) * 16;
        uint32_t so = SWZ128((uint32_t)(r * 128 + c16));
        size_t g = (size_t)(row0 + r) * 128 + c16;
        cp16(sb + so,         qhg + g);
        cp16(sb + 16384 + so, qlg + g);
    }
    CP_COMMIT();
    CP_WAIT0();
    __syncthreads();

    const int rbA = (lane & 7) + ((lane >> 3) & 1) * 8;
    const int cA  = (lane >> 4) & 1;
    uint32_t qfh[4][4], qfl[4][4];
    #pragma unroll
    for (int c = 0; c < 4; ++c) {
        uint32_t off = SWZ128((uint32_t)((wm + rbA) * 128 + (c * 2 + cA) * 16));
        ldmx4(qfh[c], sb + off);
        ldmx4(qfl[c], sb + 16384 + off);
    }
    __syncthreads();   // done reading Q smem; stages may overwrite

    // ---- state ----
    float o[8][4];
    #pragma unroll
    for (int nf = 0; nf < 8; nf++)
        #pragma unroll
        for (int i = 0; i < 4; i++) o[nf][i] = 0.f;
    float mprev0 = -CUDART_INF_F, mprev1 = -CUDART_INF_F;
    float lsum0 = 0.f, lsum1 = 0.f;

    const float sc = 0.125f * 1.4426950408889634f;   // 1/sqrt(D) * log2(e)
    const int nct = 2 * rt + 2;

    // B-fragment lane geometry (K: non-trans; V: trans — same addr pattern as A)
    const int rbB = (lane & 7) + ((lane >> 4) & 1) * 8;
    const int cB  = (lane >> 3) & 1;
    const int lr  = lane >> 2;          // row within 8
    const int lc2 = (lane & 3) * 2;     // col pair within 8
    const int r0g = row0 + wm + lr;     // global rows r0g, r0g+8

    // ---- pipeline prologue ----
    attn_load_kv(sb, 0, 0, tid, khg, klg, vhg, vlg); CP_COMMIT();
    if (nct > 1) attn_load_kv(sb, 1, 1, tid, khg, klg, vhg, vlg);
    CP_COMMIT();

    for (int ct = 0; ct < nct; ++ct) {
        CP_WAIT1();
        __syncthreads();
        const uint32_t base = sb + (uint32_t)(ct & 1) * AT_STAGE;

        // ---- S = Q K^T (3-pass split) ----
        float s[8][4];
        #pragma unroll
        for (int nf = 0; nf < 8; nf++)
            #pragma unroll
            for (int i = 0; i < 4; i++) s[nf][i] = 0.f;

        #pragma unroll
        for (int c = 0; c < 4; ++c) {          // k16 chunks over d
            uint32_t kh[4][4], kl[4][4];
            #pragma unroll
            for (int g = 0; g < 4; ++g) {      // kv 16-row groups
                uint32_t off = SWZ128((uint32_t)((g * 16 + rbB) * 128 + (c * 2 + cB) * 16));
                ldmx4(kh[g], base + off);
                ldmx4(kl[g], base + 8192 + off);
            }
            #pragma unroll
            for (int nf = 0; nf < 8; ++nf) {
                int g = nf >> 1, i = (nf & 1) * 2;
                mma16816(s[nf], qfh[c], kh[g][i], kh[g][i + 1]);
                mma16816(s[nf], qfh[c], kl[g][i], kl[g][i + 1]);
                mma16816(s[nf], qfl[c], kh[g][i], kh[g][i + 1]);
            }
        }

        // ---- causal mask ----
        if (ct * 64 + 63 > row0 + wm) {
            #pragma unroll
            for (int nf = 0; nf < 8; ++nf) {
                int cg = ct * 64 + nf * 8 + lc2;
                if (cg     > r0g)     s[nf][0] = -CUDART_INF_F;
                if (cg + 1 > r0g)     s[nf][1] = -CUDART_INF_F;
                if (cg     > r0g + 8) s[nf][2] = -CUDART_INF_F;
                if (cg + 1 > r0g + 8) s[nf][3] = -CUDART_INF_F;
            }
        }

        // ---- online softmax ----
        float mt0 = -CUDART_INF_F, mt1 = -CUDART_INF_F;
        #pragma unroll
        for (int nf = 0; nf < 8; ++nf) {
            mt0 = fmaxf(mt0, fmaxf(s[nf][0], s[nf][1]));
            mt1 = fmaxf(mt1, fmaxf(s[nf][2], s[nf][3]));
        }
        mt0 = fmaxf(mt0, __shfl_xor_sync(0xffffffffu, mt0, 1));
        mt0 = fmaxf(mt0, __shfl_xor_sync(0xffffffffu, mt0, 2));
        mt1 = fmaxf(mt1, __shfl_xor_sync(0xffffffffu, mt1, 1));
        mt1 = fmaxf(mt1, __shfl_xor_sync(0xffffffffu, mt1, 2));

        float mn0 = fmaxf(mprev0, mt0);
        float mn1 = fmaxf(mprev1, mt1);
        float a0 = exp2f((mprev0 - mn0) * sc);
        float a1 = exp2f((mprev1 - mn1) * sc);
        lsum0 *= a0; lsum1 *= a1;
        #pragma unroll
        for (int nf = 0; nf < 8; ++nf) {
            s[nf][0] = exp2f((s[nf][0] - mn0) * sc);
            s[nf][1] = exp2f((s[nf][1] - mn0) * sc);
            s[nf][2] = exp2f((s[nf][2] - mn1) * sc);
            s[nf][3] = exp2f((s[nf][3] - mn1) * sc);
            lsum0 += s[nf][0] + s[nf][1];
            lsum1 += s[nf][2] + s[nf][3];
            o[nf][0] *= a0; o[nf][1] *= a0;
            o[nf][2] *= a1; o[nf][3] *= a1;
        }
        mprev0 = mn0; mprev1 = mn1;

        // ---- pack P into split-bf16 A-fragments ----
        uint32_t pfh[4][4], pfl[4][4];
        #pragma unroll
        for (int kk = 0; kk < 4; ++kk) {
            split_pair(s[2*kk][0],   s[2*kk][1],   pfh[kk][0], pfl[kk][0]);
            split_pair(s[2*kk][2],   s[2*kk][3],   pfh[kk][1], pfl[kk][1]);
            split_pair(s[2*kk+1][0], s[2*kk+1][1], pfh[kk][2], pfl[kk][2]);
            split_pair(s[2*kk+1][2], s[2*kk+1][3], pfh[kk][3], pfl[kk][3]);
        }

        // ---- O += P V (3-pass split, ldmatrix.trans for V) ----
        #pragma unroll
        for (int kk = 0; kk < 4; ++kk) {       // kv16 chunks (k dim)
            #pragma unroll
            for (int dd = 0; dd < 4; ++dd) {   // d16 groups
                uint32_t vh[4], vl[4];
                uint32_t off = SWZ128((uint32_t)((kk * 16 + rbA) * 128 + (dd * 2 + cA) * 16));
                ldmx4t(vh, base + 16384 + off);
                ldmx4t(vl, base + 24576 + off);
                #pragma unroll
                for (int j = 0; j < 2; ++j) {
                    int nf = dd * 2 + j;
                    uint32_t b0h = vh[j * 2], b1h = vh[j * 2 + 1];
                    uint32_t b0l = vl[j * 2], b1l = vl[j * 2 + 1];
                    mma16816(o[nf], pfh[kk], b0h, b1h);
                    mma16816(o[nf], pfh[kk], b0l, b1l);
                    mma16816(o[nf], pfl[kk], b0h, b1h);
                }
            }
        }

        __syncthreads();   // all warps done reading this stage
        if (ct + 2 < nct)
            attn_load_kv(sb, ct & 1, ct + 2, tid, khg, klg, vhg, vlg);
        CP_COMMIT();
    }

    // ---- finalize: row sums across quad, normalize, write split output ----
    lsum0 += __shfl_xor_sync(0xffffffffu, lsum0, 1);
    lsum0 += __shfl_xor_sync(0xffffffffu, lsum0, 2);
    lsum1 += __shfl_xor_sync(0xffffffffu, lsum1, 1);
    lsum1 += __shfl_xor_sync(0xffffffffu, lsum1, 2);
    float inv0 = 1.f / lsum0;
    float inv1 = 1.f / lsum1;

    const int b = bh >> 4, h = bh & 15;
    const size_t m0G = (size_t)b * SS + (size_t)(row0 + wm + lr);
    __nv_bfloat16* oh0 = g_ohi + m0G * EE + h * DD;
    __nv_bfloat16* ol0 = g_olo + m0G * EE + h * DD;
    __nv_bfloat16* oh1 = oh0 + (size_t)8 * EE;
    __nv_bfloat16* ol1 = ol0 + (size_t)8 * EE;
    #pragma unroll
    for (int nf = 0; nf < 8; ++nf) {
        int col = nf * 8 + lc2;
        uint32_t hi, lo;
        split_pair(o[nf][0] * inv0, o[nf][1] * inv0, hi, lo);
        *(uint32_t*)(oh0 + col) = hi;
        *(uint32_t*)(ol0 + col) = lo;
        split_pair(o[nf][2] * inv1, o[nf][3] * inv1, hi, lo);
        *(uint32_t*)(oh1 + col) = hi;
        *(uint32_t*)(ol1 + col) = lo;
    }
}

// ---------------------------------------------------------------------------
extern "C" void kernel_launch(void* const* d_in, const int* in_sizes, int n_in,
                              void* d_out, int out_size)
{
    const float* x  = (const float*)d_in[0];
    const float* wq = (const float*)d_in[1];
    const float* bq = (const float*)d_in[2];
    const float* wk = (const float*)d_in[3];
    const float* bk = (const float*)d_in[4];
    const float* wv = (const float*)d_in[5];
    const float* bv = (const float*)d_in[6];
    const float* wo = (const float*)d_in[7];
    const float* bo = (const float*)d_in[8];
    float* y = (float*)d_out;

    (void)in_sizes; (void)n_in; (void)out_size;

    cudaFuncSetAttribute(qkv_mma_kernel, cudaFuncAttributeMaxDynamicSharedMemorySize,
                         GEMM_SMEM);
    cudaFuncSetAttribute(oproj_mma_kernel, cudaFuncAttributeMaxDynamicSharedMemorySize,
                         GEMM_SMEM);
    cudaFuncSetAttribute(attn_mma_kernel, cudaFuncAttributeMaxDynamicSharedMemorySize,
                         AT_SMEM);

    // 1) Split/transpose prep (bf16 hi/lo)
    split_x_kernel<<<(MM * EE) / (256 * 8), 256>>>(x);
    split_w_kernel<<<dim3(16, 48), 256>>>(wq, wk, wv);
    split_wo_kernel<<<dim3(16, 16), 256>>>(wo);

    // 2) QKV projection (mma.sync, writes split bf16 Q/K/V)
    qkv_mma_kernel<<<dim3(64, 48), 256, GEMM_SMEM>>>(bq, bk, bv);

    // 3) Flash attention (mma.sync, split bf16, writes split concat output)
    attn_mma_kernel<<<dim3(16, 64), 256, AT_SMEM>>>();

    // 4) Output projection (mma.sync)
    oproj_mma_kernel<<<dim3(64, 16), 256, GEMM_SMEM>>>(bo, y);
}

// round 5
// speedup vs baseline: 3.3670x; 1.0079x over previous
#include <cuda_runtime.h>
#include <cuda_bf16.h>
#include <math_constants.h>
#include <cstdint>

#define BB 4
#define SS 2048
#define EE 1024
#define HH 16
#define DD 64
#define MM (BB*SS)   // 8192

// ---------------------------------------------------------------------------
// Device-global scratch (allocation-free rule)
// ---------------------------------------------------------------------------
__device__ __align__(16) __nv_bfloat16 g_xhi[MM*EE];
__device__ __align__(16) __nv_bfloat16 g_xlo[MM*EE];
__device__ __align__(16) __nv_bfloat16 g_whi[48*DD*EE];   // [z*64+d][e] == W_all^T
__device__ __align__(16) __nv_bfloat16 g_wlo[48*DD*EE];
__device__ __align__(16) __nv_bfloat16 g_wohi[EE*EE];     // [n][k] (wo transposed)
__device__ __align__(16) __nv_bfloat16 g_wolo[EE*EE];

// Q/K/V in split bf16, layout [bh][s][d] (bh = b*16+h), 128B rows
__device__ __align__(16) __nv_bfloat16 g_qhi[BB*HH*SS*DD];
__device__ __align__(16) __nv_bfloat16 g_qlo[BB*HH*SS*DD];
__device__ __align__(16) __nv_bfloat16 g_khi[BB*HH*SS*DD];
__device__ __align__(16) __nv_bfloat16 g_klo[BB*HH*SS*DD];
__device__ __align__(16) __nv_bfloat16 g_vhi[BB*HH*SS*DD];
__device__ __align__(16) __nv_bfloat16 g_vlo[BB*HH*SS*DD];

// Attention output, head-concat layout [m][h*64+d], split bf16
__device__ __align__(16) __nv_bfloat16 g_ohi[MM*EE];
__device__ __align__(16) __nv_bfloat16 g_olo[MM*EE];

// ---------------------------------------------------------------------------
// mma.sync / ldmatrix / cp.async helpers (base-arch; no tcgen05 under sm_103)
// ---------------------------------------------------------------------------
__device__ __forceinline__ uint32_t smem_to_u32(const void* p) {
    uint32_t a;
    asm("{ .reg .u64 t; cvta.to.shared.u64 t, %1; cvt.u32.u64 %0, t; }"
        : "=r"(a) : "l"(p));
    return a;
}
__device__ __forceinline__ void cp16(uint32_t saddr, const void* gaddr) {
    asm volatile("cp.async.cg.shared.global [%0], [%1], 16;"
                 :: "r"(saddr), "l"(gaddr));
}
#define CP_COMMIT() asm volatile("cp.async.commit_group;" ::: "memory")
#define CP_WAIT1()  asm volatile("cp.async.wait_group 1;" ::: "memory")
#define CP_WAIT0()  asm volatile("cp.async.wait_group 0;" ::: "memory")

__device__ __forceinline__ void ldmx4(uint32_t* r, uint32_t addr) {
    asm volatile("ldmatrix.sync.aligned.m8n8.x4.shared.b16 {%0,%1,%2,%3}, [%4];"
        : "=r"(r[0]), "=r"(r[1]), "=r"(r[2]), "=r"(r[3]) : "r"(addr));
}
__device__ __forceinline__ void ldmx4t(uint32_t* r, uint32_t addr) {
    asm volatile("ldmatrix.sync.aligned.m8n8.x4.trans.shared.b16 {%0,%1,%2,%3}, [%4];"
        : "=r"(r[0]), "=r"(r[1]), "=r"(r[2]), "=r"(r[3]) : "r"(addr));
}
__device__ __forceinline__ void mma16816(float* c, const uint32_t* a,
                                         uint32_t b0, uint32_t b1) {
    asm volatile("mma.sync.aligned.m16n8k16.row.col.f32.bf16.bf16.f32 "
        "{%0,%1,%2,%3}, {%4,%5,%6,%7}, {%8,%9}, {%0,%1,%2,%3};"
        : "+f"(c[0]), "+f"(c[1]), "+f"(c[2]), "+f"(c[3])
        : "r"(a[0]), "r"(a[1]), "r"(a[2]), "r"(a[3]), "r"(b0), "r"(b1));
}

#define SWZ64(off)  ((off) ^ (((off) >> 3) & 0x30))   // 64B rows
#define SWZ128(off) ((off) ^ (((off) >> 3) & 0x70))   // 128B rows

// ---------------------------------------------------------------------------
// Split helpers
// ---------------------------------------------------------------------------
__device__ __forceinline__ void split1(float v, __nv_bfloat16& h, __nv_bfloat16& l) {
    h = __float2bfloat16_rn(v);
    l = __float2bfloat16_rn(v - __bfloat162float(h));
}
__device__ __forceinline__ uint32_t pck(__nv_bfloat16 a, __nv_bfloat16 b) {
    return ((uint32_t)__bfloat16_as_ushort(b) << 16) | (uint32_t)__bfloat16_as_ushort(a);
}
__device__ __forceinline__ void split_pair(float v0, float v1,
                                           uint32_t& hi, uint32_t& lo) {
    __nv_bfloat16 h0, l0, h1, l1;
    split1(v0, h0, l0); split1(v1, h1, l1);
    hi = pck(h0, h1); lo = pck(l0, l1);
}

// x [8192x1024] fp32 -> hi/lo bf16
__global__ __launch_bounds__(256) void split_x_kernel(const float* __restrict__ x) {
    size_t i = ((size_t)blockIdx.x * 256 + threadIdx.x) * 8;
    float4 v0 = *(const float4*)(x + i);
    float4 v1 = *(const float4*)(x + i + 4);
    float vv[8] = {v0.x, v0.y, v0.z, v0.w, v1.x, v1.y, v1.z, v1.w};
    __nv_bfloat16 h[8], l[8];
    #pragma unroll
    for (int j = 0; j < 8; j++) split1(vv[j], h[j], l[j]);
    uint4 uh = {pck(h[0],h[1]), pck(h[2],h[3]), pck(h[4],h[5]), pck(h[6],h[7])};
    uint4 ul = {pck(l[0],l[1]), pck(l[2],l[3]), pck(l[4],l[5]), pck(l[6],l[7])};
    *(uint4*)(g_xhi + i) = uh;
    *(uint4*)(g_xlo + i) = ul;
}

// wq/wk/wv [16][1024][64] -> g_w{hi,lo} [z][d][e] (transposed, split)
__global__ __launch_bounds__(256) void split_w_kernel(
    const float* __restrict__ wq, const float* __restrict__ wk, const float* __restrict__ wv) {
    __shared__ float t[64][65];
    const int z = blockIdx.y;
    const int which = z >> 4, h = z & 15;
    const float* W = (which == 0 ? wq : which == 1 ? wk : wv) + (size_t)h * EE * DD;
    const int e0 = blockIdx.x * 64;
    const int tid = threadIdx.x;
    #pragma unroll
    for (int q = 0; q < 4; q++) {
        int idx = q * 256 + tid;
        int r = idx >> 4, c = (idx & 15) * 4;
        float4 v = *(const float4*)(W + (size_t)(e0 + r) * DD + c);
        t[r][c] = v.x; t[r][c+1] = v.y; t[r][c+2] = v.z; t[r][c+3] = v.w;
    }
    __syncthreads();
    #pragma unroll
    for (int q = 0; q < 4; q++) {
        int idx = q * 256 + tid;
        int d = idx >> 4, e = (idx & 15) * 4;
        __nv_bfloat16 h4[4], l4[4];
        #pragma unroll
        for (int j = 0; j < 4; j++) split1(t[e + j][d], h4[j], l4[j]);
        size_t o = ((size_t)z * DD + d) * EE + e0 + e;
        *(uint32_t*)(g_whi + o)     = pck(h4[0], h4[1]);
        *(uint32_t*)(g_whi + o + 2) = pck(h4[2], h4[3]);
        *(uint32_t*)(g_wlo + o)     = pck(l4[0], l4[1]);
        *(uint32_t*)(g_wlo + o + 2) = pck(l4[2], l4[3]);
    }
}

// wo [1024 k][1024 n] -> g_wo{hi,lo} [n][k] (transposed, split)
__global__ __launch_bounds__(256) void split_wo_kernel(const float* __restrict__ wo) {
    __shared__ float t[64][65];
    const int k0 = blockIdx.x * 64;
    const int n0 = blockIdx.y * 64;
    const int tid = threadIdx.x;
    #pragma unroll
    for (int q = 0; q < 4; q++) {
        int idx = q * 256 + tid;
        int r = idx >> 4, c = (idx & 15) * 4;
        float4 v = *(const float4*)(wo + (size_t)(k0 + r) * EE + n0 + c);
        t[r][c] = v.x; t[r][c+1] = v.y; t[r][c+2] = v.z; t[r][c+3] = v.w;
    }
    __syncthreads();
    #pragma unroll
    for (int q = 0; q < 4; q++) {
        int idx = q * 256 + tid;
        int d = idx >> 4, e = (idx & 15) * 4;
        __nv_bfloat16 h4[4], l4[4];
        #pragma unroll
        for (int j = 0; j < 4; j++) split1(t[e + j][d], h4[j], l4[j]);
        size_t o = (size_t)(n0 + d) * EE + k0 + e;
        *(uint32_t*)(g_wohi + o)     = pck(h4[0], h4[1]);
        *(uint32_t*)(g_wohi + o + 2) = pck(h4[2], h4[3]);
        *(uint32_t*)(g_wolo + o)     = pck(l4[0], l4[1]);
        *(uint32_t*)(g_wolo + o + 2) = pck(l4[2], l4[3]);
    }
}

// ---------------------------------------------------------------------------
// GEMM core 128x128: C[128x128] += A[128x1024] * B[128x1024]^T, split-bf16
// 3-pass. 256 threads (8 warps, 4m x 2n), warp tile 32x64, BK=32 elems,
// 3-stage cp.async. Stage (32KB): Ahi 8K | Alo 8K | Bhi 8K | Blo 8K,
// each matrix 128 rows x 64 bytes, SW64.
// ---------------------------------------------------------------------------
#define STG2 32768
#define GEMM_SMEM (3 * STG2)

__device__ __forceinline__ void load_stage2(
    uint32_t sb, int s, int kt, int tid,
    const char* agh, const char* agl, const char* bgh, const char* bgl)
{
    const uint32_t st = sb + (uint32_t)s * STG2;
    const int c16 = (tid & 3) * 16;
    const size_t gk = (size_t)kt * 64 + (size_t)c16;
    #pragma unroll
    for (int p = 0; p < 2; ++p) {
        int row = p * 64 + (tid >> 2);
        uint32_t so = SWZ64((uint32_t)(row * 64 + c16));
        size_t g = (size_t)row * 2048 + gk;
        cp16(st + so,         agh + g);
        cp16(st +  8192 + so, agl + g);
        cp16(st + 16384 + so, bgh + g);
        cp16(st + 24576 + so, bgl + g);
    }
}

__device__ __forceinline__ void gemm_core_128x128(
    uint32_t sb,
    const char* agh, const char* agl, const char* bgh, const char* bgl,
    float acc[2][8][4])
{
    const int tid = threadIdx.x;
    const int warp = tid >> 5, lane = tid & 31;
    const int wm = (warp & 3) * 32;
    const int wn = (warp >> 2) * 64;

    uint32_t offA[2][2], offB[4][2];
    {
        const int rbA = (lane & 7) + ((lane >> 3) & 1) * 8;
        const int cA  = (lane >> 4) & 1;
        const int rbB = (lane & 7) + ((lane >> 4) & 1) * 8;
        const int cB  = (lane >> 3) & 1;
        #pragma unroll
        for (int s = 0; s < 2; ++s) {
            #pragma unroll
            for (int f = 0; f < 2; ++f)
                offA[f][s] = SWZ64((uint32_t)((wm + f*16 + rbA) * 64 + (s*2 + cA) * 16));
            #pragma unroll
            for (int g = 0; g < 4; ++g)
                offB[g][s] = SWZ64((uint32_t)((wn + g*16 + rbB) * 64 + (s*2 + cB) * 16));
        }
    }
    #pragma unroll
    for (int f = 0; f < 2; f++)
        #pragma unroll
        for (int nf = 0; nf < 8; nf++)
            #pragma unroll
            for (int i = 0; i < 4; i++) acc[f][nf][i] = 0.f;

    load_stage2(sb, 0, 0, tid, agh, agl, bgh, bgl); CP_COMMIT();
    load_stage2(sb, 1, 1, tid, agh, agl, bgh, bgl); CP_COMMIT();

    for (int kt = 0; kt < 32; ++kt) {
        CP_WAIT1();
        __syncthreads();
        if (kt + 2 < 32)
            load_stage2(sb, (kt + 2) % 3, kt + 2, tid, agh, agl, bgh, bgl);
        CP_COMMIT();

        const uint32_t base = sb + (uint32_t)(kt % 3) * STG2;
        #pragma unroll
        for (int s16 = 0; s16 < 2; ++s16) {
            uint32_t ah0[4], ah1[4], al0[4], al1[4];
            ldmx4(ah0, base + offA[0][s16]);
            ldmx4(ah1, base + offA[1][s16]);
            ldmx4(al0, base + 8192 + offA[0][s16]);
            ldmx4(al1, base + 8192 + offA[1][s16]);
            uint32_t bh[4][4], bl[4][4];
            #pragma unroll
            for (int g = 0; g < 4; ++g) {
                ldmx4(bh[g], base + 16384 + offB[g][s16]);
                ldmx4(bl[g], base + 24576 + offB[g][s16]);
            }
            uint32_t* ah[2] = {ah0, ah1};
            uint32_t* al[2] = {al0, al1};
            #pragma unroll
            for (int f = 0; f < 2; ++f) {
                #pragma unroll
                for (int nf = 0; nf < 8; ++nf) {
                    int g = nf >> 1, i = (nf & 1) * 2;
                    mma16816(acc[f][nf], ah[f], bh[g][i], bh[g][i + 1]);
                    mma16816(acc[f][nf], ah[f], bl[g][i], bl[g][i + 1]);
                    mma16816(acc[f][nf], al[f], bh[g][i], bh[g][i + 1]);
                }
            }
        }
    }
}

// ---------------------------------------------------------------------------
// QKV projection, merged single GEMM: C[8192 x 3072] = X * W_all^T
// grid (64 mtiles, 24 ntiles). Each warp's 64 cols live in ONE head z.
// ---------------------------------------------------------------------------
__global__ __launch_bounds__(256, 2) void qkv_mma_kernel(
    const float* __restrict__ bq, const float* __restrict__ bk,
    const float* __restrict__ bv)
{
    extern __shared__ char smem[];
    const uint32_t sb = smem_to_u32(smem);
    const int tid = threadIdx.x;
    const int m0 = blockIdx.x * 128;
    const int n0 = blockIdx.y * 128;

    const char* agh = (const char*)(g_xhi + (size_t)m0 * EE);
    const char* agl = (const char*)(g_xlo + (size_t)m0 * EE);
    const char* bgh = (const char*)(g_whi + (size_t)n0 * EE);
    const char* bgl = (const char*)(g_wlo + (size_t)n0 * EE);

    float acc[2][8][4];
    gemm_core_128x128(sb, agh, agl, bgh, bgl, acc);

    const int warp = tid >> 5, lane = tid & 31;
    const int wm = (warp & 3) * 32, wn = (warp >> 2) * 64;
    const int r = lane >> 2, cp2 = (lane & 3) * 2;

    // whole warp tile is in one z (64-aligned, 64 wide)
    const int z = (n0 + wn) >> 6;
    const int which = z >> 4, h = z & 15;
    const float* bp = (which == 0 ? bq : which == 1 ? bk : bv) + h * DD;
    __nv_bfloat16* ohp = (which == 0 ? g_qhi : which == 1 ? g_khi : g_vhi);
    __nv_bfloat16* olp = (which == 0 ? g_qlo : which == 1 ? g_klo : g_vlo);

    #pragma unroll
    for (int f = 0; f < 2; ++f) {
        #pragma unroll
        for (int half = 0; half < 2; ++half) {
            int m = m0 + wm + f * 16 + r + half * 8;
            int b = m >> 11, s = m & 2047;
            size_t rowoff = (((size_t)b * HH + h) * SS + s) * DD;
            #pragma unroll
            for (int nf = 0; nf < 8; ++nf) {
                int d = nf * 8 + cp2;
                float v0 = acc[f][nf][half * 2 + 0] + bp[d];
                float v1 = acc[f][nf][half * 2 + 1] + bp[d + 1];
                uint32_t hi, lo;
                split_pair(v0, v1, hi, lo);
                *(uint32_t*)(ohp + rowoff + d) = hi;
                *(uint32_t*)(olp + rowoff + d) = lo;
            }
        }
    }
}

// ---------------------------------------------------------------------------
// Output projection: y[8192x1024] = O_cat * wo + bo, grid (64, 8)
// ---------------------------------------------------------------------------
__global__ __launch_bounds__(256, 2) void oproj_mma_kernel(
    const float* __restrict__ bo, float* __restrict__ y)
{
    extern __shared__ char smem[];
    const uint32_t sb = smem_to_u32(smem);
    const int tid = threadIdx.x;
    const int m0 = blockIdx.x * 128;
    const int n0 = blockIdx.y * 128;

    const char* agh = (const char*)(g_ohi + (size_t)m0 * EE);
    const char* agl = (const char*)(g_olo + (size_t)m0 * EE);
    const char* bgh = (const char*)(g_wohi + (size_t)n0 * EE);
    const char* bgl = (const char*)(g_wolo + (size_t)n0 * EE);

    float acc[2][8][4];
    gemm_core_128x128(sb, agh, agl, bgh, bgl, acc);

    const int warp = tid >> 5, lane = tid & 31;
    const int wm = (warp & 3) * 32, wn = (warp >> 2) * 64;
    const int r = lane >> 2, cp2 = (lane & 3) * 2;
    #pragma unroll
    for (int f = 0; f < 2; ++f) {
        #pragma unroll
        for (int half = 0; half < 2; ++half) {
            int m = m0 + wm + f * 16 + r + half * 8;
            float* row = y + (size_t)m * EE + n0 + wn;
            #pragma unroll
            for (int nf = 0; nf < 8; ++nf) {
                int col = nf * 8 + cp2;
                float2 v;
                v.x = acc[f][nf][half * 2 + 0] + bo[n0 + wn + col];
                v.y = acc[f][nf][half * 2 + 1] + bo[n0 + wn + col + 1];
                *(float2*)(row + col) = v;
            }
        }
    }
}

// ---------------------------------------------------------------------------
// Flash attention on mma.sync, split-bf16, causal. (unchanged from R4)
// Block: 256 threads (8 warps), Br=128 (16 rows/warp), Bc=64, D=64.
// smem: 2 stages x 32KB (Khi 8K | Klo 8K | Vhi 8K | Vlo 8K), 128B rows, SW128.
// ---------------------------------------------------------------------------
#define AT_STAGE 32768
#define AT_SMEM  (2 * AT_STAGE)

__device__ __forceinline__ void attn_load_kv(
    uint32_t sb, int stage, int ct, int tid,
    const char* khg, const char* klg, const char* vhg, const char* vlg)
{
    const uint32_t st = sb + (uint32_t)stage * AT_STAGE;
    const int col0 = ct * 64;
    #pragma unroll
    for (int p = 0; p < 2; ++p) {
        int idx = p * 256 + tid;
        int r = idx >> 3, c16 = (idx & 7) * 16;
        uint32_t so = SWZ128((uint32_t)(r * 128 + c16));
        size_t g = (size_t)(col0 + r) * 128 + c16;
        cp16(st + so,         khg + g);
        cp16(st +  8192 + so, klg + g);
        cp16(st + 16384 + so, vhg + g);
        cp16(st + 24576 + so, vlg + g);
    }
}

__global__ __launch_bounds__(256, 1) void attn_mma_kernel()
{
    extern __shared__ char smem[];
    const uint32_t sb = smem_to_u32(smem);
    const int tid = threadIdx.x;
    const int warp = tid >> 5, lane = tid & 31;
    const int rt = blockIdx.x;            // 0..15 (128-row tiles)
    const int bh = blockIdx.y;            // 0..63
    const int row0 = rt * 128;
    const int wm = warp * 16;

    const char* qhg = (const char*)(g_qhi + (size_t)bh * SS * DD);
    const char* qlg = (const char*)(g_qlo + (size_t)bh * SS * DD);
    const char* khg = (const char*)(g_khi + (size_t)bh * SS * DD);
    const char* klg = (const char*)(g_klo + (size_t)bh * SS * DD);
    const char* vhg = (const char*)(g_vhi + (size_t)bh * SS * DD);
    const char* vlg = (const char*)(g_vlo + (size_t)bh * SS * DD);

    // ---- load Q tile (hi at sb, lo at sb+16K), extract A-fragments ----
    #pragma unroll
    for (int p = 0; p < 4; ++p) {
        int idx = p * 256 + tid;
        int r = idx >> 3, c16 = (idx & 7) * 16;
        uint32_t so = SWZ128((uint32_t)(r * 128 + c16));
        size_t g = (size_t)(row0 + r) * 128 + c16;
        cp16(sb + so,         qhg + g);
        cp16(sb + 16384 + so, qlg + g);
    }
    CP_COMMIT();
    CP_WAIT0();
    __syncthreads();

    const int rbA = (lane & 7) + ((lane >> 3) & 1) * 8;
    const int cA  = (lane >> 4) & 1;
    uint32_t qfh[4][4], qfl[4][4];
    #pragma unroll
    for (int c = 0; c < 4; ++c) {
        uint32_t off = SWZ128((uint32_t)((wm + rbA) * 128 + (c * 2 + cA) * 16));
        ldmx4(qfh[c], sb + off);
        ldmx4(qfl[c], sb + 16384 + off);
    }
    __syncthreads();   // done reading Q smem; stages may overwrite

    // ---- state ----
    float o[8][4];
    #pragma unroll
    for (int nf = 0; nf < 8; nf++)
        #pragma unroll
        for (int i = 0; i < 4; i++) o[nf][i] = 0.f;
    float mprev0 = -CUDART_INF_F, mprev1 = -CUDART_INF_F;
    float lsum0 = 0.f, lsum1 = 0.f;

    const float sc = 0.125f * 1.4426950408889634f;   // 1/sqrt(D) * log2(e)
    const int nct = 2 * rt + 2;

    const int rbB = (lane & 7) + ((lane >> 4) & 1) * 8;
    const int cB  = (lane >> 3) & 1;
    const int lr  = lane >> 2;
    const int lc2 = (lane & 3) * 2;
    const int r0g = row0 + wm + lr;

    attn_load_kv(sb, 0, 0, tid, khg, klg, vhg, vlg); CP_COMMIT();
    if (nct > 1) attn_load_kv(sb, 1, 1, tid, khg, klg, vhg, vlg);
    CP_COMMIT();

    for (int ct = 0; ct < nct; ++ct) {
        CP_WAIT1();
        __syncthreads();
        const uint32_t base = sb + (uint32_t)(ct & 1) * AT_STAGE;

        // ---- S = Q K^T (3-pass split) ----
        float s[8][4];
        #pragma unroll
        for (int nf = 0; nf < 8; nf++)
            #pragma unroll
            for (int i = 0; i < 4; i++) s[nf][i] = 0.f;

        #pragma unroll
        for (int c = 0; c < 4; ++c) {
            uint32_t kh[4][4], kl[4][4];
            #pragma unroll
            for (int g = 0; g < 4; ++g) {
                uint32_t off = SWZ128((uint32_t)((g * 16 + rbB) * 128 + (c * 2 + cB) * 16));
                ldmx4(kh[g], base + off);
                ldmx4(kl[g], base + 8192 + off);
            }
            #pragma unroll
            for (int nf = 0; nf < 8; ++nf) {
                int g = nf >> 1, i = (nf & 1) * 2;
                mma16816(s[nf], qfh[c], kh[g][i], kh[g][i + 1]);
                mma16816(s[nf], qfh[c], kl[g][i], kl[g][i + 1]);
                mma16816(s[nf], qfl[c], kh[g][i], kh[g][i + 1]);
            }
        }

        // ---- causal mask ----
        if (ct * 64 + 63 > row0 + wm) {
            #pragma unroll
            for (int nf = 0; nf < 8; ++nf) {
                int cg = ct * 64 + nf * 8 + lc2;
                if (cg     > r0g)     s[nf][0] = -CUDART_INF_F;
                if (cg + 1 > r0g)     s[nf][1] = -CUDART_INF_F;
                if (cg     > r0g + 8) s[nf][2] = -CUDART_INF_F;
                if (cg + 1 > r0g + 8) s[nf][3] = -CUDART_INF_F;
            }
        }

        // ---- online softmax ----
        float mt0 = -CUDART_INF_F, mt1 = -CUDART_INF_F;
        #pragma unroll
        for (int nf = 0; nf < 8; ++nf) {
            mt0 = fmaxf(mt0, fmaxf(s[nf][0], s[nf][1]));
            mt1 = fmaxf(mt1, fmaxf(s[nf][2], s[nf][3]));
        }
        mt0 = fmaxf(mt0, __shfl_xor_sync(0xffffffffu, mt0, 1));
        mt0 = fmaxf(mt0, __shfl_xor_sync(0xffffffffu, mt0, 2));
        mt1 = fmaxf(mt1, __shfl_xor_sync(0xffffffffu, mt1, 1));
        mt1 = fmaxf(mt1, __shfl_xor_sync(0xffffffffu, mt1, 2));

        float mn0 = fmaxf(mprev0, mt0);
        float mn1 = fmaxf(mprev1, mt1);
        float a0 = exp2f((mprev0 - mn0) * sc);
        float a1 = exp2f((mprev1 - mn1) * sc);
        lsum0 *= a0; lsum1 *= a1;
        #pragma unroll
        for (int nf = 0; nf < 8; ++nf) {
            s[nf][0] = exp2f((s[nf][0] - mn0) * sc);
            s[nf][1] = exp2f((s[nf][1] - mn0) * sc);
            s[nf][2] = exp2f((s[nf][2] - mn1) * sc);
            s[nf][3] = exp2f((s[nf][3] - mn1) * sc);
            lsum0 += s[nf][0] + s[nf][1];
            lsum1 += s[nf][2] + s[nf][3];
            o[nf][0] *= a0; o[nf][1] *= a0;
            o[nf][2] *= a1; o[nf][3] *= a1;
        }
        mprev0 = mn0; mprev1 = mn1;

        // ---- pack P into split-bf16 A-fragments ----
        uint32_t pfh[4][4], pfl[4][4];
        #pragma unroll
        for (int kk = 0; kk < 4; ++kk) {
            split_pair(s[2*kk][0],   s[2*kk][1],   pfh[kk][0], pfl[kk][0]);
            split_pair(s[2*kk][2],   s[2*kk][3],   pfh[kk][1], pfl[kk][1]);
            split_pair(s[2*kk+1][0], s[2*kk+1][1], pfh[kk][2], pfl[kk][2]);
            split_pair(s[2*kk+1][2], s[2*kk+1][3], pfh[kk][3], pfl[kk][3]);
        }

        // ---- O += P V (3-pass split, ldmatrix.trans for V) ----
        #pragma unroll
        for (int kk = 0; kk < 4; ++kk) {
            #pragma unroll
            for (int dd = 0; dd < 4; ++dd) {
                uint32_t vh[4], vl[4];
                uint32_t off = SWZ128((uint32_t)((kk * 16 + rbA) * 128 + (dd * 2 + cA) * 16));
                ldmx4t(vh, base + 16384 + off);
                ldmx4t(vl, base + 24576 + off);
                #pragma unroll
                for (int j = 0; j < 2; ++j) {
                    int nf = dd * 2 + j;
                    uint32_t b0h = vh[j * 2], b1h = vh[j * 2 + 1];
                    uint32_t b0l = vl[j * 2], b1l = vl[j * 2 + 1];
                    mma16816(o[nf], pfh[kk], b0h, b1h);
                    mma16816(o[nf], pfh[kk], b0l, b1l);
                    mma16816(o[nf], pfl[kk], b0h, b1h);
                }
            }
        }

        __syncthreads();
        if (ct + 2 < nct)
            attn_load_kv(sb, ct & 1, ct + 2, tid, khg, klg, vhg, vlg);
        CP_COMMIT();
    }

    // ---- finalize ----
    lsum0 += __shfl_xor_sync(0xffffffffu, lsum0, 1);
    lsum0 += __shfl_xor_sync(0xffffffffu, lsum0, 2);
    lsum1 += __shfl_xor_sync(0xffffffffu, lsum1, 1);
    lsum1 += __shfl_xor_sync(0xffffffffu, lsum1, 2);
    float inv0 = 1.f / lsum0;
    float inv1 = 1.f / lsum1;

    const int b = bh >> 4, h = bh & 15;
    const size_t m0G = (size_t)b * SS + (size_t)(row0 + wm + lr);
    __nv_bfloat16* oh0 = g_ohi + m0G * EE + h * DD;
    __nv_bfloat16* ol0 = g_olo + m0G * EE + h * DD;
    __nv_bfloat16* oh1 = oh0 + (size_t)8 * EE;
    __nv_bfloat16* ol1 = ol0 + (size_t)8 * EE;
    #pragma unroll
    for (int nf = 0; nf < 8; ++nf) {
        int col = nf * 8 + lc2;
        uint32_t hi, lo;
        split_pair(o[nf][0] * inv0, o[nf][1] * inv0, hi, lo);
        *(uint32_t*)(oh0 + col) = hi;
        *(uint32_t*)(ol0 + col) = lo;
        split_pair(o[nf][2] * inv1, o[nf][3] * inv1, hi, lo);
        *(uint32_t*)(oh1 + col) = hi;
        *(uint32_t*)(ol1 + col) = lo;
    }
}

// ---------------------------------------------------------------------------
extern "C" void kernel_launch(void* const* d_in, const int* in_sizes, int n_in,
                              void* d_out, int out_size)
{
    const float* x  = (const float*)d_in[0];
    const float* wq = (const float*)d_in[1];
    const float* bq = (const float*)d_in[2];
    const float* wk = (const float*)d_in[3];
    const float* bk = (const float*)d_in[4];
    const float* wv = (const float*)d_in[5];
    const float* bv = (const float*)d_in[6];
    const float* wo = (const float*)d_in[7];
    const float* bo = (const float*)d_in[8];
    float* y = (float*)d_out;

    (void)in_sizes; (void)n_in; (void)out_size;

    cudaFuncSetAttribute(qkv_mma_kernel, cudaFuncAttributeMaxDynamicSharedMemorySize,
                         GEMM_SMEM);
    cudaFuncSetAttribute(oproj_mma_kernel, cudaFuncAttributeMaxDynamicSharedMemorySize,
                         GEMM_SMEM);
    cudaFuncSetAttribute(attn_mma_kernel, cudaFuncAttributeMaxDynamicSharedMemorySize,
                         AT_SMEM);

    // 1) Split/transpose prep (bf16 hi/lo)
    split_x_kernel<<<(MM * EE) / (256 * 8), 256>>>(x);
    split_w_kernel<<<dim3(16, 48), 256>>>(wq, wk, wv);
    split_wo_kernel<<<dim3(16, 16), 256>>>(wo);

    // 2) QKV projection: single merged GEMM [8192 x 3072]
    qkv_mma_kernel<<<dim3(64, 24), 256, GEMM_SMEM>>>(bq, bk, bv);

    // 3) Flash attention (mma.sync, split bf16)
    attn_mma_kernel<<<dim3(16, 64), 256, AT_SMEM>>>();

    // 4) Output projection [8192 x 1024]
    oproj_mma_kernel<<<dim3(64, 8), 256, GEMM_SMEM>>>(bo, y);
}

// round 6
// speedup vs baseline: 3.4529x; 1.0255x over previous
#include <cuda_runtime.h>
#include <cuda_bf16.h>
#include <math_constants.h>
#include <cstdint>

#define BB 4
#define SS 2048
#define EE 1024
#define HH 16
#define DD 64
#define MM (BB*SS)   // 8192

// ---------------------------------------------------------------------------
// Device-global scratch (allocation-free rule)
// ---------------------------------------------------------------------------
__device__ __align__(16) __nv_bfloat16 g_xhi[MM*EE];
__device__ __align__(16) __nv_bfloat16 g_xlo[MM*EE];
__device__ __align__(16) __nv_bfloat16 g_whi[48*DD*EE];   // [z*64+d][e] == W_all^T
__device__ __align__(16) __nv_bfloat16 g_wlo[48*DD*EE];
__device__ __align__(16) __nv_bfloat16 g_wohi[EE*EE];     // [n][k] (wo transposed)
__device__ __align__(16) __nv_bfloat16 g_wolo[EE*EE];

// Q/K/V in split bf16, layout [bh][s][d] (bh = b*16+h), 128B rows
__device__ __align__(16) __nv_bfloat16 g_qhi[BB*HH*SS*DD];
__device__ __align__(16) __nv_bfloat16 g_qlo[BB*HH*SS*DD];
__device__ __align__(16) __nv_bfloat16 g_khi[BB*HH*SS*DD];
__device__ __align__(16) __nv_bfloat16 g_klo[BB*HH*SS*DD];
__device__ __align__(16) __nv_bfloat16 g_vhi[BB*HH*SS*DD];
__device__ __align__(16) __nv_bfloat16 g_vlo[BB*HH*SS*DD];

// Attention output, head-concat layout [m][h*64+d], split bf16
__device__ __align__(16) __nv_bfloat16 g_ohi[MM*EE];
__device__ __align__(16) __nv_bfloat16 g_olo[MM*EE];

// ---------------------------------------------------------------------------
// mma.sync / ldmatrix / cp.async helpers
// ---------------------------------------------------------------------------
__device__ __forceinline__ uint32_t smem_to_u32(const void* p) {
    uint32_t a;
    asm("{ .reg .u64 t; cvta.to.shared.u64 t, %1; cvt.u32.u64 %0, t; }"
        : "=r"(a) : "l"(p));
    return a;
}
__device__ __forceinline__ void cp16(uint32_t saddr, const void* gaddr) {
    asm volatile("cp.async.cg.shared.global [%0], [%1], 16;"
                 :: "r"(saddr), "l"(gaddr));
}
#define CP_COMMIT() asm volatile("cp.async.commit_group;" ::: "memory")
#define CP_WAIT1()  asm volatile("cp.async.wait_group 1;" ::: "memory")
#define CP_WAIT0()  asm volatile("cp.async.wait_group 0;" ::: "memory")

__device__ __forceinline__ void ldmx4(uint32_t* r, uint32_t addr) {
    asm volatile("ldmatrix.sync.aligned.m8n8.x4.shared.b16 {%0,%1,%2,%3}, [%4];"
        : "=r"(r[0]), "=r"(r[1]), "=r"(r[2]), "=r"(r[3]) : "r"(addr));
}
__device__ __forceinline__ void ldmx4t(uint32_t* r, uint32_t addr) {
    asm volatile("ldmatrix.sync.aligned.m8n8.x4.trans.shared.b16 {%0,%1,%2,%3}, [%4];"
        : "=r"(r[0]), "=r"(r[1]), "=r"(r[2]), "=r"(r[3]) : "r"(addr));
}
__device__ __forceinline__ void mma16816(float* c, const uint32_t* a,
                                         uint32_t b0, uint32_t b1) {
    asm volatile("mma.sync.aligned.m16n8k16.row.col.f32.bf16.bf16.f32 "
        "{%0,%1,%2,%3}, {%4,%5,%6,%7}, {%8,%9}, {%0,%1,%2,%3};"
        : "+f"(c[0]), "+f"(c[1]), "+f"(c[2]), "+f"(c[3])
        : "r"(a[0]), "r"(a[1]), "r"(a[2]), "r"(a[3]), "r"(b0), "r"(b1));
}

#define SWZ64(off)  ((off) ^ (((off) >> 3) & 0x30))   // 64B rows
#define SWZ128(off) ((off) ^ (((off) >> 3) & 0x70))   // 128B rows

// ---------------------------------------------------------------------------
// Split helpers
// ---------------------------------------------------------------------------
__device__ __forceinline__ void split1(float v, __nv_bfloat16& h, __nv_bfloat16& l) {
    h = __float2bfloat16_rn(v);
    l = __float2bfloat16_rn(v - __bfloat162float(h));
}
__device__ __forceinline__ uint32_t pck(__nv_bfloat16 a, __nv_bfloat16 b) {
    return ((uint32_t)__bfloat16_as_ushort(b) << 16) | (uint32_t)__bfloat16_as_ushort(a);
}
__device__ __forceinline__ void split_pair(float v0, float v1,
                                           uint32_t& hi, uint32_t& lo) {
    __nv_bfloat16 h0, l0, h1, l1;
    split1(v0, h0, l0); split1(v1, h1, l1);
    hi = pck(h0, h1); lo = pck(l0, l1);
}

// x [8192x1024] fp32 -> hi/lo bf16
__global__ __launch_bounds__(256) void split_x_kernel(const float* __restrict__ x) {
    size_t i = ((size_t)blockIdx.x * 256 + threadIdx.x) * 8;
    float4 v0 = *(const float4*)(x + i);
    float4 v1 = *(const float4*)(x + i + 4);
    float vv[8] = {v0.x, v0.y, v0.z, v0.w, v1.x, v1.y, v1.z, v1.w};
    __nv_bfloat16 h[8], l[8];
    #pragma unroll
    for (int j = 0; j < 8; j++) split1(vv[j], h[j], l[j]);
    uint4 uh = {pck(h[0],h[1]), pck(h[2],h[3]), pck(h[4],h[5]), pck(h[6],h[7])};
    uint4 ul = {pck(l[0],l[1]), pck(l[2],l[3]), pck(l[4],l[5]), pck(l[6],l[7])};
    *(uint4*)(g_xhi + i) = uh;
    *(uint4*)(g_xlo + i) = ul;
}

// wq/wk/wv [16][1024][64] -> g_w{hi,lo} [z][d][e] (transposed, split)
__global__ __launch_bounds__(256) void split_w_kernel(
    const float* __restrict__ wq, const float* __restrict__ wk, const float* __restrict__ wv) {
    __shared__ float t[64][65];
    const int z = blockIdx.y;
    const int which = z >> 4, h = z & 15;
    const float* W = (which == 0 ? wq : which == 1 ? wk : wv) + (size_t)h * EE * DD;
    const int e0 = blockIdx.x * 64;
    const int tid = threadIdx.x;
    #pragma unroll
    for (int q = 0; q < 4; q++) {
        int idx = q * 256 + tid;
        int r = idx >> 4, c = (idx & 15) * 4;
        float4 v = *(const float4*)(W + (size_t)(e0 + r) * DD + c);
        t[r][c] = v.x; t[r][c+1] = v.y; t[r][c+2] = v.z; t[r][c+3] = v.w;
    }
    __syncthreads();
    #pragma unroll
    for (int q = 0; q < 4; q++) {
        int idx = q * 256 + tid;
        int d = idx >> 4, e = (idx & 15) * 4;
        __nv_bfloat16 h4[4], l4[4];
        #pragma unroll
        for (int j = 0; j < 4; j++) split1(t[e + j][d], h4[j], l4[j]);
        size_t o = ((size_t)z * DD + d) * EE + e0 + e;
        *(uint32_t*)(g_whi + o)     = pck(h4[0], h4[1]);
        *(uint32_t*)(g_whi + o + 2) = pck(h4[2], h4[3]);
        *(uint32_t*)(g_wlo + o)     = pck(l4[0], l4[1]);
        *(uint32_t*)(g_wlo + o + 2) = pck(l4[2], l4[3]);
    }
}

// wo [1024 k][1024 n] -> g_wo{hi,lo} [n][k] (transposed, split)
__global__ __launch_bounds__(256) void split_wo_kernel(const float* __restrict__ wo) {
    __shared__ float t[64][65];
    const int k0 = blockIdx.x * 64;
    const int n0 = blockIdx.y * 64;
    const int tid = threadIdx.x;
    #pragma unroll
    for (int q = 0; q < 4; q++) {
        int idx = q * 256 + tid;
        int r = idx >> 4, c = (idx & 15) * 4;
        float4 v = *(const float4*)(wo + (size_t)(k0 + r) * EE + n0 + c);
        t[r][c] = v.x; t[r][c+1] = v.y; t[r][c+2] = v.z; t[r][c+3] = v.w;
    }
    __syncthreads();
    #pragma unroll
    for (int q = 0; q < 4; q++) {
        int idx = q * 256 + tid;
        int d = idx >> 4, e = (idx & 15) * 4;
        __nv_bfloat16 h4[4], l4[4];
        #pragma unroll
        for (int j = 0; j < 4; j++) split1(t[e + j][d], h4[j], l4[j]);
        size_t o = (size_t)(n0 + d) * EE + k0 + e;
        *(uint32_t*)(g_wohi + o)     = pck(h4[0], h4[1]);
        *(uint32_t*)(g_wohi + o + 2) = pck(h4[2], h4[3]);
        *(uint32_t*)(g_wolo + o)     = pck(l4[0], l4[1]);
        *(uint32_t*)(g_wolo + o + 2) = pck(l4[2], l4[3]);
    }
}

// ---------------------------------------------------------------------------
// GEMM core 128x64 (R4-proven): C += A[128x1024] * B[64x1024]^T, split-bf16
// 3-pass. 256 threads (8 warps, 4m x 2n), warp tile 32x32, BK=32 elems,
// 3-stage cp.async. Stage (24KB): Ahi 8K | Alo 8K | Bhi 4K | Blo 4K.
// ---------------------------------------------------------------------------
#define STAGE_BYTES 24576
#define GEMM_SMEM   (3 * STAGE_BYTES)

__device__ __forceinline__ void load_stage(
    uint32_t sb, int s, int kt, int tid,
    const char* agh, const char* agl, const char* bgh, const char* bgl)
{
    const uint32_t sA = sb + (uint32_t)s * STAGE_BYTES;
    const size_t gk = (size_t)kt * 64 + (size_t)((tid & 3) * 16);
    const int c16 = (tid & 3) * 16;
    #pragma unroll
    for (int i = 0; i < 2; ++i) {
        int row = i * 64 + (tid >> 2);
        uint32_t so = SWZ64((uint32_t)(row * 64 + c16));
        cp16(sA + so,        agh + (size_t)row * 2048 + gk);
        cp16(sA + 8192 + so, agl + (size_t)row * 2048 + gk);
    }
    {
        int row = tid >> 2;
        uint32_t so = SWZ64((uint32_t)(row * 64 + c16));
        cp16(sA + 16384 + so, bgh + (size_t)row * 2048 + gk);
        cp16(sA + 20480 + so, bgl + (size_t)row * 2048 + gk);
    }
}

__device__ __forceinline__ void gemm_core_128x64(
    uint32_t sb,
    const char* agh, const char* agl, const char* bgh, const char* bgl,
    float acc[2][4][4])
{
    const int tid = threadIdx.x;
    const int warp = tid >> 5, lane = tid & 31;
    const int wm = (warp & 3) * 32;
    const int wn = (warp >> 2) * 32;

    uint32_t offA[2][2], offB[2][2];
    {
        const int rbA = (lane & 7) + ((lane >> 3) & 1) * 8;
        const int cA  = (lane >> 4) & 1;
        const int rbB = (lane & 7) + ((lane >> 4) & 1) * 8;
        const int cB  = (lane >> 3) & 1;
        #pragma unroll
        for (int f = 0; f < 2; ++f)
            #pragma unroll
            for (int s = 0; s < 2; ++s) {
                offA[f][s] = SWZ64((uint32_t)((wm + f*16 + rbA) * 64 + (s*2 + cA) * 16));
                offB[f][s] = SWZ64((uint32_t)((wn + f*16 + rbB) * 64 + (s*2 + cB) * 16));
            }
    }
    #pragma unroll
    for (int f = 0; f < 2; f++)
        #pragma unroll
        for (int nf = 0; nf < 4; nf++)
            #pragma unroll
            for (int i = 0; i < 4; i++) acc[f][nf][i] = 0.f;

    load_stage(sb, 0, 0, tid, agh, agl, bgh, bgl); CP_COMMIT();
    load_stage(sb, 1, 1, tid, agh, agl, bgh, bgl); CP_COMMIT();

    for (int kt = 0; kt < 32; ++kt) {
        CP_WAIT1();
        __syncthreads();
        if (kt + 2 < 32)
            load_stage(sb, (kt + 2) % 3, kt + 2, tid, agh, agl, bgh, bgl);
        CP_COMMIT();

        const uint32_t base = sb + (uint32_t)(kt % 3) * STAGE_BYTES;
        #pragma unroll
        for (int s16 = 0; s16 < 2; ++s16) {
            uint32_t ah0[4], ah1[4], al0[4], al1[4];
            uint32_t bh0[4], bh1[4], bl0[4], bl1[4];
            ldmx4(ah0, base + offA[0][s16]);
            ldmx4(ah1, base + offA[1][s16]);
            ldmx4(al0, base + 8192 + offA[0][s16]);
            ldmx4(al1, base + 8192 + offA[1][s16]);
            ldmx4(bh0, base + 16384 + offB[0][s16]);
            ldmx4(bh1, base + 16384 + offB[1][s16]);
            ldmx4(bl0, base + 20480 + offB[0][s16]);
            ldmx4(bl1, base + 20480 + offB[1][s16]);
            uint32_t* ah[2] = {ah0, ah1};
            uint32_t* al[2] = {al0, al1};
            uint32_t* bh[2] = {bh0, bh1};
            uint32_t* bl[2] = {bl0, bl1};
            #pragma unroll
            for (int f = 0; f < 2; ++f) {
                #pragma unroll
                for (int nf = 0; nf < 4; ++nf) {
                    uint32_t b0h = bh[nf >> 1][(nf & 1) * 2];
                    uint32_t b1h = bh[nf >> 1][(nf & 1) * 2 + 1];
                    uint32_t b0l = bl[nf >> 1][(nf & 1) * 2];
                    uint32_t b1l = bl[nf >> 1][(nf & 1) * 2 + 1];
                    mma16816(acc[f][nf], ah[f], b0h, b1h);
                    mma16816(acc[f][nf], ah[f], b0l, b1l);
                    mma16816(acc[f][nf], al[f], b0h, b1h);
                }
            }
        }
    }
}

// ---------------------------------------------------------------------------
// QKV projection, merged GEMM C[8192 x 3072] = X * W_all^T
// grid (64 mtiles, 48 ntiles of 64). Block's 64 cols = ONE head z = blockIdx.y.
// __launch_bounds__(256,3): cap regs at 80 so 3 CTAs co-reside per SM.
// ---------------------------------------------------------------------------
__global__ __launch_bounds__(256, 3) void qkv_mma_kernel(
    const float* __restrict__ bq, const float* __restrict__ bk,
    const float* __restrict__ bv)
{
    extern __shared__ char smem[];
    const uint32_t sb = smem_to_u32(smem);
    const int tid = threadIdx.x;
    const int m0 = blockIdx.x * 128;
    const int z = blockIdx.y;
    const int which = z >> 4, h = z & 15;

    const char* agh = (const char*)(g_xhi + (size_t)m0 * EE);
    const char* agl = (const char*)(g_xlo + (size_t)m0 * EE);
    const char* bgh = (const char*)(g_whi + (size_t)z * DD * EE);
    const char* bgl = (const char*)(g_wlo + (size_t)z * DD * EE);

    float acc[2][4][4];
    gemm_core_128x64(sb, agh, agl, bgh, bgl, acc);

    const float* bp = (which == 0 ? bq : which == 1 ? bk : bv) + h * DD;
    __nv_bfloat16* ohp = (which == 0 ? g_qhi : which == 1 ? g_khi : g_vhi);
    __nv_bfloat16* olp = (which == 0 ? g_qlo : which == 1 ? g_klo : g_vlo);

    const int warp = tid >> 5, lane = tid & 31;
    const int wm = (warp & 3) * 32, wn = (warp >> 2) * 32;
    const int r = lane >> 2, cp2 = (lane & 3) * 2;
    #pragma unroll
    for (int f = 0; f < 2; ++f) {
        #pragma unroll
        for (int half = 0; half < 2; ++half) {
            int m = m0 + wm + f * 16 + r + half * 8;
            int b = m >> 11, s = m & 2047;
            size_t rowoff = (((size_t)b * HH + h) * SS + s) * DD;
            #pragma unroll
            for (int nf = 0; nf < 4; ++nf) {
                int d = wn + nf * 8 + cp2;
                float v0 = acc[f][nf][half * 2 + 0] + bp[d];
                float v1 = acc[f][nf][half * 2 + 1] + bp[d + 1];
                uint32_t hi, lo;
                split_pair(v0, v1, hi, lo);
                *(uint32_t*)(ohp + rowoff + d) = hi;
                *(uint32_t*)(olp + rowoff + d) = lo;
            }
        }
    }
}

// ---------------------------------------------------------------------------
// Output projection: y[8192x1024] = O_cat * wo + bo, grid (64, 16)
// ---------------------------------------------------------------------------
__global__ __launch_bounds__(256, 3) void oproj_mma_kernel(
    const float* __restrict__ bo, float* __restrict__ y)
{
    extern __shared__ char smem[];
    const uint32_t sb = smem_to_u32(smem);
    const int tid = threadIdx.x;
    const int m0 = blockIdx.x * 128;
    const int n0 = blockIdx.y * 64;

    const char* agh = (const char*)(g_ohi + (size_t)m0 * EE);
    const char* agl = (const char*)(g_olo + (size_t)m0 * EE);
    const char* bgh = (const char*)(g_wohi + (size_t)n0 * EE);
    const char* bgl = (const char*)(g_wolo + (size_t)n0 * EE);

    float acc[2][4][4];
    gemm_core_128x64(sb, agh, agl, bgh, bgl, acc);

    const int warp = tid >> 5, lane = tid & 31;
    const int wm = (warp & 3) * 32, wn = (warp >> 2) * 32;
    const int r = lane >> 2, cp2 = (lane & 3) * 2;
    #pragma unroll
    for (int f = 0; f < 2; ++f) {
        #pragma unroll
        for (int half = 0; half < 2; ++half) {
            int m = m0 + wm + f * 16 + r + half * 8;
            float* row = y + (size_t)m * EE + n0;
            #pragma unroll
            for (int nf = 0; nf < 4; ++nf) {
                int col = wn + nf * 8 + cp2;
                float2 v;
                v.x = acc[f][nf][half * 2 + 0] + bo[n0 + col];
                v.y = acc[f][nf][half * 2 + 1] + bo[n0 + col + 1];
                *(float2*)(row + col) = v;
            }
        }
    }
}

// ---------------------------------------------------------------------------
// Flash attention on mma.sync, split-bf16, causal. (unchanged from R4)
// ---------------------------------------------------------------------------
#define AT_STAGE 32768
#define AT_SMEM  (2 * AT_STAGE)

__device__ __forceinline__ void attn_load_kv(
    uint32_t sb, int stage, int ct, int tid,
    const char* khg, const char* klg, const char* vhg, const char* vlg)
{
    const uint32_t st = sb + (uint32_t)stage * AT_STAGE;
    const int col0 = ct * 64;
    #pragma unroll
    for (int p = 0; p < 2; ++p) {
        int idx = p * 256 + tid;
        int r = idx >> 3, c16 = (idx & 7) * 16;
        uint32_t so = SWZ128((uint32_t)(r * 128 + c16));
        size_t g = (size_t)(col0 + r) * 128 + c16;
        cp16(st + so,         khg + g);
        cp16(st +  8192 + so, klg + g);
        cp16(st + 16384 + so, vhg + g);
        cp16(st + 24576 + so, vlg + g);
    }
}

__global__ __launch_bounds__(256, 1) void attn_mma_kernel()
{
    extern __shared__ char smem[];
    const uint32_t sb = smem_to_u32(smem);
    const int tid = threadIdx.x;
    const int warp = tid >> 5, lane = tid & 31;
    const int rt = blockIdx.x;            // 0..15 (128-row tiles)
    const int bh = blockIdx.y;            // 0..63
    const int row0 = rt * 128;
    const int wm = warp * 16;

    const char* qhg = (const char*)(g_qhi + (size_t)bh * SS * DD);
    const char* qlg = (const char*)(g_qlo + (size_t)bh * SS * DD);
    const char* khg = (const char*)(g_khi + (size_t)bh * SS * DD);
    const char* klg = (const char*)(g_klo + (size_t)bh * SS * DD);
    const char* vhg = (const char*)(g_vhi + (size_t)bh * SS * DD);
    const char* vlg = (const char*)(g_vlo + (size_t)bh * SS * DD);

    // ---- load Q tile (hi at sb, lo at sb+16K), extract A-fragments ----
    #pragma unroll
    for (int p = 0; p < 4; ++p) {
        int idx = p * 256 + tid;
        int r = idx >> 3, c16 = (idx & 7) * 16;
        uint32_t so = SWZ128((uint32_t)(r * 128 + c16));
        size_t g = (size_t)(row0 + r) * 128 + c16;
        cp16(sb + so,         qhg + g);
        cp16(sb + 16384 + so, qlg + g);
    }
    CP_COMMIT();
    CP_WAIT0();
    __syncthreads();

    const int rbA = (lane & 7) + ((lane >> 3) & 1) * 8;
    const int cA  = (lane >> 4) & 1;
    uint32_t qfh[4][4], qfl[4][4];
    #pragma unroll
    for (int c = 0; c < 4; ++c) {
        uint32_t off = SWZ128((uint32_t)((wm + rbA) * 128 + (c * 2 + cA) * 16));
        ldmx4(qfh[c], sb + off);
        ldmx4(qfl[c], sb + 16384 + off);
    }
    __syncthreads();

    float o[8][4];
    #pragma unroll
    for (int nf = 0; nf < 8; nf++)
        #pragma unroll
        for (int i = 0; i < 4; i++) o[nf][i] = 0.f;
    float mprev0 = -CUDART_INF_F, mprev1 = -CUDART_INF_F;
    float lsum0 = 0.f, lsum1 = 0.f;

    const float sc = 0.125f * 1.4426950408889634f;
    const int nct = 2 * rt + 2;

    const int rbB = (lane & 7) + ((lane >> 4) & 1) * 8;
    const int cB  = (lane >> 3) & 1;
    const int lr  = lane >> 2;
    const int lc2 = (lane & 3) * 2;
    const int r0g = row0 + wm + lr;

    attn_load_kv(sb, 0, 0, tid, khg, klg, vhg, vlg); CP_COMMIT();
    if (nct > 1) attn_load_kv(sb, 1, 1, tid, khg, klg, vhg, vlg);
    CP_COMMIT();

    for (int ct = 0; ct < nct; ++ct) {
        CP_WAIT1();
        __syncthreads();
        const uint32_t base = sb + (uint32_t)(ct & 1) * AT_STAGE;

        float s[8][4];
        #pragma unroll
        for (int nf = 0; nf < 8; nf++)
            #pragma unroll
            for (int i = 0; i < 4; i++) s[nf][i] = 0.f;

        #pragma unroll
        for (int c = 0; c < 4; ++c) {
            uint32_t kh[4][4], kl[4][4];
            #pragma unroll
            for (int g = 0; g < 4; ++g) {
                uint32_t off = SWZ128((uint32_t)((g * 16 + rbB) * 128 + (c * 2 + cB) * 16));
                ldmx4(kh[g], base + off);
                ldmx4(kl[g], base + 8192 + off);
            }
            #pragma unroll
            for (int nf = 0; nf < 8; ++nf) {
                int g = nf >> 1, i = (nf & 1) * 2;
                mma16816(s[nf], qfh[c], kh[g][i], kh[g][i + 1]);
                mma16816(s[nf], qfh[c], kl[g][i], kl[g][i + 1]);
                mma16816(s[nf], qfl[c], kh[g][i], kh[g][i + 1]);
            }
        }

        if (ct * 64 + 63 > row0 + wm) {
            #pragma unroll
            for (int nf = 0; nf < 8; ++nf) {
                int cg = ct * 64 + nf * 8 + lc2;
                if (cg     > r0g)     s[nf][0] = -CUDART_INF_F;
                if (cg + 1 > r0g)     s[nf][1] = -CUDART_INF_F;
                if (cg     > r0g + 8) s[nf][2] = -CUDART_INF_F;
                if (cg + 1 > r0g + 8) s[nf][3] = -CUDART_INF_F;
            }
        }

        float mt0 = -CUDART_INF_F, mt1 = -CUDART_INF_F;
        #pragma unroll
        for (int nf = 0; nf < 8; ++nf) {
            mt0 = fmaxf(mt0, fmaxf(s[nf][0], s[nf][1]));
            mt1 = fmaxf(mt1, fmaxf(s[nf][2], s[nf][3]));
        }
        mt0 = fmaxf(mt0, __shfl_xor_sync(0xffffffffu, mt0, 1));
        mt0 = fmaxf(mt0, __shfl_xor_sync(0xffffffffu, mt0, 2));
        mt1 = fmaxf(mt1, __shfl_xor_sync(0xffffffffu, mt1, 1));
        mt1 = fmaxf(mt1, __shfl_xor_sync(0xffffffffu, mt1, 2));

        float mn0 = fmaxf(mprev0, mt0);
        float mn1 = fmaxf(mprev1, mt1);
        float a0 = exp2f((mprev0 - mn0) * sc);
        float a1 = exp2f((mprev1 - mn1) * sc);
        lsum0 *= a0; lsum1 *= a1;
        #pragma unroll
        for (int nf = 0; nf < 8; ++nf) {
            s[nf][0] = exp2f((s[nf][0] - mn0) * sc);
            s[nf][1] = exp2f((s[nf][1] - mn0) * sc);
            s[nf][2] = exp2f((s[nf][2] - mn1) * sc);
            s[nf][3] = exp2f((s[nf][3] - mn1) * sc);
            lsum0 += s[nf][0] + s[nf][1];
            lsum1 += s[nf][2] + s[nf][3];
            o[nf][0] *= a0; o[nf][1] *= a0;
            o[nf][2] *= a1; o[nf][3] *= a1;
        }
        mprev0 = mn0; mprev1 = mn1;

        uint32_t pfh[4][4], pfl[4][4];
        #pragma unroll
        for (int kk = 0; kk < 4; ++kk) {
            split_pair(s[2*kk][0],   s[2*kk][1],   pfh[kk][0], pfl[kk][0]);
            split_pair(s[2*kk][2],   s[2*kk][3],   pfh[kk][1], pfl[kk][1]);
            split_pair(s[2*kk+1][0], s[2*kk+1][1], pfh[kk][2], pfl[kk][2]);
            split_pair(s[2*kk+1][2], s[2*kk+1][3], pfh[kk][3], pfl[kk][3]);
        }

        #pragma unroll
        for (int kk = 0; kk < 4; ++kk) {
            #pragma unroll
            for (int dd = 0; dd < 4; ++dd) {
                uint32_t vh[4], vl[4];
                uint32_t off = SWZ128((uint32_t)((kk * 16 + rbA) * 128 + (dd * 2 + cA) * 16));
                ldmx4t(vh, base + 16384 + off);
                ldmx4t(vl, base + 24576 + off);
                #pragma unroll
                for (int j = 0; j < 2; ++j) {
                    int nf = dd * 2 + j;
                    uint32_t b0h = vh[j * 2], b1h = vh[j * 2 + 1];
                    uint32_t b0l = vl[j * 2], b1l = vl[j * 2 + 1];
                    mma16816(o[nf], pfh[kk], b0h, b1h);
                    mma16816(o[nf], pfh[kk], b0l, b1l);
                    mma16816(o[nf], pfl[kk], b0h, b1h);
                }
            }
        }

        __syncthreads();
        if (ct + 2 < nct)
            attn_load_kv(sb, ct & 1, ct + 2, tid, khg, klg, vhg, vlg);
        CP_COMMIT();
    }

    lsum0 += __shfl_xor_sync(0xffffffffu, lsum0, 1);
    lsum0 += __shfl_xor_sync(0xffffffffu, lsum0, 2);
    lsum1 += __shfl_xor_sync(0xffffffffu, lsum1, 1);
    lsum1 += __shfl_xor_sync(0xffffffffu, lsum1, 2);
    float inv0 = 1.f / lsum0;
    float inv1 = 1.f / lsum1;

    const int b = bh >> 4, h = bh & 15;
    const size_t m0G = (size_t)b * SS + (size_t)(row0 + wm + lr);
    __nv_bfloat16* oh0 = g_ohi + m0G * EE + h * DD;
    __nv_bfloat16* ol0 = g_olo + m0G * EE + h * DD;
    __nv_bfloat16* oh1 = oh0 + (size_t)8 * EE;
    __nv_bfloat16* ol1 = ol0 + (size_t)8 * EE;
    #pragma unroll
    for (int nf = 0; nf < 8; ++nf) {
        int col = nf * 8 + lc2;
        uint32_t hi, lo;
        split_pair(o[nf][0] * inv0, o[nf][1] * inv0, hi, lo);
        *(uint32_t*)(oh0 + col) = hi;
        *(uint32_t*)(ol0 + col) = lo;
        split_pair(o[nf][2] * inv1, o[nf][3] * inv1, hi, lo);
        *(uint32_t*)(oh1 + col) = hi;
        *(uint32_t*)(ol1 + col) = lo;
    }
}

// ---------------------------------------------------------------------------
extern "C" void kernel_launch(void* const* d_in, const int* in_sizes, int n_in,
                              void* d_out, int out_size)
{
    const float* x  = (const float*)d_in[0];
    const float* wq = (const float*)d_in[1];
    const float* bq = (const float*)d_in[2];
    const float* wk = (const float*)d_in[3];
    const float* bk = (const float*)d_in[4];
    const float* wv = (const float*)d_in[5];
    const float* bv = (const float*)d_in[6];
    const float* wo = (const float*)d_in[7];
    const float* bo = (const float*)d_in[8];
    float* y = (float*)d_out;

    (void)in_sizes; (void)n_in; (void)out_size;

    cudaFuncSetAttribute(qkv_mma_kernel, cudaFuncAttributeMaxDynamicSharedMemorySize,
                         GEMM_SMEM);
    cudaFuncSetAttribute(oproj_mma_kernel, cudaFuncAttributeMaxDynamicSharedMemorySize,
                         GEMM_SMEM);
    cudaFuncSetAttribute(attn_mma_kernel, cudaFuncAttributeMaxDynamicSharedMemorySize,
                         AT_SMEM);

    // 1) Split/transpose prep (bf16 hi/lo)
    split_x_kernel<<<(MM * EE) / (256 * 8), 256>>>(x);
    split_w_kernel<<<dim3(16, 48), 256>>>(wq, wk, wv);
    split_wo_kernel<<<dim3(16, 16), 256>>>(wo);

    // 2) QKV projection: merged GEMM [8192 x 3072], BN=64, 3 CTAs/SM
    qkv_mma_kernel<<<dim3(64, 48), 256, GEMM_SMEM>>>(bq, bk, bv);

    // 3) Flash attention (mma.sync, split bf16)
    attn_mma_kernel<<<dim3(16, 64), 256, AT_SMEM>>>();

    // 4) Output projection [8192 x 1024]
    oproj_mma_kernel<<<dim3(64, 16), 256, GEMM_SMEM>>>(bo, y);
}

// round 7
// speedup vs baseline: 7.7909x; 2.2563x over previous
#include <cuda_runtime.h>
#include <cuda_fp16.h>
#include <math_constants.h>
#include <cstdint>

#define BB 4
#define SS 2048
#define EE 1024
#define HH 16
#define DD 64
#define MM (BB*SS)   // 8192

// ---------------------------------------------------------------------------
// Device-global scratch (allocation-free rule) — all fp16 now
// ---------------------------------------------------------------------------
__device__ __align__(16) __half g_x16[MM*EE];
__device__ __align__(16) __half g_w16[48*DD*EE];    // [z*64+d][e] == W_all^T
__device__ __align__(16) __half g_wo16[EE*EE];      // [n][k] (wo transposed)
__device__ __align__(16) __half g_q16[BB*HH*SS*DD]; // [bh][s][d], 128B rows
__device__ __align__(16) __half g_k16[BB*HH*SS*DD];
__device__ __align__(16) __half g_v16[BB*HH*SS*DD];
__device__ __align__(16) __half g_o16[MM*EE];       // [m][h*64+d]

// ---------------------------------------------------------------------------
// mma.sync / ldmatrix / cp.async helpers
// ---------------------------------------------------------------------------
__device__ __forceinline__ uint32_t smem_to_u32(const void* p) {
    uint32_t a;
    asm("{ .reg .u64 t; cvta.to.shared.u64 t, %1; cvt.u32.u64 %0, t; }"
        : "=r"(a) : "l"(p));
    return a;
}
__device__ __forceinline__ void cp16(uint32_t saddr, const void* gaddr) {
    asm volatile("cp.async.cg.shared.global [%0], [%1], 16;"
                 :: "r"(saddr), "l"(gaddr));
}
#define CP_COMMIT() asm volatile("cp.async.commit_group;" ::: "memory")
#define CP_WAIT1()  asm volatile("cp.async.wait_group 1;" ::: "memory")
#define CP_WAIT0()  asm volatile("cp.async.wait_group 0;" ::: "memory")

__device__ __forceinline__ void ldmx4(uint32_t* r, uint32_t addr) {
    asm volatile("ldmatrix.sync.aligned.m8n8.x4.shared.b16 {%0,%1,%2,%3}, [%4];"
        : "=r"(r[0]), "=r"(r[1]), "=r"(r[2]), "=r"(r[3]) : "r"(addr));
}
__device__ __forceinline__ void ldmx4t(uint32_t* r, uint32_t addr) {
    asm volatile("ldmatrix.sync.aligned.m8n8.x4.trans.shared.b16 {%0,%1,%2,%3}, [%4];"
        : "=r"(r[0]), "=r"(r[1]), "=r"(r[2]), "=r"(r[3]) : "r"(addr));
}
__device__ __forceinline__ void mmah(float* c, const uint32_t* a,
                                     uint32_t b0, uint32_t b1) {
    asm volatile("mma.sync.aligned.m16n8k16.row.col.f32.f16.f16.f32 "
        "{%0,%1,%2,%3}, {%4,%5,%6,%7}, {%8,%9}, {%0,%1,%2,%3};"
        : "+f"(c[0]), "+f"(c[1]), "+f"(c[2]), "+f"(c[3])
        : "r"(a[0]), "r"(a[1]), "r"(a[2]), "r"(a[3]), "r"(b0), "r"(b1));
}

#define SWZ128(off) ((off) ^ (((off) >> 3) & 0x70))   // 128B rows

__device__ __forceinline__ uint32_t pckh(__half a, __half b) {
    return ((uint32_t)__half_as_ushort(b) << 16) | (uint32_t)__half_as_ushort(a);
}
__device__ __forceinline__ uint32_t cvt_pair(float v0, float v1) {
    return pckh(__float2half_rn(v0), __float2half_rn(v1));
}

// ---------------------------------------------------------------------------
// Conversion prep kernels (fp32 -> fp16)
// ---------------------------------------------------------------------------
__global__ __launch_bounds__(256) void cvt_x_kernel(const float* __restrict__ x) {
    size_t i = ((size_t)blockIdx.x * 256 + threadIdx.x) * 8;
    float4 v0 = *(const float4*)(x + i);
    float4 v1 = *(const float4*)(x + i + 4);
    uint4 u;
    u.x = cvt_pair(v0.x, v0.y); u.y = cvt_pair(v0.z, v0.w);
    u.z = cvt_pair(v1.x, v1.y); u.w = cvt_pair(v1.z, v1.w);
    *(uint4*)(g_x16 + i) = u;
}

// wq/wk/wv [16][1024][64] -> g_w16 [z*64+d][e] (transposed)
__global__ __launch_bounds__(256) void cvt_w_kernel(
    const float* __restrict__ wq, const float* __restrict__ wk, const float* __restrict__ wv) {
    __shared__ float t[64][65];
    const int z = blockIdx.y;
    const int which = z >> 4, h = z & 15;
    const float* W = (which == 0 ? wq : which == 1 ? wk : wv) + (size_t)h * EE * DD;
    const int e0 = blockIdx.x * 64;
    const int tid = threadIdx.x;
    #pragma unroll
    for (int q = 0; q < 4; q++) {
        int idx = q * 256 + tid;
        int r = idx >> 4, c = (idx & 15) * 4;
        float4 v = *(const float4*)(W + (size_t)(e0 + r) * DD + c);
        t[r][c] = v.x; t[r][c+1] = v.y; t[r][c+2] = v.z; t[r][c+3] = v.w;
    }
    __syncthreads();
    #pragma unroll
    for (int q = 0; q < 4; q++) {
        int idx = q * 256 + tid;
        int d = idx >> 4, e = (idx & 15) * 4;
        size_t o = ((size_t)z * DD + d) * EE + e0 + e;
        *(uint32_t*)(g_w16 + o)     = cvt_pair(t[e][d],   t[e+1][d]);
        *(uint32_t*)(g_w16 + o + 2) = cvt_pair(t[e+2][d], t[e+3][d]);
    }
}

// wo [1024 k][1024 n] -> g_wo16 [n][k] (transposed)
__global__ __launch_bounds__(256) void cvt_wo_kernel(const float* __restrict__ wo) {
    __shared__ float t[64][65];
    const int k0 = blockIdx.x * 64;
    const int n0 = blockIdx.y * 64;
    const int tid = threadIdx.x;
    #pragma unroll
    for (int q = 0; q < 4; q++) {
        int idx = q * 256 + tid;
        int r = idx >> 4, c = (idx & 15) * 4;
        float4 v = *(const float4*)(wo + (size_t)(k0 + r) * EE + n0 + c);
        t[r][c] = v.x; t[r][c+1] = v.y; t[r][c+2] = v.z; t[r][c+3] = v.w;
    }
    __syncthreads();
    #pragma unroll
    for (int q = 0; q < 4; q++) {
        int idx = q * 256 + tid;
        int d = idx >> 4, e = (idx & 15) * 4;   // d: n index, e: k index
        size_t o = (size_t)(n0 + d) * EE + k0 + e;
        *(uint32_t*)(g_wo16 + o)     = cvt_pair(t[e][d],   t[e+1][d]);
        *(uint32_t*)(g_wo16 + o + 2) = cvt_pair(t[e+2][d], t[e+3][d]);
    }
}

// ---------------------------------------------------------------------------
// GEMM core 128x64, fp16 single-pass: C = A[128x1024] * B[64x1024]^T
// 256 threads (8 warps, 4m x 2n), warp tile 32x32, BK=64 elems (128B rows),
// 3-stage cp.async. Stage (24KB): A 16K | B 8K. SW128.
// ---------------------------------------------------------------------------
#define STAGE_BYTES 24576
#define GEMM_SMEM   (3 * STAGE_BYTES)

__device__ __forceinline__ void load_stage(
    uint32_t sb, int s, int kt, int tid,
    const char* ag, const char* bg)
{
    const uint32_t st = sb + (uint32_t)s * STAGE_BYTES;
    const int c16 = (tid & 7) * 16;
    const size_t gk = (size_t)kt * 128 + (size_t)c16;
    #pragma unroll
    for (int p = 0; p < 4; ++p) {
        int row = p * 32 + (tid >> 3);
        uint32_t so = SWZ128((uint32_t)(row * 128 + c16));
        cp16(st + so, ag + (size_t)row * 2048 + gk);
    }
    #pragma unroll
    for (int p = 0; p < 2; ++p) {
        int row = p * 32 + (tid >> 3);
        uint32_t so = SWZ128((uint32_t)(row * 128 + c16));
        cp16(st + 16384 + so, bg + (size_t)row * 2048 + gk);
    }
}

__device__ __forceinline__ void gemm_core_128x64_h(
    uint32_t sb, const char* ag, const char* bg, float acc[2][4][4])
{
    const int tid = threadIdx.x;
    const int warp = tid >> 5, lane = tid & 31;
    const int wm = (warp & 3) * 32;
    const int wn = (warp >> 2) * 32;

    uint32_t offA[2], offB[2];
    {
        const int rbA = (lane & 7) + ((lane >> 3) & 1) * 8;
        const int cA  = (lane >> 4) & 1;
        const int rbB = (lane & 7) + ((lane >> 4) & 1) * 8;
        const int cB  = (lane >> 3) & 1;
        #pragma unroll
        for (int f = 0; f < 2; ++f) {
            offA[f] = SWZ128((uint32_t)((wm + f*16 + rbA) * 128 + cA * 16));
            offB[f] = SWZ128((uint32_t)((wn + f*16 + rbB) * 128 + cB * 16));
        }
    }
    #pragma unroll
    for (int f = 0; f < 2; f++)
        #pragma unroll
        for (int nf = 0; nf < 4; nf++)
            #pragma unroll
            for (int i = 0; i < 4; i++) acc[f][nf][i] = 0.f;

    load_stage(sb, 0, 0, tid, ag, bg); CP_COMMIT();
    load_stage(sb, 1, 1, tid, ag, bg); CP_COMMIT();

    for (int kt = 0; kt < 16; ++kt) {
        CP_WAIT1();
        __syncthreads();
        if (kt + 2 < 16)
            load_stage(sb, (kt + 2) % 3, kt + 2, tid, ag, bg);
        CP_COMMIT();

        const uint32_t base = sb + (uint32_t)(kt % 3) * STAGE_BYTES;
        #pragma unroll
        for (int s16 = 0; s16 < 4; ++s16) {
            const uint32_t sx = (uint32_t)(s16 * 32);   // XOR-composable offset
            uint32_t a0[4], a1[4], b0[4], b1[4];
            ldmx4(a0, base + (offA[0] ^ sx));
            ldmx4(a1, base + (offA[1] ^ sx));
            ldmx4(b0, base + 16384 + (offB[0] ^ sx));
            ldmx4(b1, base + 16384 + (offB[1] ^ sx));
            uint32_t* aa[2] = {a0, a1};
            uint32_t* bb[2] = {b0, b1};
            #pragma unroll
            for (int f = 0; f < 2; ++f)
                #pragma unroll
                for (int nf = 0; nf < 4; ++nf)
                    mmah(acc[f][nf], aa[f],
                         bb[nf >> 1][(nf & 1) * 2], bb[nf >> 1][(nf & 1) * 2 + 1]);
        }
    }
}

// ---------------------------------------------------------------------------
// QKV projection: merged GEMM C[8192 x 3072] = X * W_all^T
// grid (64 mtiles, 48 z). Writes fp16 Q/K/V [bh][s][d].
// ---------------------------------------------------------------------------
__global__ __launch_bounds__(256, 3) void qkv_mma_kernel(
    const float* __restrict__ bq, const float* __restrict__ bk,
    const float* __restrict__ bv)
{
    extern __shared__ char smem[];
    const uint32_t sb = smem_to_u32(smem);
    const int tid = threadIdx.x;
    const int m0 = blockIdx.x * 128;
    const int z = blockIdx.y;
    const int which = z >> 4, h = z & 15;

    const char* ag = (const char*)(g_x16 + (size_t)m0 * EE);
    const char* bg = (const char*)(g_w16 + (size_t)z * DD * EE);

    float acc[2][4][4];
    gemm_core_128x64_h(sb, ag, bg, acc);

    const float* bp = (which == 0 ? bq : which == 1 ? bk : bv) + h * DD;
    __half* op = (which == 0 ? g_q16 : which == 1 ? g_k16 : g_v16);

    const int warp = tid >> 5, lane = tid & 31;
    const int wm = (warp & 3) * 32, wn = (warp >> 2) * 32;
    const int r = lane >> 2, cp2 = (lane & 3) * 2;
    #pragma unroll
    for (int f = 0; f < 2; ++f) {
        #pragma unroll
        for (int half = 0; half < 2; ++half) {
            int m = m0 + wm + f * 16 + r + half * 8;
            int b = m >> 11, s = m & 2047;
            size_t rowoff = (((size_t)b * HH + h) * SS + s) * DD;
            #pragma unroll
            for (int nf = 0; nf < 4; ++nf) {
                int d = wn + nf * 8 + cp2;
                float v0 = acc[f][nf][half * 2 + 0] + bp[d];
                float v1 = acc[f][nf][half * 2 + 1] + bp[d + 1];
                *(uint32_t*)(op + rowoff + d) = cvt_pair(v0, v1);
            }
        }
    }
}

// ---------------------------------------------------------------------------
// Output projection: y[8192x1024] = O_cat * wo + bo, grid (64, 16)
// ---------------------------------------------------------------------------
__global__ __launch_bounds__(256, 3) void oproj_mma_kernel(
    const float* __restrict__ bo, float* __restrict__ y)
{
    extern __shared__ char smem[];
    const uint32_t sb = smem_to_u32(smem);
    const int tid = threadIdx.x;
    const int m0 = blockIdx.x * 128;
    const int n0 = blockIdx.y * 64;

    const char* ag = (const char*)(g_o16 + (size_t)m0 * EE);
    const char* bg = (const char*)(g_wo16 + (size_t)n0 * EE);

    float acc[2][4][4];
    gemm_core_128x64_h(sb, ag, bg, acc);

    const int warp = tid >> 5, lane = tid & 31;
    const int wm = (warp & 3) * 32, wn = (warp >> 2) * 32;
    const int r = lane >> 2, cp2 = (lane & 3) * 2;
    #pragma unroll
    for (int f = 0; f < 2; ++f) {
        #pragma unroll
        for (int half = 0; half < 2; ++half) {
            int m = m0 + wm + f * 16 + r + half * 8;
            float* row = y + (size_t)m * EE + n0;
            #pragma unroll
            for (int nf = 0; nf < 4; ++nf) {
                int col = wn + nf * 8 + cp2;
                float2 v;
                v.x = acc[f][nf][half * 2 + 0] + bo[n0 + col];
                v.y = acc[f][nf][half * 2 + 1] + bo[n0 + col + 1];
                *(float2*)(row + col) = v;
            }
        }
    }
}

// ---------------------------------------------------------------------------
// Flash attention, fp16 single-pass, causal.
// Block: 256 threads (8 warps), Br=128 (16 rows/warp), Bc=64, D=64.
// smem: 2 stages x 16KB (K 8K | V 8K), 128B rows, SW128. Q tile 16KB reuses
// stage-0 space before the mainloop starts.
// ---------------------------------------------------------------------------
#define AT_STAGE 16384
#define AT_SMEM  (2 * AT_STAGE)

__device__ __forceinline__ void attn_load_kv(
    uint32_t sb, int stage, int ct, int tid,
    const char* kg, const char* vg)
{
    const uint32_t st = sb + (uint32_t)stage * AT_STAGE;
    const int col0 = ct * 64;
    #pragma unroll
    for (int p = 0; p < 2; ++p) {
        int idx = p * 256 + tid;
        int r = idx >> 3, c16 = (idx & 7) * 16;
        uint32_t so = SWZ128((uint32_t)(r * 128 + c16));
        size_t g = (size_t)(col0 + r) * 128 + c16;
        cp16(st + so,        kg + g);
        cp16(st + 8192 + so, vg + g);
    }
}

__global__ __launch_bounds__(256, 1) void attn_mma_kernel()
{
    extern __shared__ char smem[];
    const uint32_t sb = smem_to_u32(smem);
    const int tid = threadIdx.x;
    const int warp = tid >> 5, lane = tid & 31;
    const int rt = blockIdx.x;            // 0..15 (128-row tiles)
    const int bh = blockIdx.y;            // 0..63
    const int row0 = rt * 128;
    const int wm = warp * 16;

    const char* qg = (const char*)(g_q16 + (size_t)bh * SS * DD);
    const char* kg = (const char*)(g_k16 + (size_t)bh * SS * DD);
    const char* vg = (const char*)(g_v16 + (size_t)bh * SS * DD);

    // ---- load Q tile (16KB at sb), extract A-fragments ----
    #pragma unroll
    for (int p = 0; p < 2; ++p) {
        int idx = p * 256 + tid;
        int r = idx >> 2, c16 = (idx & 3) * 32 + (tid & 1) * 0;  // 128 rows x 8 chunks
        (void)c16;
        // simpler: 128 rows * 8 chunks = 1024 chunks over 2 passes of 512
        int chunk = p * 512 + (tid * 2);
        #pragma unroll
        for (int q = 0; q < 2; ++q) {
            int cc = chunk + q;
            int rr = cc >> 3, c = (cc & 7) * 16;
            uint32_t so = SWZ128((uint32_t)(rr * 128 + c));
            cp16(sb + so, qg + (size_t)(row0 + rr) * 128 + c);
        }
    }
    CP_COMMIT();
    CP_WAIT0();
    __syncthreads();

    const int rbA = (lane & 7) + ((lane >> 3) & 1) * 8;
    const int cA  = (lane >> 4) & 1;
    uint32_t qf[4][4];
    #pragma unroll
    for (int c = 0; c < 4; ++c) {
        uint32_t off = SWZ128((uint32_t)((wm + rbA) * 128 + (c * 2 + cA) * 16));
        ldmx4(qf[c], sb + off);
    }
    __syncthreads();   // done reading Q smem; stages may overwrite

    float o[8][4];
    #pragma unroll
    for (int nf = 0; nf < 8; nf++)
        #pragma unroll
        for (int i = 0; i < 4; i++) o[nf][i] = 0.f;
    float mprev0 = -CUDART_INF_F, mprev1 = -CUDART_INF_F;
    float lsum0 = 0.f, lsum1 = 0.f;

    const float sc = 0.125f * 1.4426950408889634f;   // 1/sqrt(D) * log2(e)
    const int nct = 2 * rt + 2;

    const int rbB = (lane & 7) + ((lane >> 4) & 1) * 8;
    const int cB  = (lane >> 3) & 1;
    const int lr  = lane >> 2;
    const int lc2 = (lane & 3) * 2;
    const int r0g = row0 + wm + lr;

    attn_load_kv(sb, 0, 0, tid, kg, vg); CP_COMMIT();
    attn_load_kv(sb, 1, 1, tid, kg, vg); CP_COMMIT();

    for (int ct = 0; ct < nct; ++ct) {
        CP_WAIT1();
        __syncthreads();
        const uint32_t base = sb + (uint32_t)(ct & 1) * AT_STAGE;

        // ---- S = Q K^T ----
        float s[8][4];
        #pragma unroll
        for (int nf = 0; nf < 8; nf++)
            #pragma unroll
            for (int i = 0; i < 4; i++) s[nf][i] = 0.f;

        #pragma unroll
        for (int c = 0; c < 4; ++c) {
            uint32_t kh[4][4];
            #pragma unroll
            for (int g = 0; g < 4; ++g) {
                uint32_t off = SWZ128((uint32_t)((g * 16 + rbB) * 128 + (c * 2 + cB) * 16));
                ldmx4(kh[g], base + off);
            }
            #pragma unroll
            for (int nf = 0; nf < 8; ++nf) {
                int g = nf >> 1, i = (nf & 1) * 2;
                mmah(s[nf], qf[c], kh[g][i], kh[g][i + 1]);
            }
        }

        // ---- causal mask ----
        if (ct * 64 + 63 > row0 + wm) {
            #pragma unroll
            for (int nf = 0; nf < 8; ++nf) {
                int cg = ct * 64 + nf * 8 + lc2;
                if (cg     > r0g)     s[nf][0] = -CUDART_INF_F;
                if (cg + 1 > r0g)     s[nf][1] = -CUDART_INF_F;
                if (cg     > r0g + 8) s[nf][2] = -CUDART_INF_F;
                if (cg + 1 > r0g + 8) s[nf][3] = -CUDART_INF_F;
            }
        }

        // ---- online softmax ----
        float mt0 = -CUDART_INF_F, mt1 = -CUDART_INF_F;
        #pragma unroll
        for (int nf = 0; nf < 8; ++nf) {
            mt0 = fmaxf(mt0, fmaxf(s[nf][0], s[nf][1]));
            mt1 = fmaxf(mt1, fmaxf(s[nf][2], s[nf][3]));
        }
        mt0 = fmaxf(mt0, __shfl_xor_sync(0xffffffffu, mt0, 1));
        mt0 = fmaxf(mt0, __shfl_xor_sync(0xffffffffu, mt0, 2));
        mt1 = fmaxf(mt1, __shfl_xor_sync(0xffffffffu, mt1, 1));
        mt1 = fmaxf(mt1, __shfl_xor_sync(0xffffffffu, mt1, 2));

        float mn0 = fmaxf(mprev0, mt0);
        float mn1 = fmaxf(mprev1, mt1);
        float a0 = exp2f((mprev0 - mn0) * sc);
        float a1 = exp2f((mprev1 - mn1) * sc);
        lsum0 *= a0; lsum1 *= a1;
        #pragma unroll
        for (int nf = 0; nf < 8; ++nf) {
            s[nf][0] = exp2f((s[nf][0] - mn0) * sc);
            s[nf][1] = exp2f((s[nf][1] - mn0) * sc);
            s[nf][2] = exp2f((s[nf][2] - mn1) * sc);
            s[nf][3] = exp2f((s[nf][3] - mn1) * sc);
            lsum0 += s[nf][0] + s[nf][1];
            lsum1 += s[nf][2] + s[nf][3];
            o[nf][0] *= a0; o[nf][1] *= a0;
            o[nf][2] *= a1; o[nf][3] *= a1;
        }
        mprev0 = mn0; mprev1 = mn1;

        // ---- pack P into fp16 A-fragments ----
        uint32_t pf[4][4];
        #pragma unroll
        for (int kk = 0; kk < 4; ++kk) {
            pf[kk][0] = cvt_pair(s[2*kk][0],   s[2*kk][1]);
            pf[kk][1] = cvt_pair(s[2*kk][2],   s[2*kk][3]);
            pf[kk][2] = cvt_pair(s[2*kk+1][0], s[2*kk+1][1]);
            pf[kk][3] = cvt_pair(s[2*kk+1][2], s[2*kk+1][3]);
        }

        // ---- O += P V (ldmatrix.trans for V) ----
        #pragma unroll
        for (int kk = 0; kk < 4; ++kk) {
            #pragma unroll
            for (int dd = 0; dd < 4; ++dd) {
                uint32_t vh[4];
                uint32_t off = SWZ128((uint32_t)((kk * 16 + rbA) * 128 + (dd * 2 + cA) * 16));
                ldmx4t(vh, base + 8192 + off);
                #pragma unroll
                for (int j = 0; j < 2; ++j) {
                    int nf = dd * 2 + j;
                    mmah(o[nf], pf[kk], vh[j * 2], vh[j * 2 + 1]);
                }
            }
        }

        __syncthreads();
        if (ct + 2 < nct)
            attn_load_kv(sb, ct & 1, ct + 2, tid, kg, vg);
        CP_COMMIT();
    }

    // ---- finalize ----
    lsum0 += __shfl_xor_sync(0xffffffffu, lsum0, 1);
    lsum0 += __shfl_xor_sync(0xffffffffu, lsum0, 2);
    lsum1 += __shfl_xor_sync(0xffffffffu, lsum1, 1);
    lsum1 += __shfl_xor_sync(0xffffffffu, lsum1, 2);
    float inv0 = 1.f / lsum0;
    float inv1 = 1.f / lsum1;

    const int b = bh >> 4, h = bh & 15;
    const size_t m0G = (size_t)b * SS + (size_t)(row0 + wm + lr);
    __half* o0 = g_o16 + m0G * EE + h * DD;
    __half* o1 = o0 + (size_t)8 * EE;
    #pragma unroll
    for (int nf = 0; nf < 8; ++nf) {
        int col = nf * 8 + lc2;
        *(uint32_t*)(o0 + col) = cvt_pair(o[nf][0] * inv0, o[nf][1] * inv0);
        *(uint32_t*)(o1 + col) = cvt_pair(o[nf][2] * inv1, o[nf][3] * inv1);
    }
}

// ---------------------------------------------------------------------------
extern "C" void kernel_launch(void* const* d_in, const int* in_sizes, int n_in,
                              void* d_out, int out_size)
{
    const float* x  = (const float*)d_in[0];
    const float* wq = (const float*)d_in[1];
    const float* bq = (const float*)d_in[2];
    const float* wk = (const float*)d_in[3];
    const float* bk = (const float*)d_in[4];
    const float* wv = (const float*)d_in[5];
    const float* bv = (const float*)d_in[6];
    const float* wo = (const float*)d_in[7];
    const float* bo = (const float*)d_in[8];
    float* y = (float*)d_out;

    (void)in_sizes; (void)n_in; (void)out_size;

    cudaFuncSetAttribute(qkv_mma_kernel, cudaFuncAttributeMaxDynamicSharedMemorySize,
                         GEMM_SMEM);
    cudaFuncSetAttribute(oproj_mma_kernel, cudaFuncAttributeMaxDynamicSharedMemorySize,
                         GEMM_SMEM);
    cudaFuncSetAttribute(attn_mma_kernel, cudaFuncAttributeMaxDynamicSharedMemorySize,
                         AT_SMEM);

    // 1) fp32 -> fp16 prep
    cvt_x_kernel<<<(MM * EE) / (256 * 8), 256>>>(x);
    cvt_w_kernel<<<dim3(16, 48), 256>>>(wq, wk, wv);
    cvt_wo_kernel<<<dim3(16, 16), 256>>>(wo);

    // 2) QKV projection: merged GEMM [8192 x 3072]
    qkv_mma_kernel<<<dim3(64, 48), 256, GEMM_SMEM>>>(bq, bk, bv);

    // 3) Flash attention (fp16 single-pass)
    attn_mma_kernel<<<dim3(16, 64), 256, AT_SMEM>>>();

    // 4) Output projection [8192 x 1024]
    oproj_mma_kernel<<<dim3(64, 16), 256, GEMM_SMEM>>>(bo, y);
}

// round 8
// speedup vs baseline: 7.8250x; 1.0044x over previous
#include <cuda_runtime.h>
#include <cuda_fp16.h>
#include <math_constants.h>
#include <cstdint>

#define BB 4
#define SS 2048
#define EE 1024
#define HH 16
#define DD 64
#define MM (BB*SS)   // 8192

// ---------------------------------------------------------------------------
// Device-global scratch (allocation-free rule) — all fp16
// ---------------------------------------------------------------------------
__device__ __align__(16) __half g_x16[MM*EE];
__device__ __align__(16) __half g_w16[48*DD*EE];    // [z*64+d][e] == W_all^T
__device__ __align__(16) __half g_wo16[EE*EE];      // [n][k] (wo transposed)
__device__ __align__(16) __half g_q16[BB*HH*SS*DD]; // [bh][s][d], 128B rows
__device__ __align__(16) __half g_k16[BB*HH*SS*DD];
__device__ __align__(16) __half g_v16[BB*HH*SS*DD];
__device__ __align__(16) __half g_o16[MM*EE];       // [m][h*64+d]

// ---------------------------------------------------------------------------
// mma.sync / ldmatrix / cp.async helpers
// ---------------------------------------------------------------------------
__device__ __forceinline__ uint32_t smem_to_u32(const void* p) {
    uint32_t a;
    asm("{ .reg .u64 t; cvta.to.shared.u64 t, %1; cvt.u32.u64 %0, t; }"
        : "=r"(a) : "l"(p));
    return a;
}
__device__ __forceinline__ void cp16(uint32_t saddr, const void* gaddr) {
    asm volatile("cp.async.cg.shared.global [%0], [%1], 16;"
                 :: "r"(saddr), "l"(gaddr));
}
#define CP_COMMIT() asm volatile("cp.async.commit_group;" ::: "memory")
#define CP_WAIT1()  asm volatile("cp.async.wait_group 1;" ::: "memory")
#define CP_WAIT0()  asm volatile("cp.async.wait_group 0;" ::: "memory")

__device__ __forceinline__ void ldmx4(uint32_t* r, uint32_t addr) {
    asm volatile("ldmatrix.sync.aligned.m8n8.x4.shared.b16 {%0,%1,%2,%3}, [%4];"
        : "=r"(r[0]), "=r"(r[1]), "=r"(r[2]), "=r"(r[3]) : "r"(addr));
}
__device__ __forceinline__ void ldmx4t(uint32_t* r, uint32_t addr) {
    asm volatile("ldmatrix.sync.aligned.m8n8.x4.trans.shared.b16 {%0,%1,%2,%3}, [%4];"
        : "=r"(r[0]), "=r"(r[1]), "=r"(r[2]), "=r"(r[3]) : "r"(addr));
}
__device__ __forceinline__ void mmah(float* c, const uint32_t* a,
                                     uint32_t b0, uint32_t b1) {
    asm volatile("mma.sync.aligned.m16n8k16.row.col.f32.f16.f16.f32 "
        "{%0,%1,%2,%3}, {%4,%5,%6,%7}, {%8,%9}, {%0,%1,%2,%3};"
        : "+f"(c[0]), "+f"(c[1]), "+f"(c[2]), "+f"(c[3])
        : "r"(a[0]), "r"(a[1]), "r"(a[2]), "r"(a[3]), "r"(b0), "r"(b1));
}

#define SWZ128(off) ((off) ^ (((off) >> 3) & 0x70))   // 128B rows

__device__ __forceinline__ uint32_t pckh(__half a, __half b) {
    return ((uint32_t)__half_as_ushort(b) << 16) | (uint32_t)__half_as_ushort(a);
}
__device__ __forceinline__ uint32_t cvt_pair(float v0, float v1) {
    return pckh(__float2half_rn(v0), __float2half_rn(v1));
}

// ---------------------------------------------------------------------------
// Conversion prep kernels (fp32 -> fp16)
// ---------------------------------------------------------------------------
__global__ __launch_bounds__(256) void cvt_x_kernel(const float* __restrict__ x) {
    size_t i = ((size_t)blockIdx.x * 256 + threadIdx.x) * 8;
    float4 v0 = *(const float4*)(x + i);
    float4 v1 = *(const float4*)(x + i + 4);
    uint4 u;
    u.x = cvt_pair(v0.x, v0.y); u.y = cvt_pair(v0.z, v0.w);
    u.z = cvt_pair(v1.x, v1.y); u.w = cvt_pair(v1.z, v1.w);
    *(uint4*)(g_x16 + i) = u;
}

// wq/wk/wv [16][1024][64] -> g_w16 [z*64+d][e] (transposed)
__global__ __launch_bounds__(256) void cvt_w_kernel(
    const float* __restrict__ wq, const float* __restrict__ wk, const float* __restrict__ wv) {
    __shared__ float t[64][65];
    const int z = blockIdx.y;
    const int which = z >> 4, h = z & 15;
    const float* W = (which == 0 ? wq : which == 1 ? wk : wv) + (size_t)h * EE * DD;
    const int e0 = blockIdx.x * 64;
    const int tid = threadIdx.x;
    #pragma unroll
    for (int q = 0; q < 4; q++) {
        int idx = q * 256 + tid;
        int r = idx >> 4, c = (idx & 15) * 4;
        float4 v = *(const float4*)(W + (size_t)(e0 + r) * DD + c);
        t[r][c] = v.x; t[r][c+1] = v.y; t[r][c+2] = v.z; t[r][c+3] = v.w;
    }
    __syncthreads();
    #pragma unroll
    for (int q = 0; q < 4; q++) {
        int idx = q * 256 + tid;
        int d = idx >> 4, e = (idx & 15) * 4;
        size_t o = ((size_t)z * DD + d) * EE + e0 + e;
        *(uint32_t*)(g_w16 + o)     = cvt_pair(t[e][d],   t[e+1][d]);
        *(uint32_t*)(g_w16 + o + 2) = cvt_pair(t[e+2][d], t[e+3][d]);
    }
}

// wo [1024 k][1024 n] -> g_wo16 [n][k] (transposed)
__global__ __launch_bounds__(256) void cvt_wo_kernel(const float* __restrict__ wo) {
    __shared__ float t[64][65];
    const int k0 = blockIdx.x * 64;
    const int n0 = blockIdx.y * 64;
    const int tid = threadIdx.x;
    #pragma unroll
    for (int q = 0; q < 4; q++) {
        int idx = q * 256 + tid;
        int r = idx >> 4, c = (idx & 15) * 4;
        float4 v = *(const float4*)(wo + (size_t)(k0 + r) * EE + n0 + c);
        t[r][c] = v.x; t[r][c+1] = v.y; t[r][c+2] = v.z; t[r][c+3] = v.w;
    }
    __syncthreads();
    #pragma unroll
    for (int q = 0; q < 4; q++) {
        int idx = q * 256 + tid;
        int d = idx >> 4, e = (idx & 15) * 4;   // d: n index, e: k index
        size_t o = (size_t)(n0 + d) * EE + k0 + e;
        *(uint32_t*)(g_wo16 + o)     = cvt_pair(t[e][d],   t[e+1][d]);
        *(uint32_t*)(g_wo16 + o + 2) = cvt_pair(t[e+2][d], t[e+3][d]);
    }
}

// ---------------------------------------------------------------------------
// GEMM core 128x128, fp16 single-pass: C = A[128x1024] * B[128x1024]^T
// 256 threads (8 warps, 4m x 2n), warp tile 32x64, BK=64 elems (128B rows),
// 3-stage cp.async. Stage (32KB): A 16K | B 16K. SW128.
// ---------------------------------------------------------------------------
#define STAGE_BYTES 32768
#define GEMM_SMEM   (3 * STAGE_BYTES)

__device__ __forceinline__ void load_stage(
    uint32_t sb, int s, int kt, int tid,
    const char* ag, const char* bg)
{
    const uint32_t st = sb + (uint32_t)s * STAGE_BYTES;
    const int c16 = (tid & 7) * 16;
    const size_t gk = (size_t)kt * 128 + (size_t)c16;
    #pragma unroll
    for (int p = 0; p < 4; ++p) {
        int row = p * 32 + (tid >> 3);
        uint32_t so = SWZ128((uint32_t)(row * 128 + c16));
        size_t g = (size_t)row * 2048 + gk;
        cp16(st + so,         ag + g);
        cp16(st + 16384 + so, bg + g);
    }
}

__device__ __forceinline__ void gemm_core_128x128_h(
    uint32_t sb, const char* ag, const char* bg, float acc[2][8][4])
{
    const int tid = threadIdx.x;
    const int warp = tid >> 5, lane = tid & 31;
    const int wm = (warp & 3) * 32;
    const int wn = (warp >> 2) * 64;

    uint32_t offA[2], offB[4];
    {
        const int rbA = (lane & 7) + ((lane >> 3) & 1) * 8;
        const int cA  = (lane >> 4) & 1;
        const int rbB = (lane & 7) + ((lane >> 4) & 1) * 8;
        const int cB  = (lane >> 3) & 1;
        #pragma unroll
        for (int f = 0; f < 2; ++f)
            offA[f] = SWZ128((uint32_t)((wm + f*16 + rbA) * 128 + cA * 16));
        #pragma unroll
        for (int g = 0; g < 4; ++g)
            offB[g] = SWZ128((uint32_t)((wn + g*16 + rbB) * 128 + cB * 16));
    }
    #pragma unroll
    for (int f = 0; f < 2; f++)
        #pragma unroll
        for (int nf = 0; nf < 8; nf++)
            #pragma unroll
            for (int i = 0; i < 4; i++) acc[f][nf][i] = 0.f;

    load_stage(sb, 0, 0, tid, ag, bg); CP_COMMIT();
    load_stage(sb, 1, 1, tid, ag, bg); CP_COMMIT();

    for (int kt = 0; kt < 16; ++kt) {
        CP_WAIT1();
        __syncthreads();
        if (kt + 2 < 16)
            load_stage(sb, (kt + 2) % 3, kt + 2, tid, ag, bg);
        CP_COMMIT();

        const uint32_t base = sb + (uint32_t)(kt % 3) * STAGE_BYTES;
        #pragma unroll
        for (int s16 = 0; s16 < 4; ++s16) {
            const uint32_t sx = (uint32_t)(s16 * 32);   // XOR-composable col offset
            uint32_t a0[4], a1[4];
            ldmx4(a0, base + (offA[0] ^ sx));
            ldmx4(a1, base + (offA[1] ^ sx));
            uint32_t b[4][4];
            #pragma unroll
            for (int g = 0; g < 4; ++g)
                ldmx4(b[g], base + 16384 + (offB[g] ^ sx));
            uint32_t* aa[2] = {a0, a1};
            #pragma unroll
            for (int f = 0; f < 2; ++f)
                #pragma unroll
                for (int nf = 0; nf < 8; ++nf)
                    mmah(acc[f][nf], aa[f],
                         b[nf >> 1][(nf & 1) * 2], b[nf >> 1][(nf & 1) * 2 + 1]);
        }
    }
}

// ---------------------------------------------------------------------------
// QKV projection: merged GEMM C[8192 x 3072] = X * W_all^T
// grid (64 mtiles, 24 ntiles of 128). Each warp's 64 cols = ONE head z.
// ---------------------------------------------------------------------------
__global__ __launch_bounds__(256, 2) void qkv_mma_kernel(
    const float* __restrict__ bq, const float* __restrict__ bk,
    const float* __restrict__ bv)
{
    extern __shared__ char smem[];
    const uint32_t sb = smem_to_u32(smem);
    const int tid = threadIdx.x;
    const int m0 = blockIdx.x * 128;
    const int n0 = blockIdx.y * 128;

    const char* ag = (const char*)(g_x16 + (size_t)m0 * EE);
    const char* bg = (const char*)(g_w16 + (size_t)n0 * EE);

    float acc[2][8][4];
    gemm_core_128x128_h(sb, ag, bg, acc);

    const int warp = tid >> 5, lane = tid & 31;
    const int wm = (warp & 3) * 32, wn = (warp >> 2) * 64;
    const int r = lane >> 2, cp2 = (lane & 3) * 2;

    const int z = (n0 + wn) >> 6;               // one head per warp
    const int which = z >> 4, h = z & 15;
    const float* bp = (which == 0 ? bq : which == 1 ? bk : bv) + h * DD;
    __half* op = (which == 0 ? g_q16 : which == 1 ? g_k16 : g_v16);

    #pragma unroll
    for (int f = 0; f < 2; ++f) {
        #pragma unroll
        for (int half = 0; half < 2; ++half) {
            int m = m0 + wm + f * 16 + r + half * 8;
            int b = m >> 11, s = m & 2047;
            size_t rowoff = (((size_t)b * HH + h) * SS + s) * DD;
            #pragma unroll
            for (int nf = 0; nf < 8; ++nf) {
                int d = nf * 8 + cp2;
                float v0 = acc[f][nf][half * 2 + 0] + bp[d];
                float v1 = acc[f][nf][half * 2 + 1] + bp[d + 1];
                *(uint32_t*)(op + rowoff + d) = cvt_pair(v0, v1);
            }
        }
    }
}

// ---------------------------------------------------------------------------
// Output projection: y[8192x1024] = O_cat * wo + bo, grid (64, 8)
// ---------------------------------------------------------------------------
__global__ __launch_bounds__(256, 2) void oproj_mma_kernel(
    const float* __restrict__ bo, float* __restrict__ y)
{
    extern __shared__ char smem[];
    const uint32_t sb = smem_to_u32(smem);
    const int tid = threadIdx.x;
    const int m0 = blockIdx.x * 128;
    const int n0 = blockIdx.y * 128;

    const char* ag = (const char*)(g_o16 + (size_t)m0 * EE);
    const char* bg = (const char*)(g_wo16 + (size_t)n0 * EE);

    float acc[2][8][4];
    gemm_core_128x128_h(sb, ag, bg, acc);

    const int warp = tid >> 5, lane = tid & 31;
    const int wm = (warp & 3) * 32, wn = (warp >> 2) * 64;
    const int r = lane >> 2, cp2 = (lane & 3) * 2;
    #pragma unroll
    for (int f = 0; f < 2; ++f) {
        #pragma unroll
        for (int half = 0; half < 2; ++half) {
            int m = m0 + wm + f * 16 + r + half * 8;
            float* row = y + (size_t)m * EE + n0 + wn;
            #pragma unroll
            for (int nf = 0; nf < 8; ++nf) {
                int col = nf * 8 + cp2;
                float2 v;
                v.x = acc[f][nf][half * 2 + 0] + bo[n0 + wn + col];
                v.y = acc[f][nf][half * 2 + 1] + bo[n0 + wn + col + 1];
                *(float2*)(row + col) = v;
            }
        }
    }
}

// ---------------------------------------------------------------------------
// Flash attention, fp16 single-pass, causal.
// Block: 256 threads (8 warps), Br=128 (16 rows/warp), Bc=64, D=64.
// smem: 2 stages x 16KB (K 8K | V 8K), SW128. 2 CTAs/SM; long blocks first.
// ---------------------------------------------------------------------------
#define AT_STAGE 16384
#define AT_SMEM  (2 * AT_STAGE)

__device__ __forceinline__ void attn_load_kv(
    uint32_t sb, int stage, int ct, int tid,
    const char* kg, const char* vg)
{
    const uint32_t st = sb + (uint32_t)stage * AT_STAGE;
    const int col0 = ct * 64;
    #pragma unroll
    for (int p = 0; p < 2; ++p) {
        int idx = p * 256 + tid;
        int r = idx >> 3, c16 = (idx & 7) * 16;
        uint32_t so = SWZ128((uint32_t)(r * 128 + c16));
        size_t g = (size_t)(col0 + r) * 128 + c16;
        cp16(st + so,        kg + g);
        cp16(st + 8192 + so, vg + g);
    }
}

__global__ __launch_bounds__(256, 2) void attn_mma_kernel()
{
    extern __shared__ char smem[];
    const uint32_t sb = smem_to_u32(smem);
    const int tid = threadIdx.x;
    const int warp = tid >> 5, lane = tid & 31;
    const int rt = (int)gridDim.x - 1 - (int)blockIdx.x;  // long blocks first
    const int bh = blockIdx.y;
    const int row0 = rt * 128;
    const int wm = warp * 16;

    const char* qg = (const char*)(g_q16 + (size_t)bh * SS * DD);
    const char* kg = (const char*)(g_k16 + (size_t)bh * SS * DD);
    const char* vg = (const char*)(g_v16 + (size_t)bh * SS * DD);

    // ---- load Q tile (16KB at sb), extract A-fragments ----
    #pragma unroll
    for (int p = 0; p < 4; ++p) {
        int cc = p * 256 + tid;
        int rr = cc >> 3, c = (cc & 7) * 16;
        uint32_t so = SWZ128((uint32_t)(rr * 128 + c));
        cp16(sb + so, qg + (size_t)(row0 + rr) * 128 + c);
    }
    CP_COMMIT();
    CP_WAIT0();
    __syncthreads();

    const int rbA = (lane & 7) + ((lane >> 3) & 1) * 8;
    const int cA  = (lane >> 4) & 1;
    uint32_t qf[4][4];
    #pragma unroll
    for (int c = 0; c < 4; ++c) {
        uint32_t off = SWZ128((uint32_t)((wm + rbA) * 128 + (c * 2 + cA) * 16));
        ldmx4(qf[c], sb + off);
    }
    __syncthreads();   // done reading Q smem; stages may overwrite

    float o[8][4];
    #pragma unroll
    for (int nf = 0; nf < 8; nf++)
        #pragma unroll
        for (int i = 0; i < 4; i++) o[nf][i] = 0.f;
    float mprev0 = -CUDART_INF_F, mprev1 = -CUDART_INF_F;
    float lsum0 = 0.f, lsum1 = 0.f;

    const float sc = 0.125f * 1.4426950408889634f;   // 1/sqrt(D) * log2(e)
    const int nct = 2 * rt + 2;

    const int rbB = (lane & 7) + ((lane >> 4) & 1) * 8;
    const int cB  = (lane >> 3) & 1;
    const int lr  = lane >> 2;
    const int lc2 = (lane & 3) * 2;
    const int r0g = row0 + wm + lr;

    attn_load_kv(sb, 0, 0, tid, kg, vg); CP_COMMIT();
    attn_load_kv(sb, 1, 1, tid, kg, vg); CP_COMMIT();

    for (int ct = 0; ct < nct; ++ct) {
        CP_WAIT1();
        __syncthreads();
        const uint32_t base = sb + (uint32_t)(ct & 1) * AT_STAGE;

        // ---- S = Q K^T ----
        float s[8][4];
        #pragma unroll
        for (int nf = 0; nf < 8; nf++)
            #pragma unroll
            for (int i = 0; i < 4; i++) s[nf][i] = 0.f;

        #pragma unroll
        for (int c = 0; c < 4; ++c) {
            uint32_t kh[4][4];
            #pragma unroll
            for (int g = 0; g < 4; ++g) {
                uint32_t off = SWZ128((uint32_t)((g * 16 + rbB) * 128 + (c * 2 + cB) * 16));
                ldmx4(kh[g], base + off);
            }
            #pragma unroll
            for (int nf = 0; nf < 8; ++nf) {
                int g = nf >> 1, i = (nf & 1) * 2;
                mmah(s[nf], qf[c], kh[g][i], kh[g][i + 1]);
            }
        }

        // ---- causal mask ----
        if (ct * 64 + 63 > row0 + wm) {
            #pragma unroll
            for (int nf = 0; nf < 8; ++nf) {
                int cg = ct * 64 + nf * 8 + lc2;
                if (cg     > r0g)     s[nf][0] = -CUDART_INF_F;
                if (cg + 1 > r0g)     s[nf][1] = -CUDART_INF_F;
                if (cg     > r0g + 8) s[nf][2] = -CUDART_INF_F;
                if (cg + 1 > r0g + 8) s[nf][3] = -CUDART_INF_F;
            }
        }

        // ---- online softmax ----
        float mt0 = -CUDART_INF_F, mt1 = -CUDART_INF_F;
        #pragma unroll
        for (int nf = 0; nf < 8; ++nf) {
            mt0 = fmaxf(mt0, fmaxf(s[nf][0], s[nf][1]));
            mt1 = fmaxf(mt1, fmaxf(s[nf][2], s[nf][3]));
        }
        mt0 = fmaxf(mt0, __shfl_xor_sync(0xffffffffu, mt0, 1));
        mt0 = fmaxf(mt0, __shfl_xor_sync(0xffffffffu, mt0, 2));
        mt1 = fmaxf(mt1, __shfl_xor_sync(0xffffffffu, mt1, 1));
        mt1 = fmaxf(mt1, __shfl_xor_sync(0xffffffffu, mt1, 2));

        float mn0 = fmaxf(mprev0, mt0);
        float mn1 = fmaxf(mprev1, mt1);
        float a0 = exp2f((mprev0 - mn0) * sc);
        float a1 = exp2f((mprev1 - mn1) * sc);
        lsum0 *= a0; lsum1 *= a1;
        #pragma unroll
        for (int nf = 0; nf < 8; ++nf) {
            s[nf][0] = exp2f((s[nf][0] - mn0) * sc);
            s[nf][1] = exp2f((s[nf][1] - mn0) * sc);
            s[nf][2] = exp2f((s[nf][2] - mn1) * sc);
            s[nf][3] = exp2f((s[nf][3] - mn1) * sc);
            lsum0 += s[nf][0] + s[nf][1];
            lsum1 += s[nf][2] + s[nf][3];
            o[nf][0] *= a0; o[nf][1] *= a0;
            o[nf][2] *= a1; o[nf][3] *= a1;
        }
        mprev0 = mn0; mprev1 = mn1;

        // ---- pack P into fp16 A-fragments ----
        uint32_t pf[4][4];
        #pragma unroll
        for (int kk = 0; kk < 4; ++kk) {
            pf[kk][0] = cvt_pair(s[2*kk][0],   s[2*kk][1]);
            pf[kk][1] = cvt_pair(s[2*kk][2],   s[2*kk][3]);
            pf[kk][2] = cvt_pair(s[2*kk+1][0], s[2*kk+1][1]);
            pf[kk][3] = cvt_pair(s[2*kk+1][2], s[2*kk+1][3]);
        }

        // ---- O += P V (ldmatrix.trans for V) ----
        #pragma unroll
        for (int kk = 0; kk < 4; ++kk) {
            #pragma unroll
            for (int dd = 0; dd < 4; ++dd) {
                uint32_t vh[4];
                uint32_t off = SWZ128((uint32_t)((kk * 16 + rbA) * 128 + (dd * 2 + cA) * 16));
                ldmx4t(vh, base + 8192 + off);
                #pragma unroll
                for (int j = 0; j < 2; ++j) {
                    int nf = dd * 2 + j;
                    mmah(o[nf], pf[kk], vh[j * 2], vh[j * 2 + 1]);
                }
            }
        }

        __syncthreads();
        if (ct + 2 < nct)
            attn_load_kv(sb, ct & 1, ct + 2, tid, kg, vg);
        CP_COMMIT();
    }

    // ---- finalize ----
    lsum0 += __shfl_xor_sync(0xffffffffu, lsum0, 1);
    lsum0 += __shfl_xor_sync(0xffffffffu, lsum0, 2);
    lsum1 += __shfl_xor_sync(0xffffffffu, lsum1, 1);
    lsum1 += __shfl_xor_sync(0xffffffffu, lsum1, 2);
    float inv0 = 1.f / lsum0;
    float inv1 = 1.f / lsum1;

    const int b = bh >> 4, h = bh & 15;
    const size_t m0G = (size_t)b * SS + (size_t)(row0 + wm + lr);
    __half* o0 = g_o16 + m0G * EE + h * DD;
    __half* o1 = o0 + (size_t)8 * EE;
    #pragma unroll
    for (int nf = 0; nf < 8; ++nf) {
        int col = nf * 8 + lc2;
        *(uint32_t*)(o0 + col) = cvt_pair(o[nf][0] * inv0, o[nf][1] * inv0);
        *(uint32_t*)(o1 + col) = cvt_pair(o[nf][2] * inv1, o[nf][3] * inv1);
    }
}

// ---------------------------------------------------------------------------
extern "C" void kernel_launch(void* const* d_in, const int* in_sizes, int n_in,
                              void* d_out, int out_size)
{
    const float* x  = (const float*)d_in[0];
    const float* wq = (const float*)d_in[1];
    const float* bq = (const float*)d_in[2];
    const float* wk = (const float*)d_in[3];
    const float* bk = (const float*)d_in[4];
    const float* wv = (const float*)d_in[5];
    const float* bv = (const float*)d_in[6];
    const float* wo = (const float*)d_in[7];
    const float* bo = (const float*)d_in[8];
    float* y = (float*)d_out;

    (void)in_sizes; (void)n_in; (void)out_size;

    cudaFuncSetAttribute(qkv_mma_kernel, cudaFuncAttributeMaxDynamicSharedMemorySize,
                         GEMM_SMEM);
    cudaFuncSetAttribute(oproj_mma_kernel, cudaFuncAttributeMaxDynamicSharedMemorySize,
                         GEMM_SMEM);
    cudaFuncSetAttribute(attn_mma_kernel, cudaFuncAttributeMaxDynamicSharedMemorySize,
                         AT_SMEM);

    // 1) fp32 -> fp16 prep
    cvt_x_kernel<<<(MM * EE) / (256 * 8), 256>>>(x);
    cvt_w_kernel<<<dim3(16, 48), 256>>>(wq, wk, wv);
    cvt_wo_kernel<<<dim3(16, 16), 256>>>(wo);

    // 2) QKV projection: merged GEMM [8192 x 3072], 128x128 tiles
    qkv_mma_kernel<<<dim3(64, 24), 256, GEMM_SMEM>>>(bq, bk, bv);

    // 3) Flash attention (fp16 single-pass, 2 CTAs/SM, long-first)
    attn_mma_kernel<<<dim3(16, 64), 256, AT_SMEM>>>();

    // 4) Output projection [8192 x 1024], 128x128 tiles
    oproj_mma_kernel<<<dim3(64, 8), 256, GEMM_SMEM>>>(bo, y);
}

// round 9
// speedup vs baseline: 8.2246x; 1.0511x over previous
#include <cuda_runtime.h>
#include <cuda_fp16.h>
#include <math_constants.h>
#include <cstdint>

#define BB 4
#define SS 2048
#define EE 1024
#define HH 16
#define DD 64
#define MM (BB*SS)   // 8192

// ---------------------------------------------------------------------------
// Device-global scratch (allocation-free rule) — all fp16
// ---------------------------------------------------------------------------
__device__ __align__(16) __half g_x16[MM*EE];
__device__ __align__(16) __half g_w16[48*DD*EE];    // [z*64+d][e] == W_all^T
__device__ __align__(16) __half g_wo16[EE*EE];      // [n][k] (wo transposed)
__device__ __align__(16) __half g_q16[BB*HH*SS*DD]; // [bh][s][d], pre-scaled by 1/sqrt(D)*log2e
__device__ __align__(16) __half g_k16[BB*HH*SS*DD];
__device__ __align__(16) __half g_v16[BB*HH*SS*DD];
__device__ __align__(16) __half g_o16[MM*EE];       // [m][h*64+d]

// ---------------------------------------------------------------------------
// mma.sync / ldmatrix / cp.async helpers
// ---------------------------------------------------------------------------
__device__ __forceinline__ uint32_t smem_to_u32(const void* p) {
    uint32_t a;
    asm("{ .reg .u64 t; cvta.to.shared.u64 t, %1; cvt.u32.u64 %0, t; }"
        : "=r"(a) : "l"(p));
    return a;
}
__device__ __forceinline__ void cp16(uint32_t saddr, const void* gaddr) {
    asm volatile("cp.async.cg.shared.global [%0], [%1], 16;"
                 :: "r"(saddr), "l"(gaddr));
}
#define CP_COMMIT() asm volatile("cp.async.commit_group;" ::: "memory")
#define CP_WAIT1()  asm volatile("cp.async.wait_group 1;" ::: "memory")
#define CP_WAIT2()  asm volatile("cp.async.wait_group 2;" ::: "memory")
#define CP_WAIT0()  asm volatile("cp.async.wait_group 0;" ::: "memory")

__device__ __forceinline__ void ldmx4(uint32_t* r, uint32_t addr) {
    asm volatile("ldmatrix.sync.aligned.m8n8.x4.shared.b16 {%0,%1,%2,%3}, [%4];"
        : "=r"(r[0]), "=r"(r[1]), "=r"(r[2]), "=r"(r[3]) : "r"(addr));
}
__device__ __forceinline__ void ldmx4t(uint32_t* r, uint32_t addr) {
    asm volatile("ldmatrix.sync.aligned.m8n8.x4.trans.shared.b16 {%0,%1,%2,%3}, [%4];"
        : "=r"(r[0]), "=r"(r[1]), "=r"(r[2]), "=r"(r[3]) : "r"(addr));
}
__device__ __forceinline__ void mmah(float* c, const uint32_t* a,
                                     uint32_t b0, uint32_t b1) {
    asm volatile("mma.sync.aligned.m16n8k16.row.col.f32.f16.f16.f32 "
        "{%0,%1,%2,%3}, {%4,%5,%6,%7}, {%8,%9}, {%0,%1,%2,%3};"
        : "+f"(c[0]), "+f"(c[1]), "+f"(c[2]), "+f"(c[3])
        : "r"(a[0]), "r"(a[1]), "r"(a[2]), "r"(a[3]), "r"(b0), "r"(b1));
}

#define SWZ128(off) ((off) ^ (((off) >> 3) & 0x70))   // 128B rows

__device__ __forceinline__ uint32_t pckh(__half a, __half b) {
    return ((uint32_t)__half_as_ushort(b) << 16) | (uint32_t)__half_as_ushort(a);
}
__device__ __forceinline__ uint32_t cvt_pair(float v0, float v1) {
    return pckh(__float2half_rn(v0), __float2half_rn(v1));
}

// ---------------------------------------------------------------------------
// Merged prep kernel: fp32 -> fp16 for x, W_all (transposed), wo (transposed)
// grid = 4096 (x) + 768 (w) + 256 (wo) = 5120 blocks of 256.
// ---------------------------------------------------------------------------
__global__ __launch_bounds__(256) void prep_kernel(
    const float* __restrict__ x,
    const float* __restrict__ wq, const float* __restrict__ wk,
    const float* __restrict__ wv, const float* __restrict__ wo)
{
    __shared__ float t[64][65];
    const int bid = blockIdx.x;
    const int tid = threadIdx.x;

    if (bid < 4096) {
        size_t i = ((size_t)bid * 256 + tid) * 8;
        float4 v0 = *(const float4*)(x + i);
        float4 v1 = *(const float4*)(x + i + 4);
        uint4 u;
        u.x = cvt_pair(v0.x, v0.y); u.y = cvt_pair(v0.z, v0.w);
        u.z = cvt_pair(v1.x, v1.y); u.w = cvt_pair(v1.z, v1.w);
        *(uint4*)(g_x16 + i) = u;
    } else if (bid < 4096 + 768) {
        const int tt = bid - 4096;
        const int e0 = (tt & 15) * 64;
        const int z = tt >> 4;
        const int which = z >> 4, h = z & 15;
        const float* W = (which == 0 ? wq : which == 1 ? wk : wv) + (size_t)h * EE * DD;
        #pragma unroll
        for (int q = 0; q < 4; q++) {
            int idx = q * 256 + tid;
            int r = idx >> 4, c = (idx & 15) * 4;
            float4 v = *(const float4*)(W + (size_t)(e0 + r) * DD + c);
            t[r][c] = v.x; t[r][c+1] = v.y; t[r][c+2] = v.z; t[r][c+3] = v.w;
        }
        __syncthreads();
        #pragma unroll
        for (int q = 0; q < 4; q++) {
            int idx = q * 256 + tid;
            int d = idx >> 4, e = (idx & 15) * 4;
            size_t o = ((size_t)z * DD + d) * EE + e0 + e;
            *(uint32_t*)(g_w16 + o)     = cvt_pair(t[e][d],   t[e+1][d]);
            *(uint32_t*)(g_w16 + o + 2) = cvt_pair(t[e+2][d], t[e+3][d]);
        }
    } else {
        const int tt = bid - (4096 + 768);
        const int k0 = (tt & 15) * 64;
        const int n0 = (tt >> 4) * 64;
        #pragma unroll
        for (int q = 0; q < 4; q++) {
            int idx = q * 256 + tid;
            int r = idx >> 4, c = (idx & 15) * 4;
            float4 v = *(const float4*)(wo + (size_t)(k0 + r) * EE + n0 + c);
            t[r][c] = v.x; t[r][c+1] = v.y; t[r][c+2] = v.z; t[r][c+3] = v.w;
        }
        __syncthreads();
        #pragma unroll
        for (int q = 0; q < 4; q++) {
            int idx = q * 256 + tid;
            int d = idx >> 4, e = (idx & 15) * 4;
            size_t o = (size_t)(n0 + d) * EE + k0 + e;
            *(uint32_t*)(g_wo16 + o)     = cvt_pair(t[e][d],   t[e+1][d]);
            *(uint32_t*)(g_wo16 + o + 2) = cvt_pair(t[e+2][d], t[e+3][d]);
        }
    }
}

// ---------------------------------------------------------------------------
// GEMM core 128x128, fp16 single-pass (unchanged from R8)
// ---------------------------------------------------------------------------
#define STAGE_BYTES 32768
#define GEMM_SMEM   (3 * STAGE_BYTES)

__device__ __forceinline__ void load_stage(
    uint32_t sb, int s, int kt, int tid,
    const char* ag, const char* bg)
{
    const uint32_t st = sb + (uint32_t)s * STAGE_BYTES;
    const int c16 = (tid & 7) * 16;
    const size_t gk = (size_t)kt * 128 + (size_t)c16;
    #pragma unroll
    for (int p = 0; p < 4; ++p) {
        int row = p * 32 + (tid >> 3);
        uint32_t so = SWZ128((uint32_t)(row * 128 + c16));
        size_t g = (size_t)row * 2048 + gk;
        cp16(st + so,         ag + g);
        cp16(st + 16384 + so, bg + g);
    }
}

__device__ __forceinline__ void gemm_core_128x128_h(
    uint32_t sb, const char* ag, const char* bg, float acc[2][8][4])
{
    const int tid = threadIdx.x;
    const int warp = tid >> 5, lane = tid & 31;
    const int wm = (warp & 3) * 32;
    const int wn = (warp >> 2) * 64;

    uint32_t offA[2], offB[4];
    {
        const int rbA = (lane & 7) + ((lane >> 3) & 1) * 8;
        const int cA  = (lane >> 4) & 1;
        const int rbB = (lane & 7) + ((lane >> 4) & 1) * 8;
        const int cB  = (lane >> 3) & 1;
        #pragma unroll
        for (int f = 0; f < 2; ++f)
            offA[f] = SWZ128((uint32_t)((wm + f*16 + rbA) * 128 + cA * 16));
        #pragma unroll
        for (int g = 0; g < 4; ++g)
            offB[g] = SWZ128((uint32_t)((wn + g*16 + rbB) * 128 + cB * 16));
    }
    #pragma unroll
    for (int f = 0; f < 2; f++)
        #pragma unroll
        for (int nf = 0; nf < 8; nf++)
            #pragma unroll
            for (int i = 0; i < 4; i++) acc[f][nf][i] = 0.f;

    load_stage(sb, 0, 0, tid, ag, bg); CP_COMMIT();
    load_stage(sb, 1, 1, tid, ag, bg); CP_COMMIT();

    for (int kt = 0; kt < 16; ++kt) {
        CP_WAIT1();
        __syncthreads();
        if (kt + 2 < 16)
            load_stage(sb, (kt + 2) % 3, kt + 2, tid, ag, bg);
        CP_COMMIT();

        const uint32_t base = sb + (uint32_t)(kt % 3) * STAGE_BYTES;
        #pragma unroll
        for (int s16 = 0; s16 < 4; ++s16) {
            const uint32_t sx = (uint32_t)(s16 * 32);
            uint32_t a0[4], a1[4];
            ldmx4(a0, base + (offA[0] ^ sx));
            ldmx4(a1, base + (offA[1] ^ sx));
            uint32_t b[4][4];
            #pragma unroll
            for (int g = 0; g < 4; ++g)
                ldmx4(b[g], base + 16384 + (offB[g] ^ sx));
            uint32_t* aa[2] = {a0, a1};
            #pragma unroll
            for (int f = 0; f < 2; ++f)
                #pragma unroll
                for (int nf = 0; nf < 8; ++nf)
                    mmah(acc[f][nf], aa[f],
                         b[nf >> 1][(nf & 1) * 2], b[nf >> 1][(nf & 1) * 2 + 1]);
        }
    }
}

// ---------------------------------------------------------------------------
// QKV projection: merged GEMM C[8192 x 3072] = X * W_all^T
// Q outputs pre-scaled by 1/sqrt(D)*log2(e) so attention skips the FMUL.
// ---------------------------------------------------------------------------
__global__ __launch_bounds__(256, 2) void qkv_mma_kernel(
    const float* __restrict__ bq, const float* __restrict__ bk,
    const float* __restrict__ bv)
{
    extern __shared__ char smem[];
    const uint32_t sb = smem_to_u32(smem);
    const int tid = threadIdx.x;
    const int m0 = blockIdx.x * 128;
    const int n0 = blockIdx.y * 128;

    const char* ag = (const char*)(g_x16 + (size_t)m0 * EE);
    const char* bg = (const char*)(g_w16 + (size_t)n0 * EE);

    float acc[2][8][4];
    gemm_core_128x128_h(sb, ag, bg, acc);

    const int warp = tid >> 5, lane = tid & 31;
    const int wm = (warp & 3) * 32, wn = (warp >> 2) * 64;
    const int r = lane >> 2, cp2 = (lane & 3) * 2;

    const int z = (n0 + wn) >> 6;               // one head per warp
    const int which = z >> 4, h = z & 15;
    const float* bp = (which == 0 ? bq : which == 1 ? bk : bv) + h * DD;
    __half* op = (which == 0 ? g_q16 : which == 1 ? g_k16 : g_v16);
    const float osc = (which == 0) ? 0.125f * 1.4426950408889634f : 1.0f;

    #pragma unroll
    for (int f = 0; f < 2; ++f) {
        #pragma unroll
        for (int half = 0; half < 2; ++half) {
            int m = m0 + wm + f * 16 + r + half * 8;
            int b = m >> 11, s = m & 2047;
            size_t rowoff = (((size_t)b * HH + h) * SS + s) * DD;
            #pragma unroll
            for (int nf = 0; nf < 8; ++nf) {
                int d = nf * 8 + cp2;
                float v0 = (acc[f][nf][half * 2 + 0] + bp[d]) * osc;
                float v1 = (acc[f][nf][half * 2 + 1] + bp[d + 1]) * osc;
                *(uint32_t*)(op + rowoff + d) = cvt_pair(v0, v1);
            }
        }
    }
}

// ---------------------------------------------------------------------------
// Output projection: y[8192x1024] = O_cat * wo + bo, grid (64, 8)
// ---------------------------------------------------------------------------
__global__ __launch_bounds__(256, 2) void oproj_mma_kernel(
    const float* __restrict__ bo, float* __restrict__ y)
{
    extern __shared__ char smem[];
    const uint32_t sb = smem_to_u32(smem);
    const int tid = threadIdx.x;
    const int m0 = blockIdx.x * 128;
    const int n0 = blockIdx.y * 128;

    const char* ag = (const char*)(g_o16 + (size_t)m0 * EE);
    const char* bg = (const char*)(g_wo16 + (size_t)n0 * EE);

    float acc[2][8][4];
    gemm_core_128x128_h(sb, ag, bg, acc);

    const int warp = tid >> 5, lane = tid & 31;
    const int wm = (warp & 3) * 32, wn = (warp >> 2) * 64;
    const int r = lane >> 2, cp2 = (lane & 3) * 2;
    #pragma unroll
    for (int f = 0; f < 2; ++f) {
        #pragma unroll
        for (int half = 0; half < 2; ++half) {
            int m = m0 + wm + f * 16 + r + half * 8;
            float* row = y + (size_t)m * EE + n0 + wn;
            #pragma unroll
            for (int nf = 0; nf < 8; ++nf) {
                int col = nf * 8 + cp2;
                float2 v;
                v.x = acc[f][nf][half * 2 + 0] + bo[n0 + wn + col];
                v.y = acc[f][nf][half * 2 + 1] + bo[n0 + wn + col + 1];
                *(float2*)(row + col) = v;
            }
        }
    }
}

// ---------------------------------------------------------------------------
// Flash attention, fp16 single-pass, causal. Q pre-scaled (log2 domain).
// Block: 256 threads (8 warps), Br=128, Bc=64, D=64.
// smem: 3 stages x 16KB (K 8K | V 8K), SW128. 2 CTAs/SM; long blocks first.
// Fully-masked warp tiles (diagonal) skip all compute.
// ---------------------------------------------------------------------------
#define AT_STAGE 16384
#define AT_SMEM  (3 * AT_STAGE)

__device__ __forceinline__ void attn_load_kv(
    uint32_t sb, int stage, int ct, int tid,
    const char* kg, const char* vg)
{
    const uint32_t st = sb + (uint32_t)stage * AT_STAGE;
    const int col0 = ct * 64;
    #pragma unroll
    for (int p = 0; p < 2; ++p) {
        int idx = p * 256 + tid;
        int r = idx >> 3, c16 = (idx & 7) * 16;
        uint32_t so = SWZ128((uint32_t)(r * 128 + c16));
        size_t g = (size_t)(col0 + r) * 128 + c16;
        cp16(st + so,        kg + g);
        cp16(st + 8192 + so, vg + g);
    }
}

__global__ __launch_bounds__(256, 2) void attn_mma_kernel()
{
    extern __shared__ char smem[];
    const uint32_t sb = smem_to_u32(smem);
    const int tid = threadIdx.x;
    const int warp = tid >> 5, lane = tid & 31;
    const int rt = (int)gridDim.x - 1 - (int)blockIdx.x;  // long blocks first
    const int bh = blockIdx.y;
    const int row0 = rt * 128;
    const int wm = warp * 16;

    const char* qg = (const char*)(g_q16 + (size_t)bh * SS * DD);
    const char* kg = (const char*)(g_k16 + (size_t)bh * SS * DD);
    const char* vg = (const char*)(g_v16 + (size_t)bh * SS * DD);

    // ---- load Q tile (16KB at sb), extract A-fragments ----
    #pragma unroll
    for (int p = 0; p < 4; ++p) {
        int cc = p * 256 + tid;
        int rr = cc >> 3, c = (cc & 7) * 16;
        uint32_t so = SWZ128((uint32_t)(rr * 128 + c));
        cp16(sb + so, qg + (size_t)(row0 + rr) * 128 + c);
    }
    CP_COMMIT();
    CP_WAIT0();
    __syncthreads();

    const int rbA = (lane & 7) + ((lane >> 3) & 1) * 8;
    const int cA  = (lane >> 4) & 1;
    uint32_t qf[4][4];
    #pragma unroll
    for (int c = 0; c < 4; ++c) {
        uint32_t off = SWZ128((uint32_t)((wm + rbA) * 128 + (c * 2 + cA) * 16));
        ldmx4(qf[c], sb + off);
    }
    __syncthreads();   // done reading Q smem; stages may overwrite

    float o[8][4];
    #pragma unroll
    for (int nf = 0; nf < 8; nf++)
        #pragma unroll
        for (int i = 0; i < 4; i++) o[nf][i] = 0.f;
    float mprev0 = -CUDART_INF_F, mprev1 = -CUDART_INF_F;
    float lsum0 = 0.f, lsum1 = 0.f;

    const int nct = 2 * rt + 2;

    const int rbB = (lane & 7) + ((lane >> 4) & 1) * 8;
    const int cB  = (lane >> 3) & 1;
    const int lr  = lane >> 2;
    const int lc2 = (lane & 3) * 2;
    const int r0g = row0 + wm + lr;

    // 3-stage prologue
    attn_load_kv(sb, 0, 0, tid, kg, vg); CP_COMMIT();
    if (nct > 1) attn_load_kv(sb, 1, 1, tid, kg, vg);
    CP_COMMIT();
    if (nct > 2) attn_load_kv(sb, 2, 2, tid, kg, vg);
    CP_COMMIT();

    for (int ct = 0; ct < nct; ++ct) {
        CP_WAIT2();
        __syncthreads();
        const uint32_t base = sb + (uint32_t)(ct % 3) * AT_STAGE;

        // fully-masked warp tile on the diagonal -> skip all compute
        const bool active = (ct * 64) <= (row0 + wm + 15);
        if (active) {
            // ---- S = Q K^T (already in log2 domain via pre-scaled Q) ----
            float s[8][4];
            #pragma unroll
            for (int nf = 0; nf < 8; nf++)
                #pragma unroll
                for (int i = 0; i < 4; i++) s[nf][i] = 0.f;

            #pragma unroll
            for (int c = 0; c < 4; ++c) {
                uint32_t kh[4][4];
                #pragma unroll
                for (int g = 0; g < 4; ++g) {
                    uint32_t off = SWZ128((uint32_t)((g * 16 + rbB) * 128 + (c * 2 + cB) * 16));
                    ldmx4(kh[g], base + off);
                }
                #pragma unroll
                for (int nf = 0; nf < 8; ++nf) {
                    int g = nf >> 1, i = (nf & 1) * 2;
                    mmah(s[nf], qf[c], kh[g][i], kh[g][i + 1]);
                }
            }

            // ---- causal mask ----
            if (ct * 64 + 63 > row0 + wm) {
                #pragma unroll
                for (int nf = 0; nf < 8; ++nf) {
                    int cg = ct * 64 + nf * 8 + lc2;
                    if (cg     > r0g)     s[nf][0] = -CUDART_INF_F;
                    if (cg + 1 > r0g)     s[nf][1] = -CUDART_INF_F;
                    if (cg     > r0g + 8) s[nf][2] = -CUDART_INF_F;
                    if (cg + 1 > r0g + 8) s[nf][3] = -CUDART_INF_F;
                }
            }

            // ---- online softmax (log2 domain, no per-element scale) ----
            float mt0 = -CUDART_INF_F, mt1 = -CUDART_INF_F;
            #pragma unroll
            for (int nf = 0; nf < 8; ++nf) {
                mt0 = fmaxf(mt0, fmaxf(s[nf][0], s[nf][1]));
                mt1 = fmaxf(mt1, fmaxf(s[nf][2], s[nf][3]));
            }
            mt0 = fmaxf(mt0, __shfl_xor_sync(0xffffffffu, mt0, 1));
            mt0 = fmaxf(mt0, __shfl_xor_sync(0xffffffffu, mt0, 2));
            mt1 = fmaxf(mt1, __shfl_xor_sync(0xffffffffu, mt1, 1));
            mt1 = fmaxf(mt1, __shfl_xor_sync(0xffffffffu, mt1, 2));

            float mn0 = fmaxf(mprev0, mt0);
            float mn1 = fmaxf(mprev1, mt1);
            float a0 = exp2f(mprev0 - mn0);
            float a1 = exp2f(mprev1 - mn1);
            lsum0 *= a0; lsum1 *= a1;
            #pragma unroll
            for (int nf = 0; nf < 8; ++nf) {
                s[nf][0] = exp2f(s[nf][0] - mn0);
                s[nf][1] = exp2f(s[nf][1] - mn0);
                s[nf][2] = exp2f(s[nf][2] - mn1);
                s[nf][3] = exp2f(s[nf][3] - mn1);
                lsum0 += s[nf][0] + s[nf][1];
                lsum1 += s[nf][2] + s[nf][3];
                o[nf][0] *= a0; o[nf][1] *= a0;
                o[nf][2] *= a1; o[nf][3] *= a1;
            }
            mprev0 = mn0; mprev1 = mn1;

            // ---- pack P into fp16 A-fragments ----
            uint32_t pf[4][4];
            #pragma unroll
            for (int kk = 0; kk < 4; ++kk) {
                pf[kk][0] = cvt_pair(s[2*kk][0],   s[2*kk][1]);
                pf[kk][1] = cvt_pair(s[2*kk][2],   s[2*kk][3]);
                pf[kk][2] = cvt_pair(s[2*kk+1][0], s[2*kk+1][1]);
                pf[kk][3] = cvt_pair(s[2*kk+1][2], s[2*kk+1][3]);
            }

            // ---- O += P V (ldmatrix.trans for V) ----
            #pragma unroll
            for (int kk = 0; kk < 4; ++kk) {
                #pragma unroll
                for (int dd = 0; dd < 4; ++dd) {
                    uint32_t vh[4];
                    uint32_t off = SWZ128((uint32_t)((kk * 16 + rbA) * 128 + (dd * 2 + cA) * 16));
                    ldmx4t(vh, base + 8192 + off);
                    #pragma unroll
                    for (int j = 0; j < 2; ++j) {
                        int nf = dd * 2 + j;
                        mmah(o[nf], pf[kk], vh[j * 2], vh[j * 2 + 1]);
                    }
                }
            }
        }

        __syncthreads();
        if (ct + 3 < nct)
            attn_load_kv(sb, ct % 3, ct + 3, tid, kg, vg);
        CP_COMMIT();
    }

    // ---- finalize ----
    lsum0 += __shfl_xor_sync(0xffffffffu, lsum0, 1);
    lsum0 += __shfl_xor_sync(0xffffffffu, lsum0, 2);
    lsum1 += __shfl_xor_sync(0xffffffffu, lsum1, 1);
    lsum1 += __shfl_xor_sync(0xffffffffu, lsum1, 2);
    float inv0 = 1.f / lsum0;
    float inv1 = 1.f / lsum1;

    const int b = bh >> 4, h = bh & 15;
    const size_t m0G = (size_t)b * SS + (size_t)(row0 + wm + lr);
    __half* o0 = g_o16 + m0G * EE + h * DD;
    __half* o1 = o0 + (size_t)8 * EE;
    #pragma unroll
    for (int nf = 0; nf < 8; ++nf) {
        int col = nf * 8 + lc2;
        *(uint32_t*)(o0 + col) = cvt_pair(o[nf][0] * inv0, o[nf][1] * inv0);
        *(uint32_t*)(o1 + col) = cvt_pair(o[nf][2] * inv1, o[nf][3] * inv1);
    }
}

// ---------------------------------------------------------------------------
extern "C" void kernel_launch(void* const* d_in, const int* in_sizes, int n_in,
                              void* d_out, int out_size)
{
    const float* x  = (const float*)d_in[0];
    const float* wq = (const float*)d_in[1];
    const float* bq = (const float*)d_in[2];
    const float* wk = (const float*)d_in[3];
    const float* bk = (const float*)d_in[4];
    const float* wv = (const float*)d_in[5];
    const float* bv = (const float*)d_in[6];
    const float* wo = (const float*)d_in[7];
    const float* bo = (const float*)d_in[8];
    float* y = (float*)d_out;

    (void)in_sizes; (void)n_in; (void)out_size;

    cudaFuncSetAttribute(qkv_mma_kernel, cudaFuncAttributeMaxDynamicSharedMemorySize,
                         GEMM_SMEM);
    cudaFuncSetAttribute(oproj_mma_kernel, cudaFuncAttributeMaxDynamicSharedMemorySize,
                         GEMM_SMEM);
    cudaFuncSetAttribute(attn_mma_kernel, cudaFuncAttributeMaxDynamicSharedMemorySize,
                         AT_SMEM);

    // 1) merged fp32 -> fp16 prep (x, W_all^T, wo^T)
    prep_kernel<<<5120, 256>>>(x, wq, wk, wv, wo);

    // 2) QKV projection: merged GEMM [8192 x 3072], 128x128 tiles
    qkv_mma_kernel<<<dim3(64, 24), 256, GEMM_SMEM>>>(bq, bk, bv);

    // 3) Flash attention (fp16, log2-domain softmax, 3-stage, diag skip)
    attn_mma_kernel<<<dim3(16, 64), 256, AT_SMEM>>>();

    // 4) Output projection [8192 x 1024], 128x128 tiles
    oproj_mma_kernel<<<dim3(64, 8), 256, GEMM_SMEM>>>(bo, y);
}

// round 10
// speedup vs baseline: 8.9409x; 1.0871x over previous
#include <cuda_runtime.h>
#include <cuda_fp16.h>
#include <math_constants.h>
#include <cstdint>

#define BB 4
#define SS 2048
#define EE 1024
#define HH 16
#define DD 64
#define MM (BB*SS)   // 8192

// ---------------------------------------------------------------------------
// Device-global scratch (allocation-free rule) — all fp16
// ---------------------------------------------------------------------------
__device__ __align__(16) __half g_x16[MM*EE];
__device__ __align__(16) __half g_w16[48*DD*EE];    // [z*64+d][e] == W_all^T
__device__ __align__(16) __half g_wo16[EE*EE];      // [n][k] (wo transposed)
__device__ __align__(16) __half g_q16[BB*HH*SS*DD]; // [bh][s][d], pre-scaled by 1/sqrt(D)*log2e
__device__ __align__(16) __half g_k16[BB*HH*SS*DD];
__device__ __align__(16) __half g_v16[BB*HH*SS*DD];
__device__ __align__(16) __half g_o16[MM*EE];       // [m][h*64+d]

// ---------------------------------------------------------------------------
// mma.sync / ldmatrix / cp.async helpers
// ---------------------------------------------------------------------------
__device__ __forceinline__ uint32_t smem_to_u32(const void* p) {
    uint32_t a;
    asm("{ .reg .u64 t; cvta.to.shared.u64 t, %1; cvt.u32.u64 %0, t; }"
        : "=r"(a) : "l"(p));
    return a;
}
__device__ __forceinline__ void cp16(uint32_t saddr, const void* gaddr) {
    asm volatile("cp.async.cg.shared.global [%0], [%1], 16;"
                 :: "r"(saddr), "l"(gaddr));
}
#define CP_COMMIT() asm volatile("cp.async.commit_group;" ::: "memory")
#define CP_WAIT1()  asm volatile("cp.async.wait_group 1;" ::: "memory")
#define CP_WAIT2()  asm volatile("cp.async.wait_group 2;" ::: "memory")
#define CP_WAIT0()  asm volatile("cp.async.wait_group 0;" ::: "memory")

__device__ __forceinline__ void ldmx4(uint32_t* r, uint32_t addr) {
    asm volatile("ldmatrix.sync.aligned.m8n8.x4.shared.b16 {%0,%1,%2,%3}, [%4];"
        : "=r"(r[0]), "=r"(r[1]), "=r"(r[2]), "=r"(r[3]) : "r"(addr));
}
__device__ __forceinline__ void ldmx4t(uint32_t* r, uint32_t addr) {
    asm volatile("ldmatrix.sync.aligned.m8n8.x4.trans.shared.b16 {%0,%1,%2,%3}, [%4];"
        : "=r"(r[0]), "=r"(r[1]), "=r"(r[2]), "=r"(r[3]) : "r"(addr));
}
__device__ __forceinline__ void mmah(float* c, const uint32_t* a,
                                     uint32_t b0, uint32_t b1) {
    asm volatile("mma.sync.aligned.m16n8k16.row.col.f32.f16.f16.f32 "
        "{%0,%1,%2,%3}, {%4,%5,%6,%7}, {%8,%9}, {%0,%1,%2,%3};"
        : "+f"(c[0]), "+f"(c[1]), "+f"(c[2]), "+f"(c[3])
        : "r"(a[0]), "r"(a[1]), "r"(a[2]), "r"(a[3]), "r"(b0), "r"(b1));
}

#define SWZ128(off) ((off) ^ (((off) >> 3) & 0x70))   // 128B rows

__device__ __forceinline__ uint32_t pckh(__half a, __half b) {
    return ((uint32_t)__half_as_ushort(b) << 16) | (uint32_t)__half_as_ushort(a);
}
__device__ __forceinline__ uint32_t cvt_pair(float v0, float v1) {
    return pckh(__float2half_rn(v0), __float2half_rn(v1));
}
// pack (lo=v0, hi=v1) via single cvt (keeps +-inf, no satfinite)
__device__ __forceinline__ uint32_t cvtpair_f2h(float v0, float v1) {
    uint32_t r;
    asm("cvt.rn.f16x2.f32 %0, %1, %2;" : "=r"(r) : "f"(v1), "f"(v0));
    return r;
}
__device__ __forceinline__ uint32_t h2exp2(uint32_t x) {
    uint32_t r;
    asm("ex2.approx.f16x2 %0, %1;" : "=r"(r) : "r"(x));
    return r;
}

// ---------------------------------------------------------------------------
// Merged prep kernel: fp32 -> fp16 for x, W_all (transposed), wo (transposed)
// ---------------------------------------------------------------------------
__global__ __launch_bounds__(256) void prep_kernel(
    const float* __restrict__ x,
    const float* __restrict__ wq, const float* __restrict__ wk,
    const float* __restrict__ wv, const float* __restrict__ wo)
{
    __shared__ float t[64][65];
    const int bid = blockIdx.x;
    const int tid = threadIdx.x;

    if (bid < 4096) {
        size_t i = ((size_t)bid * 256 + tid) * 8;
        float4 v0 = *(const float4*)(x + i);
        float4 v1 = *(const float4*)(x + i + 4);
        uint4 u;
        u.x = cvt_pair(v0.x, v0.y); u.y = cvt_pair(v0.z, v0.w);
        u.z = cvt_pair(v1.x, v1.y); u.w = cvt_pair(v1.z, v1.w);
        *(uint4*)(g_x16 + i) = u;
    } else if (bid < 4096 + 768) {
        const int tt = bid - 4096;
        const int e0 = (tt & 15) * 64;
        const int z = tt >> 4;
        const int which = z >> 4, h = z & 15;
        const float* W = (which == 0 ? wq : which == 1 ? wk : wv) + (size_t)h * EE * DD;
        #pragma unroll
        for (int q = 0; q < 4; q++) {
            int idx = q * 256 + tid;
            int r = idx >> 4, c = (idx & 15) * 4;
            float4 v = *(const float4*)(W + (size_t)(e0 + r) * DD + c);
            t[r][c] = v.x; t[r][c+1] = v.y; t[r][c+2] = v.z; t[r][c+3] = v.w;
        }
        __syncthreads();
        #pragma unroll
        for (int q = 0; q < 4; q++) {
            int idx = q * 256 + tid;
            int d = idx >> 4, e = (idx & 15) * 4;
            size_t o = ((size_t)z * DD + d) * EE + e0 + e;
            *(uint32_t*)(g_w16 + o)     = cvt_pair(t[e][d],   t[e+1][d]);
            *(uint32_t*)(g_w16 + o + 2) = cvt_pair(t[e+2][d], t[e+3][d]);
        }
    } else {
        const int tt = bid - (4096 + 768);
        const int k0 = (tt & 15) * 64;
        const int n0 = (tt >> 4) * 64;
        #pragma unroll
        for (int q = 0; q < 4; q++) {
            int idx = q * 256 + tid;
            int r = idx >> 4, c = (idx & 15) * 4;
            float4 v = *(const float4*)(wo + (size_t)(k0 + r) * EE + n0 + c);
            t[r][c] = v.x; t[r][c+1] = v.y; t[r][c+2] = v.z; t[r][c+3] = v.w;
        }
        __syncthreads();
        #pragma unroll
        for (int q = 0; q < 4; q++) {
            int idx = q * 256 + tid;
            int d = idx >> 4, e = (idx & 15) * 4;
            size_t o = (size_t)(n0 + d) * EE + k0 + e;
            *(uint32_t*)(g_wo16 + o)     = cvt_pair(t[e][d],   t[e+1][d]);
            *(uint32_t*)(g_wo16 + o + 2) = cvt_pair(t[e+2][d], t[e+3][d]);
        }
    }
}

// ---------------------------------------------------------------------------
// GEMM core 128x128, fp16 single-pass (unchanged)
// ---------------------------------------------------------------------------
#define STAGE_BYTES 32768
#define GEMM_SMEM   (3 * STAGE_BYTES)

__device__ __forceinline__ void load_stage(
    uint32_t sb, int s, int kt, int tid,
    const char* ag, const char* bg)
{
    const uint32_t st = sb + (uint32_t)s * STAGE_BYTES;
    const int c16 = (tid & 7) * 16;
    const size_t gk = (size_t)kt * 128 + (size_t)c16;
    #pragma unroll
    for (int p = 0; p < 4; ++p) {
        int row = p * 32 + (tid >> 3);
        uint32_t so = SWZ128((uint32_t)(row * 128 + c16));
        size_t g = (size_t)row * 2048 + gk;
        cp16(st + so,         ag + g);
        cp16(st + 16384 + so, bg + g);
    }
}

__device__ __forceinline__ void gemm_core_128x128_h(
    uint32_t sb, const char* ag, const char* bg, float acc[2][8][4])
{
    const int tid = threadIdx.x;
    const int warp = tid >> 5, lane = tid & 31;
    const int wm = (warp & 3) * 32;
    const int wn = (warp >> 2) * 64;

    uint32_t offA[2], offB[4];
    {
        const int rbA = (lane & 7) + ((lane >> 3) & 1) * 8;
        const int cA  = (lane >> 4) & 1;
        const int rbB = (lane & 7) + ((lane >> 4) & 1) * 8;
        const int cB  = (lane >> 3) & 1;
        #pragma unroll
        for (int f = 0; f < 2; ++f)
            offA[f] = SWZ128((uint32_t)((wm + f*16 + rbA) * 128 + cA * 16));
        #pragma unroll
        for (int g = 0; g < 4; ++g)
            offB[g] = SWZ128((uint32_t)((wn + g*16 + rbB) * 128 + cB * 16));
    }
    #pragma unroll
    for (int f = 0; f < 2; f++)
        #pragma unroll
        for (int nf = 0; nf < 8; nf++)
            #pragma unroll
            for (int i = 0; i < 4; i++) acc[f][nf][i] = 0.f;

    load_stage(sb, 0, 0, tid, ag, bg); CP_COMMIT();
    load_stage(sb, 1, 1, tid, ag, bg); CP_COMMIT();

    for (int kt = 0; kt < 16; ++kt) {
        CP_WAIT1();
        __syncthreads();
        if (kt + 2 < 16)
            load_stage(sb, (kt + 2) % 3, kt + 2, tid, ag, bg);
        CP_COMMIT();

        const uint32_t base = sb + (uint32_t)(kt % 3) * STAGE_BYTES;
        #pragma unroll
        for (int s16 = 0; s16 < 4; ++s16) {
            const uint32_t sx = (uint32_t)(s16 * 32);
            uint32_t a0[4], a1[4];
            ldmx4(a0, base + (offA[0] ^ sx));
            ldmx4(a1, base + (offA[1] ^ sx));
            uint32_t b[4][4];
            #pragma unroll
            for (int g = 0; g < 4; ++g)
                ldmx4(b[g], base + 16384 + (offB[g] ^ sx));
            uint32_t* aa[2] = {a0, a1};
            #pragma unroll
            for (int f = 0; f < 2; ++f)
                #pragma unroll
                for (int nf = 0; nf < 8; ++nf)
                    mmah(acc[f][nf], aa[f],
                         b[nf >> 1][(nf & 1) * 2], b[nf >> 1][(nf & 1) * 2 + 1]);
        }
    }
}

// ---------------------------------------------------------------------------
// QKV projection: merged GEMM C[8192 x 3072] = X * W_all^T
// Q outputs pre-scaled by 1/sqrt(D)*log2(e).
// ---------------------------------------------------------------------------
__global__ __launch_bounds__(256, 2) void qkv_mma_kernel(
    const float* __restrict__ bq, const float* __restrict__ bk,
    const float* __restrict__ bv)
{
    extern __shared__ char smem[];
    const uint32_t sb = smem_to_u32(smem);
    const int tid = threadIdx.x;
    const int m0 = blockIdx.x * 128;
    const int n0 = blockIdx.y * 128;

    const char* ag = (const char*)(g_x16 + (size_t)m0 * EE);
    const char* bg = (const char*)(g_w16 + (size_t)n0 * EE);

    float acc[2][8][4];
    gemm_core_128x128_h(sb, ag, bg, acc);

    const int warp = tid >> 5, lane = tid & 31;
    const int wm = (warp & 3) * 32, wn = (warp >> 2) * 64;
    const int r = lane >> 2, cp2 = (lane & 3) * 2;

    const int z = (n0 + wn) >> 6;               // one head per warp
    const int which = z >> 4, h = z & 15;
    const float* bp = (which == 0 ? bq : which == 1 ? bk : bv) + h * DD;
    __half* op = (which == 0 ? g_q16 : which == 1 ? g_k16 : g_v16);
    const float osc = (which == 0) ? 0.125f * 1.4426950408889634f : 1.0f;

    #pragma unroll
    for (int f = 0; f < 2; ++f) {
        #pragma unroll
        for (int half = 0; half < 2; ++half) {
            int m = m0 + wm + f * 16 + r + half * 8;
            int b = m >> 11, s = m & 2047;
            size_t rowoff = (((size_t)b * HH + h) * SS + s) * DD;
            #pragma unroll
            for (int nf = 0; nf < 8; ++nf) {
                int d = nf * 8 + cp2;
                float v0 = (acc[f][nf][half * 2 + 0] + bp[d]) * osc;
                float v1 = (acc[f][nf][half * 2 + 1] + bp[d + 1]) * osc;
                *(uint32_t*)(op + rowoff + d) = cvt_pair(v0, v1);
            }
        }
    }
}

// ---------------------------------------------------------------------------
// Output projection: y[8192x1024] = O_cat * wo + bo, grid (64, 8)
// ---------------------------------------------------------------------------
__global__ __launch_bounds__(256, 2) void oproj_mma_kernel(
    const float* __restrict__ bo, float* __restrict__ y)
{
    extern __shared__ char smem[];
    const uint32_t sb = smem_to_u32(smem);
    const int tid = threadIdx.x;
    const int m0 = blockIdx.x * 128;
    const int n0 = blockIdx.y * 128;

    const char* ag = (const char*)(g_o16 + (size_t)m0 * EE);
    const char* bg = (const char*)(g_wo16 + (size_t)n0 * EE);

    float acc[2][8][4];
    gemm_core_128x128_h(sb, ag, bg, acc);

    const int warp = tid >> 5, lane = tid & 31;
    const int wm = (warp & 3) * 32, wn = (warp >> 2) * 64;
    const int r = lane >> 2, cp2 = (lane & 3) * 2;
    #pragma unroll
    for (int f = 0; f < 2; ++f) {
        #pragma unroll
        for (int half = 0; half < 2; ++half) {
            int m = m0 + wm + f * 16 + r + half * 8;
            float* row = y + (size_t)m * EE + n0 + wn;
            #pragma unroll
            for (int nf = 0; nf < 8; ++nf) {
                int col = nf * 8 + cp2;
                float2 v;
                v.x = acc[f][nf][half * 2 + 0] + bo[n0 + wn + col];
                v.y = acc[f][nf][half * 2 + 1] + bo[n0 + wn + col + 1];
                *(float2*)(row + col) = v;
            }
        }
    }
}

// ---------------------------------------------------------------------------
// Flash attention, fp16 single-pass, causal. Q pre-scaled (log2 domain).
// Softmax: f16x2 ex2.approx for P, row-sum via ones-MMA (fp32 accum).
// Block: 256 threads (8 warps), Br=128, Bc=64, D=64.
// smem: 3 stages x 16KB (K 8K | V 8K), SW128. 2 CTAs/SM; long blocks first.
// ---------------------------------------------------------------------------
#define AT_STAGE 16384
#define AT_SMEM  (3 * AT_STAGE)

__device__ __forceinline__ void attn_load_kv(
    uint32_t sb, int stage, int ct, int tid,
    const char* kg, const char* vg)
{
    const uint32_t st = sb + (uint32_t)stage * AT_STAGE;
    const int col0 = ct * 64;
    #pragma unroll
    for (int p = 0; p < 2; ++p) {
        int idx = p * 256 + tid;
        int r = idx >> 3, c16 = (idx & 7) * 16;
        uint32_t so = SWZ128((uint32_t)(r * 128 + c16));
        size_t g = (size_t)(col0 + r) * 128 + c16;
        cp16(st + so,        kg + g);
        cp16(st + 8192 + so, vg + g);
    }
}

__global__ __launch_bounds__(256, 2) void attn_mma_kernel()
{
    extern __shared__ char smem[];
    const uint32_t sb = smem_to_u32(smem);
    const int tid = threadIdx.x;
    const int warp = tid >> 5, lane = tid & 31;
    const int rt = (int)gridDim.x - 1 - (int)blockIdx.x;  // long blocks first
    const int bh = blockIdx.y;
    const int row0 = rt * 128;
    const int wm = warp * 16;

    const char* qg = (const char*)(g_q16 + (size_t)bh * SS * DD);
    const char* kg = (const char*)(g_k16 + (size_t)bh * SS * DD);
    const char* vg = (const char*)(g_v16 + (size_t)bh * SS * DD);

    // ---- load Q tile (16KB at sb), extract A-fragments ----
    #pragma unroll
    for (int p = 0; p < 4; ++p) {
        int cc = p * 256 + tid;
        int rr = cc >> 3, c = (cc & 7) * 16;
        uint32_t so = SWZ128((uint32_t)(rr * 128 + c));
        cp16(sb + so, qg + (size_t)(row0 + rr) * 128 + c);
    }
    CP_COMMIT();
    CP_WAIT0();
    __syncthreads();

    const int rbA = (lane & 7) + ((lane >> 3) & 1) * 8;
    const int cA  = (lane >> 4) & 1;
    uint32_t qf[4][4];
    #pragma unroll
    for (int c = 0; c < 4; ++c) {
        uint32_t off = SWZ128((uint32_t)((wm + rbA) * 128 + (c * 2 + cA) * 16));
        ldmx4(qf[c], sb + off);
    }
    __syncthreads();   // done reading Q smem; stages may overwrite

    float o[8][4];
    #pragma unroll
    for (int nf = 0; nf < 8; nf++)
        #pragma unroll
        for (int i = 0; i < 4; i++) o[nf][i] = 0.f;
    float lacc[4] = {0.f, 0.f, 0.f, 0.f};     // ones-MMA row-sum accumulator
    float mprev0 = -CUDART_INF_F, mprev1 = -CUDART_INF_F;

    const int nct = 2 * rt + 2;
    const uint32_t ONE2 = 0x3C003C00u;         // half2(1,1)

    const int rbB = (lane & 7) + ((lane >> 4) & 1) * 8;
    const int cB  = (lane >> 3) & 1;
    const int lr  = lane >> 2;
    const int lc2 = (lane & 3) * 2;
    const int r0g = row0 + wm + lr;

    // 3-stage prologue
    attn_load_kv(sb, 0, 0, tid, kg, vg); CP_COMMIT();
    if (nct > 1) attn_load_kv(sb, 1, 1, tid, kg, vg);
    CP_COMMIT();
    if (nct > 2) attn_load_kv(sb, 2, 2, tid, kg, vg);
    CP_COMMIT();

    for (int ct = 0; ct < nct; ++ct) {
        CP_WAIT2();
        __syncthreads();
        const uint32_t base = sb + (uint32_t)(ct % 3) * AT_STAGE;

        // fully-masked warp tile on the diagonal -> skip all compute
        const bool active = (ct * 64) <= (row0 + wm + 15);
        if (active) {
            // ---- S = Q K^T (log2 domain via pre-scaled Q) ----
            float s[8][4];
            #pragma unroll
            for (int nf = 0; nf < 8; nf++)
                #pragma unroll
                for (int i = 0; i < 4; i++) s[nf][i] = 0.f;

            #pragma unroll
            for (int c = 0; c < 4; ++c) {
                uint32_t kh[4][4];
                #pragma unroll
                for (int g = 0; g < 4; ++g) {
                    uint32_t off = SWZ128((uint32_t)((g * 16 + rbB) * 128 + (c * 2 + cB) * 16));
                    ldmx4(kh[g], base + off);
                }
                #pragma unroll
                for (int nf = 0; nf < 8; ++nf) {
                    int g = nf >> 1, i = (nf & 1) * 2;
                    mmah(s[nf], qf[c], kh[g][i], kh[g][i + 1]);
                }
            }

            // ---- causal mask ----
            if (ct * 64 + 63 > row0 + wm) {
                #pragma unroll
                for (int nf = 0; nf < 8; ++nf) {
                    int cg = ct * 64 + nf * 8 + lc2;
                    if (cg     > r0g)     s[nf][0] = -CUDART_INF_F;
                    if (cg + 1 > r0g)     s[nf][1] = -CUDART_INF_F;
                    if (cg     > r0g + 8) s[nf][2] = -CUDART_INF_F;
                    if (cg + 1 > r0g + 8) s[nf][3] = -CUDART_INF_F;
                }
            }

            // ---- row max ----
            float mt0 = -CUDART_INF_F, mt1 = -CUDART_INF_F;
            #pragma unroll
            for (int nf = 0; nf < 8; ++nf) {
                mt0 = fmaxf(mt0, fmaxf(s[nf][0], s[nf][1]));
                mt1 = fmaxf(mt1, fmaxf(s[nf][2], s[nf][3]));
            }
            mt0 = fmaxf(mt0, __shfl_xor_sync(0xffffffffu, mt0, 1));
            mt0 = fmaxf(mt0, __shfl_xor_sync(0xffffffffu, mt0, 2));
            mt1 = fmaxf(mt1, __shfl_xor_sync(0xffffffffu, mt1, 1));
            mt1 = fmaxf(mt1, __shfl_xor_sync(0xffffffffu, mt1, 2));

            float mn0 = fmaxf(mprev0, mt0);
            float mn1 = fmaxf(mprev1, mt1);
            float a0 = exp2f(mprev0 - mn0);
            float a1 = exp2f(mprev1 - mn1);
            mprev0 = mn0; mprev1 = mn1;

            // rescale O and row-sum accumulators
            lacc[0] *= a0; lacc[1] *= a0; lacc[2] *= a1; lacc[3] *= a1;
            #pragma unroll
            for (int nf = 0; nf < 8; ++nf) {
                o[nf][0] *= a0; o[nf][1] *= a0;
                o[nf][2] *= a1; o[nf][3] *= a1;
            }

            // ---- P = exp2(s - m) directly in f16x2 fragments ----
            uint32_t pf[4][4];
            #pragma unroll
            for (int kk = 0; kk < 4; ++kk) {
                pf[kk][0] = h2exp2(cvtpair_f2h(s[2*kk][0]   - mn0, s[2*kk][1]   - mn0));
                pf[kk][1] = h2exp2(cvtpair_f2h(s[2*kk][2]   - mn1, s[2*kk][3]   - mn1));
                pf[kk][2] = h2exp2(cvtpair_f2h(s[2*kk+1][0] - mn0, s[2*kk+1][1] - mn0));
                pf[kk][3] = h2exp2(cvtpair_f2h(s[2*kk+1][2] - mn1, s[2*kk+1][3] - mn1));
            }

            // ---- row sums via ones-MMA (consistent with f16 P) ----
            #pragma unroll
            for (int kk = 0; kk < 4; ++kk)
                mmah(lacc, pf[kk], ONE2, ONE2);

            // ---- O += P V (ldmatrix.trans for V) ----
            #pragma unroll
            for (int kk = 0; kk < 4; ++kk) {
                #pragma unroll
                for (int dd = 0; dd < 4; ++dd) {
                    uint32_t vh[4];
                    uint32_t off = SWZ128((uint32_t)((kk * 16 + rbA) * 128 + (dd * 2 + cA) * 16));
                    ldmx4t(vh, base + 8192 + off);
                    #pragma unroll
                    for (int j = 0; j < 2; ++j) {
                        int nf = dd * 2 + j;
                        mmah(o[nf], pf[kk], vh[j * 2], vh[j * 2 + 1]);
                    }
                }
            }
        }

        __syncthreads();
        if (ct + 3 < nct)
            attn_load_kv(sb, ct % 3, ct + 3, tid, kg, vg);
        CP_COMMIT();
    }

    // ---- finalize: lacc[0]/lacc[2] hold exact row sums of f16 P ----
    float inv0 = 1.f / lacc[0];
    float inv1 = 1.f / lacc[2];

    const int b = bh >> 4, h = bh & 15;
    const size_t m0G = (size_t)b * SS + (size_t)(row0 + wm + lr);
    __half* o0 = g_o16 + m0G * EE + h * DD;
    __half* o1 = o0 + (size_t)8 * EE;
    #pragma unroll
    for (int nf = 0; nf < 8; ++nf) {
        int col = nf * 8 + lc2;
        *(uint32_t*)(o0 + col) = cvt_pair(o[nf][0] * inv0, o[nf][1] * inv0);
        *(uint32_t*)(o1 + col) = cvt_pair(o[nf][2] * inv1, o[nf][3] * inv1);
    }
}

// ---------------------------------------------------------------------------
extern "C" void kernel_launch(void* const* d_in, const int* in_sizes, int n_in,
                              void* d_out, int out_size)
{
    const float* x  = (const float*)d_in[0];
    const float* wq = (const float*)d_in[1];
    const float* bq = (const float*)d_in[2];
    const float* wk = (const float*)d_in[3];
    const float* bk = (const float*)d_in[4];
    const float* wv = (const float*)d_in[5];
    const float* bv = (const float*)d_in[6];
    const float* wo = (const float*)d_in[7];
    const float* bo = (const float*)d_in[8];
    float* y = (float*)d_out;

    (void)in_sizes; (void)n_in; (void)out_size;

    cudaFuncSetAttribute(qkv_mma_kernel, cudaFuncAttributeMaxDynamicSharedMemorySize,
                         GEMM_SMEM);
    cudaFuncSetAttribute(oproj_mma_kernel, cudaFuncAttributeMaxDynamicSharedMemorySize,
                         GEMM_SMEM);
    cudaFuncSetAttribute(attn_mma_kernel, cudaFuncAttributeMaxDynamicSharedMemorySize,
                         AT_SMEM);

    // 1) merged fp32 -> fp16 prep (x, W_all^T, wo^T)
    prep_kernel<<<5120, 256>>>(x, wq, wk, wv, wo);

    // 2) QKV projection: merged GEMM [8192 x 3072], 128x128 tiles
    qkv_mma_kernel<<<dim3(64, 24), 256, GEMM_SMEM>>>(bq, bk, bv);

    // 3) Flash attention (f16x2 ex2 softmax, ones-MMA row sums)
    attn_mma_kernel<<<dim3(16, 64), 256, AT_SMEM>>>();

    // 4) Output projection [8192 x 1024], 128x128 tiles
    oproj_mma_kernel<<<dim3(64, 8), 256, GEMM_SMEM>>>(bo, y);
}